// round 2
// baseline (speedup 1.0000x reference)
#include <cuda_runtime.h>
#include <cstdint>

// ---------------------------------------------------------------------------
// SimplePose: 3x (jax conv_transpose k4 s2 pads(1,1) + BN + ReLU)
//             -> 1x1 conv (256->17) -> heatmap argmax + subpixel detect
//
// jax.lax.conv_transpose with EXPLICIT pads passes them straight to
// conv_general_dilated on the lhs-dilated input (no k-1-p transform, no
// kernel flip). So, with dilation 2 and pads (1,1):
//   y[oy] = sum_kh xd[oy-1+kh] * w[kh],  xd[2t]=x[t], odd->0,  H_out = 2H-2.
// Parity: kh = 2a + (1-py) with py = oy&1, oy = 2ty+py:
//   iy = ty + a,  ty in [0,H-2], a in {0,1}  -> always in range (dense GEMM!)
// Per phase (py,px): M = B*(H-1)*(W-1), K = 4*Cin, N = 256.
// Shapes: [64,8,6,2048] -> [64,14,10,256] -> [64,26,18,256] -> [64,50,34,256]
// ---------------------------------------------------------------------------

#define BDIM_B   64
#define COUT     256
#define KPT      17
#define BN_EPS   1e-5f

// final feature map 50x34
#define HD 50
#define WD 34
#define HWD (HD * WD)          // 1700
#define NPIX (BDIM_B * HWD)    // 108800

// scratch (static device arrays; cudaMalloc is forbidden)
__device__ float g_y1[BDIM_B * 14 * 10 * COUT];
__device__ float g_y2[BDIM_B * 26 * 18 * COUT];
__device__ float g_y3[BDIM_B * HD * WD * COUT];
__device__ float g_hm[BDIM_B * KPT * HWD];      // [b*17+k][1700]

// ---------------------------------------------------------------------------
// Deconv + BN + ReLU as phase-decomposed dense GEMM.
// Tile: 128(M) x 128(N) x 16(K), 256 threads, 8x8 accum per thread.
// ---------------------------------------------------------------------------
#define TBM 128
#define TBN 128
#define TBK 16

__global__ __launch_bounds__(256, 2)
void deconv_bn_relu(const float* __restrict__ x, const float* __restrict__ w,
                    const float* __restrict__ gma, const float* __restrict__ bta,
                    const float* __restrict__ mu,  const float* __restrict__ var,
                    float* __restrict__ y,
                    int H, int W, int Cin)
{
    const int phase = blockIdx.z;
    const int py = phase >> 1, px = phase & 1;
    const int n0 = blockIdx.x * TBN;
    const int m0 = blockIdx.y * TBM;
    const int Hp = H - 1, Wp = W - 1;
    const int HWp = Hp * Wp;
    const int M   = BDIM_B * HWp;
    const int K   = 4 * Cin;
    const int tid = threadIdx.x;

    __shared__ float As[TBM][TBK + 1];   // +1 pad: conflict-free column reads
    __shared__ float Bs[TBK][TBN];

    // ---- A-load mapping: each thread loads two float4 (rows r, r+64) ----
    const int ar0 = tid >> 2;            // 0..63
    const int ac4 = (tid & 3) * 4;       // 0,4,8,12
    int abb[2], aty[2], atx[2], avalid[2];
#pragma unroll
    for (int u = 0; u < 2; ++u) {
        int m  = m0 + ar0 + 64 * u;
        avalid[u] = (m < M);
        if (m >= M) m = M - 1;           // clamp (loads masked anyway)
        int bb = m / HWp;  int rem = m - bb * HWp;
        int ty = rem / Wp; int tx  = rem - ty * Wp;
        abb[u] = bb; aty[u] = ty; atx[u] = tx;
    }

    // ---- B-load mapping: row = tid>>4 (0..15), two float4 per row ----
    const int br = tid >> 4;
    const int bc = (tid & 15) * 4;

    // ---- compute mapping: 16x16 threads of 8x8 ----
    const int tr = tid >> 4;             // 0..15
    const int tc = tid & 15;             // 0..15

    float acc[8][8];
#pragma unroll
    for (int i = 0; i < 8; ++i)
#pragma unroll
        for (int j = 0; j < 8; ++j) acc[i][j] = 0.f;

    for (int kt = 0; kt < K; kt += TBK) {
        const int tap = kt / Cin;            // TBK chunks never straddle a tap
        const int ci0 = kt - tap * Cin;
        const int a = tap >> 1, b = tap & 1;

        // load A tile: x[bb, ty+a, tx+b, ci0+ac4 ..] (always in-range spatially)
#pragma unroll
        for (int u = 0; u < 2; ++u) {
            float4 v = make_float4(0.f, 0.f, 0.f, 0.f);
            if (avalid[u]) {
                const int iy = aty[u] + a;
                const int ix = atx[u] + b;
                const float* p = x + ((size_t)(abb[u] * H + iy) * W + ix) * Cin + ci0 + ac4;
                v = *(const float4*)p;
            }
            const int row = ar0 + 64 * u;
            As[row][ac4 + 0] = v.x; As[row][ac4 + 1] = v.y;
            As[row][ac4 + 2] = v.z; As[row][ac4 + 3] = v.w;
        }
        // load B tile: w[kh, kw, ci0+br, n0..]  with kh = 2a+1-py, kw = 2b+1-px
        {
            const int kh = 2 * a + 1 - py, kw = 2 * b + 1 - px;
            const float* p = w + ((size_t)((kh * 4 + kw) * Cin + ci0 + br)) * COUT + n0;
            *(float4*)&Bs[br][bc]      = *(const float4*)(p + bc);
            *(float4*)&Bs[br][bc + 64] = *(const float4*)(p + bc + 64);
        }
        __syncthreads();

#pragma unroll
        for (int k = 0; k < TBK; ++k) {
            float af[8], bfr[8];
#pragma unroll
            for (int i = 0; i < 8; ++i) af[i] = As[tr * 8 + i][k];
            float4 b0 = *(const float4*)&Bs[k][tc * 8];
            float4 b1 = *(const float4*)&Bs[k][tc * 8 + 4];
            bfr[0] = b0.x; bfr[1] = b0.y; bfr[2] = b0.z; bfr[3] = b0.w;
            bfr[4] = b1.x; bfr[5] = b1.y; bfr[6] = b1.z; bfr[7] = b1.w;
#pragma unroll
            for (int i = 0; i < 8; ++i)
#pragma unroll
                for (int j = 0; j < 8; ++j)
                    acc[i][j] = fmaf(af[i], bfr[j], acc[i][j]);
        }
        __syncthreads();
    }

    // ---- epilogue: BN + ReLU, scatter to NHWC output [B, 2H-2, 2W-2, 256] ----
    float sc[8], bi[8];
#pragma unroll
    for (int j = 0; j < 8; ++j) {
        const int c = n0 + tc * 8 + j;
        const float s = gma[c] * rsqrtf(var[c] + BN_EPS);
        sc[j] = s; bi[j] = bta[c] - mu[c] * s;
    }
    const int H2 = 2 * H - 2, W2 = 2 * W - 2;
#pragma unroll
    for (int i = 0; i < 8; ++i) {
        const int m  = m0 + tr * 8 + i;
        if (m >= M) continue;
        const int bb = m / HWp;  const int rem = m - bb * HWp;
        const int ty = rem / Wp; const int tx  = rem - ty * Wp;
        const int oy = 2 * ty + py, ox = 2 * tx + px;
        float* yp = y + ((size_t)(bb * H2 + oy) * W2 + ox) * COUT + n0 + tc * 8;
        float4 o0, o1;
        o0.x = fmaxf(fmaf(acc[i][0], sc[0], bi[0]), 0.f);
        o0.y = fmaxf(fmaf(acc[i][1], sc[1], bi[1]), 0.f);
        o0.z = fmaxf(fmaf(acc[i][2], sc[2], bi[2]), 0.f);
        o0.w = fmaxf(fmaf(acc[i][3], sc[3], bi[3]), 0.f);
        o1.x = fmaxf(fmaf(acc[i][4], sc[4], bi[4]), 0.f);
        o1.y = fmaxf(fmaf(acc[i][5], sc[5], bi[5]), 0.f);
        o1.z = fmaxf(fmaf(acc[i][6], sc[6], bi[6]), 0.f);
        o1.w = fmaxf(fmaf(acc[i][7], sc[7], bi[7]), 0.f);
        *(float4*)yp       = o0;
        *(float4*)(yp + 4) = o1;
    }
}

// ---------------------------------------------------------------------------
// 1x1 conv 256->17, output transposed to [b*17+k][HWD] for the detector.
// One warp per pixel; 8 warps per block. NPIX = 108800 = 13600 * 8 exact.
// ---------------------------------------------------------------------------
__global__ void heatmap_kernel(const float* __restrict__ y3, const float* __restrict__ wf,
                               const float* __restrict__ bfin, float* __restrict__ hm)
{
    __shared__ float wfs[COUT * KPT];
    for (int i = threadIdx.x; i < COUT * KPT; i += blockDim.x) wfs[i] = wf[i];
    __syncthreads();

    const int warp = threadIdx.x >> 5, lane = threadIdx.x & 31;
    const int pix = blockIdx.x * 8 + warp;
    const float* yp = y3 + (size_t)pix * COUT;

    float acc[KPT];
#pragma unroll
    for (int k = 0; k < KPT; ++k) acc[k] = 0.f;

    for (int c = lane; c < COUT; c += 32) {
        const float v = yp[c];
        const float* wrow = wfs + c * KPT;
#pragma unroll
        for (int k = 0; k < KPT; ++k) acc[k] = fmaf(v, wrow[k], acc[k]);
    }
#pragma unroll
    for (int k = 0; k < KPT; ++k) {
        float v = acc[k];
        v += __shfl_xor_sync(0xffffffffu, v, 16);
        v += __shfl_xor_sync(0xffffffffu, v, 8);
        v += __shfl_xor_sync(0xffffffffu, v, 4);
        v += __shfl_xor_sync(0xffffffffu, v, 2);
        v += __shfl_xor_sync(0xffffffffu, v, 1);
        acc[k] = v;
    }
    if (lane == 0) {
        const int bb = pix / HWD; const int p = pix - bb * HWD;
#pragma unroll
        for (int k = 0; k < KPT; ++k)
            hm[(size_t)(bb * KPT + k) * HWD + p] = acc[k] + bfin[k];
    }
}

// ---------------------------------------------------------------------------
// Per-(b,k) argmax + subpixel refinement. First-occurrence tie-break.
// ---------------------------------------------------------------------------
__global__ void detect_kernel(const float* __restrict__ hm, float* __restrict__ out)
{
    const float* row = hm + (size_t)blockIdx.x * HWD;
    const int tid = threadIdx.x;                 // 128 threads

    float best = -3.402823466e+38f; int bidx = 0x7fffffff;
    for (int i = tid; i < HWD; i += 128) {
        const float v = row[i];
        if (v > best) { best = v; bidx = i; }    // strict > keeps earliest index
    }
    __shared__ float sv[128];
    __shared__ int   si[128];
    sv[tid] = best; si[tid] = bidx;
    __syncthreads();
    for (int s = 64; s > 0; s >>= 1) {
        if (tid < s) {
            const float v2 = sv[tid + s]; const int i2 = si[tid + s];
            if (v2 > sv[tid] || (v2 == sv[tid] && i2 < si[tid])) { sv[tid] = v2; si[tid] = i2; }
        }
        __syncthreads();
    }
    if (tid == 0) {
        const float score = sv[0];
        const int idx = si[0];
        const bool pos = score > 0.f;
        const int pxi = pos ? (idx % WD) : 0;
        const int pyi = pos ? (idx / WD) : 0;
        const bool inner = (pxi > 0) && (pxi < WD - 1) && (pyi > 0) && (pyi < HD - 1);
        float dx = 0.f, dy = 0.f;
        if (inner) {
            const int base = pyi * WD + pxi;
            const float d1 = row[base + 1]  - row[base - 1];
            const float d2 = row[base + WD] - row[base - WD];
            dx = (d1 > 0.f) ? 0.25f : ((d1 < 0.f) ? -0.25f : 0.f);
            dy = (d2 > 0.f) ? 0.25f : ((d2 < 0.f) ? -0.25f : 0.f);
        }
        float* o = out + (size_t)blockIdx.x * 3;
        o[0] = (float)pxi + dx;
        o[1] = (float)pyi + dy;
        o[2] = score;
    }
}

// ---------------------------------------------------------------------------
extern "C" void kernel_launch(void* const* d_in, const int* in_sizes, int n_in,
                              void* d_out, int out_size)
{
    const float* x  = (const float*)d_in[0];
    const float* w1 = (const float*)d_in[1];
    const float* g1 = (const float*)d_in[2];
    const float* b1 = (const float*)d_in[3];
    const float* m1 = (const float*)d_in[4];
    const float* v1 = (const float*)d_in[5];
    const float* w2 = (const float*)d_in[6];
    const float* g2 = (const float*)d_in[7];
    const float* b2 = (const float*)d_in[8];
    const float* m2 = (const float*)d_in[9];
    const float* v2 = (const float*)d_in[10];
    const float* w3 = (const float*)d_in[11];
    const float* g3 = (const float*)d_in[12];
    const float* b3 = (const float*)d_in[13];
    const float* m3 = (const float*)d_in[14];
    const float* v3 = (const float*)d_in[15];
    const float* wf = (const float*)d_in[16];
    const float* bf = (const float*)d_in[17];
    float* out = (float*)d_out;

    float* y1; cudaGetSymbolAddress((void**)&y1, g_y1);
    float* y2; cudaGetSymbolAddress((void**)&y2, g_y2);
    float* y3; cudaGetSymbolAddress((void**)&y3, g_y3);
    float* hm; cudaGetSymbolAddress((void**)&hm, g_hm);

    // L1: [64,8,6,2048] -> [64,14,10,256];  M_phase = 64*7*5   = 2240
    deconv_bn_relu<<<dim3(2, (2240  + TBM - 1) / TBM, 4), 256>>>(x,  w1, g1, b1, m1, v1, y1, 8,  6,  2048);
    // L2: -> [64,26,18,256];                M_phase = 64*13*9  = 7488
    deconv_bn_relu<<<dim3(2, (7488  + TBM - 1) / TBM, 4), 256>>>(y1, w2, g2, b2, m2, v2, y2, 14, 10, 256);
    // L3: -> [64,50,34,256];                M_phase = 64*25*17 = 27200
    deconv_bn_relu<<<dim3(2, (27200 + TBM - 1) / TBM, 4), 256>>>(y2, w3, g3, b3, m3, v3, y3, 26, 18, 256);
    // 1x1 conv to 17 heatmaps (transposed layout for the detector)
    heatmap_kernel<<<NPIX / 8, 256>>>(y3, wf, bf, hm);
    // argmax + subpixel per (b, keypoint)
    detect_kernel<<<BDIM_B * KPT, 128>>>(hm, out);
}

// round 4
// speedup vs baseline: 1.0894x; 1.0894x over previous
#include <cuda_runtime.h>
#include <cstdint>

// ---------------------------------------------------------------------------
// SimplePose via tcgen05 tf32 3-pass (fp32-equivalent) GEMMs.
//   3x (conv_transpose k4 s2 pads(1,1) + BN + ReLU) -> 1x1 conv -> argmax det
// Phase decomposition (py,px): kh = 2a+1-py, iy = ty+a  -> dense GEMM
//   M = B*(H-1)*(W-1), K = 4*Cin, N = 256 per phase.
// fp32 emulation: v = hi + lo, hi = cvt.rna.tf32(v);
//   C = Ah*Bh + Ah*Bl + Al*Bh  (3 tcgen05 passes into one fp32 TMEM tile)
//
// tcgen05 only exists in the arch-accelerated target (sm_103a). The harness
// also builds a plain compute_103 pass, so ALL tcgen05 PTX is gated on
// __CUDA_ARCH_FEAT_SM103_ALL with a correct naive fallback body for the
// non-accelerated pass (never executed on GB300: the sm_103a cubin wins).
// ---------------------------------------------------------------------------

#if defined(__CUDA_ARCH_FEAT_SM103_ALL) || defined(__CUDA_ARCH_FEAT_SM100_ALL)
#define TCPATH 1
#else
#define TCPATH 0
#endif

#define BDIM_B   64
#define COUT     256
#define KPT      17
#define BN_EPS   1e-5f
#define HD 50
#define WD 34
#define HWD (HD * WD)          // 1700
#define NPIX (BDIM_B * HWD)    // 108800

// ---------------- scratch (static; cudaMalloc forbidden) -------------------
__device__ float g_xh[BDIM_B * 8 * 6 * 2048];
__device__ float g_xl[BDIM_B * 8 * 6 * 2048];
__device__ float g_w1h[16 * COUT * 2048];
__device__ float g_w1l[16 * COUT * 2048];
__device__ float g_w2h[16 * COUT * 256];
__device__ float g_w2l[16 * COUT * 256];
__device__ float g_w3h[16 * COUT * 256];
__device__ float g_w3l[16 * COUT * 256];
__device__ float g_y1h[BDIM_B * 14 * 10 * COUT];
__device__ float g_y1l[BDIM_B * 14 * 10 * COUT];
__device__ float g_y2h[BDIM_B * 26 * 18 * COUT];
__device__ float g_y2l[BDIM_B * 26 * 18 * COUT];
__device__ float g_y3 [BDIM_B * HD * WD * COUT];
__device__ float g_hm [BDIM_B * KPT * HWD];

// ---------------------------- helpers (arch-neutral) -----------------------
__device__ __forceinline__ float tf32_hi(float v) {
    float r;
    asm("cvt.rna.tf32.f32 %0, %1;" : "=f"(r) : "f"(v));
    return r;
}

#if TCPATH
__device__ __forceinline__ uint32_t smem_u32(const void* p) {
    uint32_t a;
    asm("{ .reg .u64 t; cvta.to.shared.u64 t, %1; cvt.u32.u64 %0, t; }" : "=r"(a) : "l"(p));
    return a;
}
__device__ __forceinline__ uint32_t elect_one() {
    uint32_t pr;
    asm volatile("{\n\t.reg .pred p;\n\telect.sync _|p, 0xFFFFFFFF;\n\tselp.b32 %0, 1, 0, p;\n\t}" : "=r"(pr));
    return pr;
}

#define MBARRIER_INIT(addr, cnt) \
    asm volatile("mbarrier.init.shared.b64 [%0], %1;" :: "r"(addr), "r"(cnt) : "memory")
#define MBARRIER_INVAL(addr) \
    asm volatile("mbarrier.inval.shared.b64 [%0];" :: "r"(addr) : "memory")
__device__ __forceinline__ void mbar_wait(uint32_t mbar, uint32_t parity) {
    asm volatile(
        "{\n\t.reg .pred P;\n\t"
        "WL%=:\n\t"
        "mbarrier.try_wait.parity.acquire.cta.shared::cta.b64 P, [%0], %1, 0x989680;\n\t"
        "@P bra.uni WD%=;\n\t"
        "bra.uni WL%=;\n\t"
        "WD%=:\n\t}"
        :: "r"(mbar), "r"(parity) : "memory");
}
#define TCGEN05_ALLOC(sm, n) \
    asm volatile("tcgen05.alloc.cta_group::1.sync.aligned.shared::cta.b32 [%0], %1;" :: "r"(sm), "r"(n) : "memory")
#define TCGEN05_DEALLOC(tm, n) \
    asm volatile("tcgen05.dealloc.cta_group::1.sync.aligned.b32 %0, %1;" :: "r"(tm), "r"(n))
#define TCGEN05_RELINQ() \
    asm volatile("tcgen05.relinquish_alloc_permit.cta_group::1.sync.aligned;")
#define TCGEN05_COMMIT(mb) \
    asm volatile("tcgen05.commit.cta_group::1.mbarrier::arrive::one.shared::cluster.b64 [%0];" :: "r"(mb) : "memory")
#define TCGEN05_FENCE_AFTER() \
    asm volatile("tcgen05.fence::after_thread_sync;" ::: "memory")
#define TCGEN05_WAIT_LD() \
    asm volatile("tcgen05.wait::ld.sync.aligned;" ::: "memory")
#define FENCE_ASYNC_SHARED() \
    asm volatile("fence.proxy.async.shared::cta;" ::: "memory")

#define TCGEN05_LD_X32(r, tm) \
    asm volatile( \
        "tcgen05.ld.sync.aligned.32x32b.x32.b32 " \
        "{%0, %1, %2, %3, %4, %5, %6, %7, " \
        " %8, %9, %10, %11, %12, %13, %14, %15, " \
        " %16, %17, %18, %19, %20, %21, %22, %23, " \
        " %24, %25, %26, %27, %28, %29, %30, %31}, [%32];" \
        : "=r"((r)[0]),  "=r"((r)[1]),  "=r"((r)[2]),  "=r"((r)[3]), \
          "=r"((r)[4]),  "=r"((r)[5]),  "=r"((r)[6]),  "=r"((r)[7]), \
          "=r"((r)[8]),  "=r"((r)[9]),  "=r"((r)[10]), "=r"((r)[11]), \
          "=r"((r)[12]), "=r"((r)[13]), "=r"((r)[14]), "=r"((r)[15]), \
          "=r"((r)[16]), "=r"((r)[17]), "=r"((r)[18]), "=r"((r)[19]), \
          "=r"((r)[20]), "=r"((r)[21]), "=r"((r)[22]), "=r"((r)[23]), \
          "=r"((r)[24]), "=r"((r)[25]), "=r"((r)[26]), "=r"((r)[27]), \
          "=r"((r)[28]), "=r"((r)[29]), "=r"((r)[30]), "=r"((r)[31]) \
        : "r"(tm))

// SMEM descriptor (K-major SW128: LBO=1, SBO=64, version=1, layout=2)
#define SMEM_DESC_BASE \
    ((uint64_t(2) << 61) | (uint64_t(1) << 46) | (uint64_t(64) << 32) | (uint64_t(1) << 16))
#define MAKE_DESC(addr) (SMEM_DESC_BASE | ((uint64_t)((addr) >> 4) & 0x3FFF))

// tf32 SS MMA, cta_group::1, M=128, N=128, K=8 per issue
// idesc: dtype=F32(1)<<4 | atype=TF32(2)<<7 | btype=TF32(2)<<10 | (N/8)<<17 | (M/16)<<24
#define IDESC_TF32 ((1u << 4) | (2u << 7) | (2u << 10) | (16u << 17) | (8u << 24))

__device__ __forceinline__ void mma_tf32_ss(uint32_t d, uint64_t da, uint64_t db,
                                            uint32_t en) {
    asm volatile(
        "{\n\t.reg .pred p;\n\t"
        "setp.ne.u32 p, %4, 0;\n\t"
        "tcgen05.mma.cta_group::1.kind::tf32 [%0], %1, %2, %3, {%5, %5, %5, %5}, p;\n\t"
        "}"
        :: "r"(d), "l"(da), "l"(db), "r"(IDESC_TF32), "r"(en), "r"(0u)
        : "memory");
}
#endif  // TCPATH

#define SWZ(o) ((o) ^ (((o) >> 3) & 0x70))

// ---------------------------------------------------------------------------
// Preprocess: elementwise hi/lo split
// ---------------------------------------------------------------------------
__global__ void split_kernel(const float* __restrict__ in, float* __restrict__ hi,
                             float* __restrict__ lo, int n)
{
    for (int i = blockIdx.x * blockDim.x + threadIdx.x; i < n; i += gridDim.x * blockDim.x) {
        const float v = in[i];
        const float h = tf32_hi(v);
        hi[i] = h; lo[i] = v - h;
    }
}

// Weight transpose + split: w[t, ci, co] -> wt[t, co, ci] (hi/lo)
__global__ void wtrans_kernel(const float* __restrict__ w, float* __restrict__ th,
                              float* __restrict__ tl, int Cin)
{
    __shared__ float tile[32][33];
    const int t = blockIdx.z;
    const int ci0 = blockIdx.x * 32, co0 = blockIdx.y * 32;
    const int tx = threadIdx.x, ty = threadIdx.y;   // block (32, 8)
#pragma unroll
    for (int i = 0; i < 4; ++i)
        tile[ty + 8 * i][tx] = w[((size_t)(t * Cin + ci0 + ty + 8 * i)) * COUT + co0 + tx];
    __syncthreads();
#pragma unroll
    for (int i = 0; i < 4; ++i) {
        const float v = tile[tx][ty + 8 * i];
        const float h = tf32_hi(v);
        const size_t o = ((size_t)(t * COUT + co0 + ty + 8 * i)) * Cin + ci0 + tx;
        th[o] = h; tl[o] = v - h;
    }
}

// ---------------------------------------------------------------------------
// Deconv + BN + ReLU via tcgen05 tf32 3-pass.  Tile: M=128, N=256, TBK=32.
// 256 threads, double-buffered SMEM stages of 96KB.
// ---------------------------------------------------------------------------
#define STAGE_BYTES 98304
#define OFF_AH 0
#define OFF_AL 16384
#define OFF_BH 32768
#define OFF_BL 65536
#define SM_TMEMPTR 0
#define SM_MBAR 8
#define SM_SC 16
#define SM_BI (16 + 1024)
#define SM_STAGE0 4096
#define SMEM_TOTAL (SM_STAGE0 + 2 * STAGE_BYTES)   // 200704

__global__ __launch_bounds__(256, 1)
void deconv_tc(const float* __restrict__ Ah, const float* __restrict__ Al,
               const float* __restrict__ Wh, const float* __restrict__ Wl,
               const float* __restrict__ gma, const float* __restrict__ bta,
               const float* __restrict__ mu,  const float* __restrict__ var,
               float* __restrict__ Yh, float* __restrict__ Yl,   // split outputs (or null)
               float* __restrict__ Yp,                           // plain output (or null)
               int H, int W, int Cin, int split_out)
{
#if TCPATH
    extern __shared__ char smem[];
    const uint32_t sb = smem_u32(smem);
    const int tid = threadIdx.x;
    const int wid = tid >> 5, lane = tid & 31;

    const int phase = blockIdx.y;
    const int py = phase >> 1, px = phase & 1;
    const int m0 = blockIdx.x * 128;
    const int Hp = H - 1, Wp = W - 1;
    const int HWp = Hp * Wp;
    const int M = BDIM_B * HWp;
    const int NK = Cin >> 3;              // (4*Cin)/32

    // TMEM alloc (warp 0)
    if (wid == 0) { TCGEN05_ALLOC(sb + SM_TMEMPTR, 256); TCGEN05_RELINQ(); }
    // BN constants
    {
        const float s = gma[tid] * rsqrtf(var[tid] + BN_EPS);
        ((float*)(smem + SM_SC))[tid] = s;
        ((float*)(smem + SM_BI))[tid] = bta[tid] - mu[tid] * s;
    }
    if (tid == 0) MBARRIER_INIT(sb + SM_MBAR, 1);
    __syncthreads();
    uint32_t tmem;
    asm volatile("ld.shared.b32 %0, [%1];" : "=r"(tmem) : "r"(sb + SM_TMEMPTR));

    // A-row mapping (thread pair per row)
    const int r = tid >> 1, hh = tid & 1;
    int mrow = m0 + r; if (mrow >= M) mrow = M - 1;
    const int bbA = mrow / HWp; const int remA = mrow - bbA * HWp;
    const int tyA = remA / Wp;  const int txA = remA - tyA * Wp;
    const size_t arowbase = ((size_t)(bbA * H + tyA) * W + txA) * Cin;

    // ---- stage loader ----
    auto load_stage = [&](int s, int chunk) {
        const int kt = chunk * 32;
        const int tap = kt / Cin;
        const int ci0 = kt - tap * Cin;
        const int a = tap >> 1, bt = tap & 1;
        const uint32_t stgo = SM_STAGE0 + s * STAGE_BYTES;
        // A tiles: 128 rows x 32 f32, 2 threads per row
        {
            const size_t ao = arowbase + (size_t)(a * W + bt) * Cin + ci0 + hh * 16;
            const float* pah = Ah + ao;
            const float* pal = Al + ao;
#pragma unroll
            for (int j = 0; j < 4; ++j) {
                const uint32_t off = (uint32_t)(r * 128 + hh * 64 + 16 * j);
                const uint32_t sw = SWZ(off);
                *(float4*)(smem + stgo + OFF_AH + sw) = *(const float4*)(pah + 4 * j);
                *(float4*)(smem + stgo + OFF_AL + sw) = *(const float4*)(pal + 4 * j);
            }
        }
        // B tiles: 256 rows x 32 f32, 1 thread per row
        {
            const int kh = 2 * a + 1 - py, kw = 2 * bt + 1 - px;
            const size_t bo = ((size_t)((kh * 4 + kw) * COUT + tid)) * Cin + ci0;
            const float* pbh = Wh + bo;
            const float* pbl = Wl + bo;
#pragma unroll
            for (int j = 0; j < 8; ++j) {
                const uint32_t off = (uint32_t)(tid * 128 + 16 * j);
                const uint32_t sw = SWZ(off);
                *(float4*)(smem + stgo + OFF_BH + sw) = *(const float4*)(pbh + 4 * j);
                *(float4*)(smem + stgo + OFF_BL + sw) = *(const float4*)(pbl + 4 * j);
            }
        }
    };

    // ---- pipeline ----
    load_stage(0, 0);
    FENCE_ASYNC_SHARED();
    __syncthreads();

    for (int i = 0; i < NK; ++i) {
        const int s = i & 1;
        if (wid == 0) {
            if (elect_one()) {
                const uint32_t stg = sb + SM_STAGE0 + s * STAGE_BYTES;
                const uint64_t dAh = MAKE_DESC(stg + OFF_AH);
                const uint64_t dAl = MAKE_DESC(stg + OFF_AL);
                const uint64_t dBh = MAKE_DESC(stg + OFF_BH);
                const uint64_t dBl = MAKE_DESC(stg + OFF_BL);
#pragma unroll
                for (int ks = 0; ks < 4; ++ks) {
#pragma unroll
                    for (int pass = 0; pass < 3; ++pass) {
                        const uint64_t da = (pass == 2) ? dAl : dAh;
                        const uint64_t db = (pass == 1) ? dBl : dBh;
                        const uint32_t en = (i > 0 || ks > 0 || pass > 0) ? 1u : 0u;
                        mma_tf32_ss(tmem,       da + ks * 2, db + ks * 2,        en);
                        mma_tf32_ss(tmem + 128, da + ks * 2, db + 1024 + ks * 2, en);
                    }
                }
                TCGEN05_COMMIT(sb + SM_MBAR);
            }
        }
        if (i + 1 < NK) load_stage(s ^ 1, i + 1);
        FENCE_ASYNC_SHARED();
        mbar_wait(sb + SM_MBAR, (uint32_t)(i & 1));
        __syncthreads();
    }

    // ---- epilogue: BN + ReLU (+ optional hi/lo split), scatter to NHWC ----
    TCGEN05_FENCE_AFTER();
    const float* scs = (const float*)(smem + SM_SC);
    const float* bis = (const float*)(smem + SM_BI);
    const int sub = wid & 3, cg = wid >> 2;
    const int mloc = sub * 32 + lane;
    const int m = m0 + mloc;
    const bool valid = (m < M);
    int bb = 0, ty = 0, tx = 0;
    if (valid) { bb = m / HWp; const int rem = m - bb * HWp; ty = rem / Wp; tx = rem - ty * Wp; }
    const int H2 = 2 * H - 2, W2 = 2 * W - 2;
    const int oy = 2 * ty + py, ox = 2 * tx + px;
    const size_t obase = ((size_t)(bb * H2 + oy) * W2 + ox) * COUT;

#pragma unroll
    for (int q = 0; q < 4; ++q) {
        const int c0 = cg * 128 + q * 32;
        uint32_t regs[32];
        TCGEN05_LD_X32(regs, tmem + c0);
        TCGEN05_WAIT_LD();
        if (valid) {
#pragma unroll
            for (int k4 = 0; k4 < 8; ++k4) {
                float v[4];
#pragma unroll
                for (int e = 0; e < 4; ++e) {
                    const int c = c0 + k4 * 4 + e;
                    v[e] = fmaxf(fmaf(__uint_as_float(regs[k4 * 4 + e]), scs[c], bis[c]), 0.f);
                }
                if (split_out) {
                    float4 h4, l4;
                    h4.x = tf32_hi(v[0]); l4.x = v[0] - h4.x;
                    h4.y = tf32_hi(v[1]); l4.y = v[1] - h4.y;
                    h4.z = tf32_hi(v[2]); l4.z = v[2] - h4.z;
                    h4.w = tf32_hi(v[3]); l4.w = v[3] - h4.w;
                    *(float4*)(Yh + obase + c0 + k4 * 4) = h4;
                    *(float4*)(Yl + obase + c0 + k4 * 4) = l4;
                } else {
                    *(float4*)(Yp + obase + c0 + k4 * 4) = make_float4(v[0], v[1], v[2], v[3]);
                }
            }
        }
    }

    __syncthreads();
    if (tid == 0) MBARRIER_INVAL(sb + SM_MBAR);
    __syncthreads();
    if (wid == 0) TCGEN05_DEALLOC(tmem, 256);
#else
    // ------------------ fallback (non-accelerated pass; correct, slow) -----
    const int tid = threadIdx.x;
    const int phase = blockIdx.y;
    const int py = phase >> 1, px = phase & 1;
    const int m0 = blockIdx.x * 128;
    const int Hp = H - 1, Wp = W - 1;
    const int HWp = Hp * Wp;
    const int M = BDIM_B * HWp;
    const int H2 = 2 * H - 2, W2 = 2 * W - 2;

    for (int idx = tid; idx < 128 * COUT; idx += 256) {
        const int ml = idx >> 8, n = idx & 255;
        const int m = m0 + ml;
        if (m >= M) continue;
        const int bb = m / HWp; const int rem = m - bb * HWp;
        const int ty = rem / Wp; const int tx = rem - ty * Wp;
        float acc = 0.f;
        for (int tap = 0; tap < 4; ++tap) {
            const int a = tap >> 1, bt = tap & 1;
            const int kh = 2 * a + 1 - py, kw = 2 * bt + 1 - px;
            const float* ah = Ah + ((size_t)(bb * H + ty + a) * W + tx + bt) * Cin;
            const float* al = Al + ((size_t)(bb * H + ty + a) * W + tx + bt) * Cin;
            const float* wh = Wh + ((size_t)((kh * 4 + kw) * COUT + n)) * Cin;
            const float* wl = Wl + ((size_t)((kh * 4 + kw) * COUT + n)) * Cin;
            for (int c = 0; c < Cin; ++c)
                acc = fmaf(ah[c] + al[c], wh[c] + wl[c], acc);
        }
        const float s = gma[n] * rsqrtf(var[n] + BN_EPS);
        float v = fmaxf(fmaf(acc - mu[n], s, bta[n]), 0.f);
        const int oy = 2 * ty + py, ox = 2 * tx + px;
        const size_t o = ((size_t)(bb * H2 + oy) * W2 + ox) * COUT + n;
        if (split_out) { const float h = tf32_hi(v); Yh[o] = h; Yl[o] = v - h; }
        else Yp[o] = v;
    }
#endif
}

// ---------------------------------------------------------------------------
// 1x1 conv 256->17; 4 pixels per thread, broadcast weight LDS.
// Output transposed to [b*17+k][HWD].
// ---------------------------------------------------------------------------
__global__ __launch_bounds__(256)
void heatmap_kernel(const float* __restrict__ y3, const float* __restrict__ wf,
                    const float* __restrict__ bfin, float* __restrict__ hm)
{
    __shared__ float wfs[COUT * KPT];
    for (int i = threadIdx.x; i < COUT * KPT; i += blockDim.x) wfs[i] = wf[i];
    __syncthreads();

    const int t = blockIdx.x * 256 + threadIdx.x;
    if (t >= NPIX / 4) return;
    const int p0 = t * 4;
    const float* yp = y3 + (size_t)p0 * COUT;

    float acc[4][KPT];
#pragma unroll
    for (int p = 0; p < 4; ++p)
#pragma unroll
        for (int k = 0; k < KPT; ++k) acc[p][k] = 0.f;

    for (int c4 = 0; c4 < COUT / 4; ++c4) {
        float4 yv[4];
#pragma unroll
        for (int p = 0; p < 4; ++p) yv[p] = *(const float4*)(yp + p * COUT + c4 * 4);
        const float* wr = wfs + (c4 * 4) * KPT;
#pragma unroll
        for (int cc = 0; cc < 4; ++cc) {
            const float y0 = (cc == 0) ? yv[0].x : (cc == 1) ? yv[0].y : (cc == 2) ? yv[0].z : yv[0].w;
            const float y1 = (cc == 0) ? yv[1].x : (cc == 1) ? yv[1].y : (cc == 2) ? yv[1].z : yv[1].w;
            const float y2 = (cc == 0) ? yv[2].x : (cc == 1) ? yv[2].y : (cc == 2) ? yv[2].z : yv[2].w;
            const float y3v = (cc == 0) ? yv[3].x : (cc == 1) ? yv[3].y : (cc == 2) ? yv[3].z : yv[3].w;
#pragma unroll
            for (int k = 0; k < KPT; ++k) {
                const float wk = wr[cc * KPT + k];     // uniform -> broadcast
                acc[0][k] = fmaf(y0, wk, acc[0][k]);
                acc[1][k] = fmaf(y1, wk, acc[1][k]);
                acc[2][k] = fmaf(y2, wk, acc[2][k]);
                acc[3][k] = fmaf(y3v, wk, acc[3][k]);
            }
        }
    }
#pragma unroll
    for (int p = 0; p < 4; ++p) {
        const int pix = p0 + p;
        const int bb = pix / HWD; const int pp = pix - bb * HWD;
#pragma unroll
        for (int k = 0; k < KPT; ++k)
            hm[(size_t)(bb * KPT + k) * HWD + pp] = acc[p][k] + bfin[k];
    }
}

// ---------------------------------------------------------------------------
// Per-(b,k) argmax + subpixel refinement.
// ---------------------------------------------------------------------------
__global__ void detect_kernel(const float* __restrict__ hm, float* __restrict__ out)
{
    const float* row = hm + (size_t)blockIdx.x * HWD;
    const int tid = threadIdx.x;                 // 128 threads

    float best = -3.402823466e+38f; int bidx = 0x7fffffff;
    for (int i = tid; i < HWD; i += 128) {
        const float v = row[i];
        if (v > best) { best = v; bidx = i; }
    }
    __shared__ float sv[128];
    __shared__ int   si[128];
    sv[tid] = best; si[tid] = bidx;
    __syncthreads();
    for (int s = 64; s > 0; s >>= 1) {
        if (tid < s) {
            const float v2 = sv[tid + s]; const int i2 = si[tid + s];
            if (v2 > sv[tid] || (v2 == sv[tid] && i2 < si[tid])) { sv[tid] = v2; si[tid] = i2; }
        }
        __syncthreads();
    }
    if (tid == 0) {
        const float score = sv[0];
        const int idx = si[0];
        const bool pos = score > 0.f;
        const int pxi = pos ? (idx % WD) : 0;
        const int pyi = pos ? (idx / WD) : 0;
        const bool inner = (pxi > 0) && (pxi < WD - 1) && (pyi > 0) && (pyi < HD - 1);
        float dx = 0.f, dy = 0.f;
        if (inner) {
            const int base = pyi * WD + pxi;
            const float d1 = row[base + 1]  - row[base - 1];
            const float d2 = row[base + WD] - row[base - WD];
            dx = (d1 > 0.f) ? 0.25f : ((d1 < 0.f) ? -0.25f : 0.f);
            dy = (d2 > 0.f) ? 0.25f : ((d2 < 0.f) ? -0.25f : 0.f);
        }
        float* o = out + (size_t)blockIdx.x * 3;
        o[0] = (float)pxi + dx;
        o[1] = (float)pyi + dy;
        o[2] = score;
    }
}

// ---------------------------------------------------------------------------
extern "C" void kernel_launch(void* const* d_in, const int* in_sizes, int n_in,
                              void* d_out, int out_size)
{
    const float* x  = (const float*)d_in[0];
    const float* w1 = (const float*)d_in[1];
    const float* g1 = (const float*)d_in[2];
    const float* b1 = (const float*)d_in[3];
    const float* m1 = (const float*)d_in[4];
    const float* v1 = (const float*)d_in[5];
    const float* w2 = (const float*)d_in[6];
    const float* g2 = (const float*)d_in[7];
    const float* b2 = (const float*)d_in[8];
    const float* m2 = (const float*)d_in[9];
    const float* v2 = (const float*)d_in[10];
    const float* w3 = (const float*)d_in[11];
    const float* g3 = (const float*)d_in[12];
    const float* b3 = (const float*)d_in[13];
    const float* m3 = (const float*)d_in[14];
    const float* v3 = (const float*)d_in[15];
    const float* wf = (const float*)d_in[16];
    const float* bf = (const float*)d_in[17];
    float* out = (float*)d_out;

    float *xh, *xl, *w1h, *w1l, *w2h, *w2l, *w3h, *w3l;
    float *y1h, *y1l, *y2h, *y2l, *y3, *hm;
    cudaGetSymbolAddress((void**)&xh,  g_xh);
    cudaGetSymbolAddress((void**)&xl,  g_xl);
    cudaGetSymbolAddress((void**)&w1h, g_w1h);
    cudaGetSymbolAddress((void**)&w1l, g_w1l);
    cudaGetSymbolAddress((void**)&w2h, g_w2h);
    cudaGetSymbolAddress((void**)&w2l, g_w2l);
    cudaGetSymbolAddress((void**)&w3h, g_w3h);
    cudaGetSymbolAddress((void**)&w3l, g_w3l);
    cudaGetSymbolAddress((void**)&y1h, g_y1h);
    cudaGetSymbolAddress((void**)&y1l, g_y1l);
    cudaGetSymbolAddress((void**)&y2h, g_y2h);
    cudaGetSymbolAddress((void**)&y2l, g_y2l);
    cudaGetSymbolAddress((void**)&y3,  g_y3);
    cudaGetSymbolAddress((void**)&hm,  g_hm);

    static bool attr_done = false;
    if (!attr_done) {
        cudaFuncSetAttribute(deconv_tc, cudaFuncAttributeMaxDynamicSharedMemorySize, SMEM_TOTAL);
        attr_done = true;
    }

    // preprocess: split x; transpose+split weights
    split_kernel<<<4096, 256>>>(x, xh, xl, BDIM_B * 8 * 6 * 2048);
    wtrans_kernel<<<dim3(2048 / 32, COUT / 32, 16), dim3(32, 8)>>>(w1, w1h, w1l, 2048);
    wtrans_kernel<<<dim3(256 / 32,  COUT / 32, 16), dim3(32, 8)>>>(w2, w2h, w2l, 256);
    wtrans_kernel<<<dim3(256 / 32,  COUT / 32, 16), dim3(32, 8)>>>(w3, w3h, w3l, 256);

    // L1: [64,8,6,2048] -> [64,14,10,256] split.  M_phase = 2240 -> 18 blocks
    deconv_tc<<<dim3(18, 4), 256, SMEM_TOTAL>>>(xh, xl, w1h, w1l, g1, b1, m1, v1,
                                                y1h, y1l, nullptr, 8, 6, 2048, 1);
    // L2: -> [64,26,18,256] split.  M_phase = 7488 -> 59 blocks
    deconv_tc<<<dim3(59, 4), 256, SMEM_TOTAL>>>(y1h, y1l, w2h, w2l, g2, b2, m2, v2,
                                                y2h, y2l, nullptr, 14, 10, 256, 1);
    // L3: -> [64,50,34,256] plain.  M_phase = 27200 -> 213 blocks
    deconv_tc<<<dim3(213, 4), 256, SMEM_TOTAL>>>(y2h, y2l, w3h, w3l, g3, b3, m3, v3,
                                                 nullptr, nullptr, y3, 26, 18, 256, 0);
    // heatmap + detect
    heatmap_kernel<<<(NPIX / 4 + 255) / 256, 256>>>(y3, wf, bf, hm);
    detect_kernel<<<BDIM_B * KPT, 128>>>(hm, out);
}

// round 5
// speedup vs baseline: 1.8828x; 1.7284x over previous
#include <cuda_runtime.h>
#include <cstdint>

// ---------------------------------------------------------------------------
// SimplePose via tcgen05 tf32 3-pass (fp32-equivalent) GEMMs.
//   3x (conv_transpose k4 s2 pads(1,1) + BN + ReLU) -> 1x1 conv -> argmax det
// Phase decomposition (py,px): kh = 2a+1-py, iy = ty+a  -> dense GEMM
//   M = B*(H-1)*(W-1), K = 4*Cin, N = 256 per phase.
// fp32 emulation: v = hi + lo, hi = cvt.rna.tf32(v);
//   C = Ah*Bh + Ah*Bl + Al*Bh  (3 tcgen05 passes into one fp32 TMEM tile)
//
// Round 5: 128x128 tiles (grid x2 in N), 3-stage SMEM ring with lag-3
// buffer-reuse waits only (no per-chunk completion wait) so the tensor pipe
// streams continuously; tensor-queue backpressure paces the loop.
// ---------------------------------------------------------------------------

#if defined(__CUDA_ARCH_FEAT_SM103_ALL) || defined(__CUDA_ARCH_FEAT_SM100_ALL)
#define TCPATH 1
#else
#define TCPATH 0
#endif

#define BDIM_B   64
#define COUT     256
#define KPT      17
#define BN_EPS   1e-5f
#define HD 50
#define WD 34
#define HWD (HD * WD)          // 1700
#define NPIX (BDIM_B * HWD)    // 108800

// ---------------- scratch (static; cudaMalloc forbidden) -------------------
__device__ float g_xh[BDIM_B * 8 * 6 * 2048];
__device__ float g_xl[BDIM_B * 8 * 6 * 2048];
__device__ float g_w1h[16 * COUT * 2048];
__device__ float g_w1l[16 * COUT * 2048];
__device__ float g_w2h[16 * COUT * 256];
__device__ float g_w2l[16 * COUT * 256];
__device__ float g_w3h[16 * COUT * 256];
__device__ float g_w3l[16 * COUT * 256];
__device__ float g_y1h[BDIM_B * 14 * 10 * COUT];
__device__ float g_y1l[BDIM_B * 14 * 10 * COUT];
__device__ float g_y2h[BDIM_B * 26 * 18 * COUT];
__device__ float g_y2l[BDIM_B * 26 * 18 * COUT];
__device__ float g_y3 [BDIM_B * HD * WD * COUT];
__device__ float g_hm [BDIM_B * KPT * HWD];

// ---------------------------- helpers (arch-neutral) -----------------------
__device__ __forceinline__ float tf32_hi(float v) {
    float r;
    asm("cvt.rna.tf32.f32 %0, %1;" : "=f"(r) : "f"(v));
    return r;
}

#if TCPATH
__device__ __forceinline__ uint32_t smem_u32(const void* p) {
    uint32_t a;
    asm("{ .reg .u64 t; cvta.to.shared.u64 t, %1; cvt.u32.u64 %0, t; }" : "=r"(a) : "l"(p));
    return a;
}
__device__ __forceinline__ uint32_t elect_one() {
    uint32_t pr;
    asm volatile("{\n\t.reg .pred p;\n\telect.sync _|p, 0xFFFFFFFF;\n\tselp.b32 %0, 1, 0, p;\n\t}" : "=r"(pr));
    return pr;
}

#define MBARRIER_INIT(addr, cnt) \
    asm volatile("mbarrier.init.shared.b64 [%0], %1;" :: "r"(addr), "r"(cnt) : "memory")
#define MBARRIER_INVAL(addr) \
    asm volatile("mbarrier.inval.shared.b64 [%0];" :: "r"(addr) : "memory")
__device__ __forceinline__ void mbar_wait(uint32_t mbar, uint32_t parity) {
    asm volatile(
        "{\n\t.reg .pred P;\n\t"
        "WL%=:\n\t"
        "mbarrier.try_wait.parity.acquire.cta.shared::cta.b64 P, [%0], %1, 0x989680;\n\t"
        "@P bra.uni WD%=;\n\t"
        "bra.uni WL%=;\n\t"
        "WD%=:\n\t}"
        :: "r"(mbar), "r"(parity) : "memory");
}
#define TCGEN05_ALLOC(sm, n) \
    asm volatile("tcgen05.alloc.cta_group::1.sync.aligned.shared::cta.b32 [%0], %1;" :: "r"(sm), "r"(n) : "memory")
#define TCGEN05_DEALLOC(tm, n) \
    asm volatile("tcgen05.dealloc.cta_group::1.sync.aligned.b32 %0, %1;" :: "r"(tm), "r"(n))
#define TCGEN05_RELINQ() \
    asm volatile("tcgen05.relinquish_alloc_permit.cta_group::1.sync.aligned;")
#define TCGEN05_COMMIT(mb) \
    asm volatile("tcgen05.commit.cta_group::1.mbarrier::arrive::one.shared::cluster.b64 [%0];" :: "r"(mb) : "memory")
#define TCGEN05_FENCE_AFTER() \
    asm volatile("tcgen05.fence::after_thread_sync;" ::: "memory")
#define TCGEN05_WAIT_LD() \
    asm volatile("tcgen05.wait::ld.sync.aligned;" ::: "memory")
#define FENCE_ASYNC_SHARED() \
    asm volatile("fence.proxy.async.shared::cta;" ::: "memory")

#define TCGEN05_LD_X32(r, tm) \
    asm volatile( \
        "tcgen05.ld.sync.aligned.32x32b.x32.b32 " \
        "{%0, %1, %2, %3, %4, %5, %6, %7, " \
        " %8, %9, %10, %11, %12, %13, %14, %15, " \
        " %16, %17, %18, %19, %20, %21, %22, %23, " \
        " %24, %25, %26, %27, %28, %29, %30, %31}, [%32];" \
        : "=r"((r)[0]),  "=r"((r)[1]),  "=r"((r)[2]),  "=r"((r)[3]), \
          "=r"((r)[4]),  "=r"((r)[5]),  "=r"((r)[6]),  "=r"((r)[7]), \
          "=r"((r)[8]),  "=r"((r)[9]),  "=r"((r)[10]), "=r"((r)[11]), \
          "=r"((r)[12]), "=r"((r)[13]), "=r"((r)[14]), "=r"((r)[15]), \
          "=r"((r)[16]), "=r"((r)[17]), "=r"((r)[18]), "=r"((r)[19]), \
          "=r"((r)[20]), "=r"((r)[21]), "=r"((r)[22]), "=r"((r)[23]), \
          "=r"((r)[24]), "=r"((r)[25]), "=r"((r)[26]), "=r"((r)[27]), \
          "=r"((r)[28]), "=r"((r)[29]), "=r"((r)[30]), "=r"((r)[31]) \
        : "r"(tm))

// SMEM descriptor (K-major SW128: LBO=1, SBO=64, version=1, layout=2)
#define SMEM_DESC_BASE \
    ((uint64_t(2) << 61) | (uint64_t(1) << 46) | (uint64_t(64) << 32) | (uint64_t(1) << 16))
#define MAKE_DESC(addr) (SMEM_DESC_BASE | ((uint64_t)((addr) >> 4) & 0x3FFF))

// tf32 SS MMA, cta_group::1, M=128, N=128, K=8 per issue
#define IDESC_TF32 ((1u << 4) | (2u << 7) | (2u << 10) | (16u << 17) | (8u << 24))

__device__ __forceinline__ void mma_tf32_ss(uint32_t d, uint64_t da, uint64_t db,
                                            uint32_t en) {
    asm volatile(
        "{\n\t.reg .pred p;\n\t"
        "setp.ne.u32 p, %4, 0;\n\t"
        "tcgen05.mma.cta_group::1.kind::tf32 [%0], %1, %2, %3, {%5, %5, %5, %5}, p;\n\t"
        "}"
        :: "r"(d), "l"(da), "l"(db), "r"(IDESC_TF32), "r"(en), "r"(0u)
        : "memory");
}
#endif  // TCPATH

#define SWZ(o) ((o) ^ (((o) >> 3) & 0x70))

// ---------------------------------------------------------------------------
// Preprocess: elementwise hi/lo split
// ---------------------------------------------------------------------------
__global__ void split_kernel(const float* __restrict__ in, float* __restrict__ hi,
                             float* __restrict__ lo, int n)
{
    for (int i = blockIdx.x * blockDim.x + threadIdx.x; i < n; i += gridDim.x * blockDim.x) {
        const float v = in[i];
        const float h = tf32_hi(v);
        hi[i] = h; lo[i] = v - h;
    }
}

// Weight transpose + split: w[t, ci, co] -> wt[t, co, ci] (hi/lo)
__global__ void wtrans_kernel(const float* __restrict__ w, float* __restrict__ th,
                              float* __restrict__ tl, int Cin)
{
    __shared__ float tile[32][33];
    const int t = blockIdx.z;
    const int ci0 = blockIdx.x * 32, co0 = blockIdx.y * 32;
    const int tx = threadIdx.x, ty = threadIdx.y;   // block (32, 8)
#pragma unroll
    for (int i = 0; i < 4; ++i)
        tile[ty + 8 * i][tx] = w[((size_t)(t * Cin + ci0 + ty + 8 * i)) * COUT + co0 + tx];
    __syncthreads();
#pragma unroll
    for (int i = 0; i < 4; ++i) {
        const float v = tile[tx][ty + 8 * i];
        const float h = tf32_hi(v);
        const size_t o = ((size_t)(t * COUT + co0 + ty + 8 * i)) * Cin + ci0 + tx;
        th[o] = h; tl[o] = v - h;
    }
}

// ---------------------------------------------------------------------------
// Deconv + BN + ReLU via tcgen05 tf32 3-pass.
// Tile: M=128, N=128, chunk K=32.  3-stage SMEM ring (64KB each), lag-3
// buffer-reuse waits; one commit per chunk; single drain before epilogue.
// ---------------------------------------------------------------------------
#define STAGE_BYTES 65536
#define OFF_AH 0
#define OFF_AL 16384
#define OFF_BH 32768
#define OFF_BL 49152
#define SM_TMEMPTR 0
#define SM_MBAR 8              // 3 mbarriers at 8,16,24
#define SM_SC 32
#define SM_BI (32 + 1024)
#define SM_STAGE0 4096
#define SMEM_TOTAL (SM_STAGE0 + 3 * STAGE_BYTES)   // 200704

__global__ __launch_bounds__(256, 1)
void deconv_tc(const float* __restrict__ Ah, const float* __restrict__ Al,
               const float* __restrict__ Wh, const float* __restrict__ Wl,
               const float* __restrict__ gma, const float* __restrict__ bta,
               const float* __restrict__ mu,  const float* __restrict__ var,
               float* __restrict__ Yh, float* __restrict__ Yl,   // split outputs (or null)
               float* __restrict__ Yp,                           // plain output (or null)
               int H, int W, int Cin, int split_out)
{
#if TCPATH
    extern __shared__ char smem[];
    const uint32_t sb = smem_u32(smem);
    const int tid = threadIdx.x;
    const int wid = tid >> 5, lane = tid & 31;

    const int n0 = blockIdx.y * 128;
    const int phase = blockIdx.z;
    const int py = phase >> 1, px = phase & 1;
    const int m0 = blockIdx.x * 128;
    const int Hp = H - 1, Wp = W - 1;
    const int HWp = Hp * Wp;
    const int M = BDIM_B * HWp;
    const int NK = Cin >> 3;              // (4*Cin)/32

    if (wid == 0) { TCGEN05_ALLOC(sb + SM_TMEMPTR, 128); TCGEN05_RELINQ(); }
    {   // BN constants (all 256 channels; indexed globally)
        const float s = gma[tid] * rsqrtf(var[tid] + BN_EPS);
        ((float*)(smem + SM_SC))[tid] = s;
        ((float*)(smem + SM_BI))[tid] = bta[tid] - mu[tid] * s;
    }
    if (tid < 3) MBARRIER_INIT(sb + SM_MBAR + tid * 8, 1);
    __syncthreads();
    uint32_t tmem;
    asm volatile("ld.shared.b32 %0, [%1];" : "=r"(tmem) : "r"(sb + SM_TMEMPTR));

    // row mapping: 2 threads per row (r = 0..127, hh = half)
    const int r = tid >> 1, hh = tid & 1;
    int mrow = m0 + r; if (mrow >= M) mrow = M - 1;
    const int bbA = mrow / HWp; const int remA = mrow - bbA * HWp;
    const int tyA = remA / Wp;  const int txA = remA - tyA * Wp;
    const size_t arowbase = ((size_t)(bbA * H + tyA) * W + txA) * Cin;

    auto load_stage = [&](int s, int chunk) {
        const int kt = chunk * 32;
        const int tap = kt / Cin;
        const int ci0 = kt - tap * Cin;
        const int a = tap >> 1, bt = tap & 1;
        const uint32_t stgo = SM_STAGE0 + s * STAGE_BYTES;
        const uint32_t off = (uint32_t)(r * 128 + hh * 64);
        // A: 128 rows x 32 f32 (hi/lo)
        {
            const size_t ao = arowbase + (size_t)(a * W + bt) * Cin + ci0 + hh * 16;
            const float* pah = Ah + ao;
            const float* pal = Al + ao;
#pragma unroll
            for (int j = 0; j < 4; ++j) {
                const uint32_t sw = SWZ(off + 16 * j);
                *(float4*)(smem + stgo + OFF_AH + sw) = *(const float4*)(pah + 4 * j);
                *(float4*)(smem + stgo + OFF_AL + sw) = *(const float4*)(pal + 4 * j);
            }
        }
        // B: 128 rows (n0 + r) x 32 f32 (hi/lo)
        {
            const int kh = 2 * a + 1 - py, kw = 2 * bt + 1 - px;
            const size_t bo = ((size_t)((kh * 4 + kw) * COUT + n0 + r)) * Cin + ci0 + hh * 16;
            const float* pbh = Wh + bo;
            const float* pbl = Wl + bo;
#pragma unroll
            for (int j = 0; j < 4; ++j) {
                const uint32_t sw = SWZ(off + 16 * j);
                *(float4*)(smem + stgo + OFF_BH + sw) = *(const float4*)(pbh + 4 * j);
                *(float4*)(smem + stgo + OFF_BL + sw) = *(const float4*)(pbl + 4 * j);
            }
        }
    };

    // ---- mainloop: lag-3 ring; never wait on the current chunk ----
    for (int i = 0; i < NK; ++i) {
        const int s3 = i % 3;
        if (i >= 3) mbar_wait(sb + SM_MBAR + s3 * 8, (uint32_t)(((i / 3) - 1) & 1));
        load_stage(s3, i);
        FENCE_ASYNC_SHARED();
        __syncthreads();
        if (wid == 0) {
            if (elect_one()) {
                const uint32_t stg = sb + SM_STAGE0 + s3 * STAGE_BYTES;
                const uint64_t dAh = MAKE_DESC(stg + OFF_AH);
                const uint64_t dAl = MAKE_DESC(stg + OFF_AL);
                const uint64_t dBh = MAKE_DESC(stg + OFF_BH);
                const uint64_t dBl = MAKE_DESC(stg + OFF_BL);
#pragma unroll
                for (int ks = 0; ks < 4; ++ks) {
#pragma unroll
                    for (int pass = 0; pass < 3; ++pass) {
                        const uint64_t da = (pass == 2) ? dAl : dAh;
                        const uint64_t db = (pass == 1) ? dBl : dBh;
                        const uint32_t en = (i > 0 || ks > 0 || pass > 0) ? 1u : 0u;
                        mma_tf32_ss(tmem, da + ks * 2, db + ks * 2, en);
                    }
                }
                TCGEN05_COMMIT(sb + SM_MBAR + s3 * 8);
            }
        }
        // no completion wait here: tensor-queue backpressure paces the loop
    }

    // ---- drain: wait for the LAST chunk (in-order completion) ----
    {
        const int last = NK - 1;
        mbar_wait(sb + SM_MBAR + (last % 3) * 8, (uint32_t)((last / 3) & 1));
    }
    TCGEN05_FENCE_AFTER();
    __syncthreads();

    // ---- epilogue: 8 warps; warp w: rows (w&3)*32+lane, cols (w>>2)*64..+63
    const float* scs = (const float*)(smem + SM_SC);
    const float* bis = (const float*)(smem + SM_BI);
    const int sub = wid & 3, half = wid >> 2;
    const int m = m0 + sub * 32 + lane;
    const bool valid = (m < M);
    int bb = 0, ty = 0, tx = 0;
    if (valid) { bb = m / HWp; const int rem = m - bb * HWp; ty = rem / Wp; tx = rem - ty * Wp; }
    const int H2 = 2 * H - 2, W2 = 2 * W - 2;
    const int oy = 2 * ty + py, ox = 2 * tx + px;
    const size_t obase = ((size_t)(bb * H2 + oy) * W2 + ox) * COUT + n0;

#pragma unroll
    for (int q = 0; q < 2; ++q) {
        const int c0 = half * 64 + q * 32;
        uint32_t regs[32];
        TCGEN05_LD_X32(regs, tmem + c0);
        TCGEN05_WAIT_LD();
        if (valid) {
#pragma unroll
            for (int k4 = 0; k4 < 8; ++k4) {
                float v[4];
#pragma unroll
                for (int e = 0; e < 4; ++e) {
                    const int c = n0 + c0 + k4 * 4 + e;
                    v[e] = fmaxf(fmaf(__uint_as_float(regs[k4 * 4 + e]), scs[c], bis[c]), 0.f);
                }
                if (split_out) {
                    float4 h4, l4;
                    h4.x = tf32_hi(v[0]); l4.x = v[0] - h4.x;
                    h4.y = tf32_hi(v[1]); l4.y = v[1] - h4.y;
                    h4.z = tf32_hi(v[2]); l4.z = v[2] - h4.z;
                    h4.w = tf32_hi(v[3]); l4.w = v[3] - h4.w;
                    *(float4*)(Yh + obase + c0 + k4 * 4) = h4;
                    *(float4*)(Yl + obase + c0 + k4 * 4) = l4;
                } else {
                    *(float4*)(Yp + obase + c0 + k4 * 4) = make_float4(v[0], v[1], v[2], v[3]);
                }
            }
        }
    }

    __syncthreads();
    if (tid < 3) MBARRIER_INVAL(sb + SM_MBAR + tid * 8);
    __syncthreads();
    if (wid == 0) TCGEN05_DEALLOC(tmem, 128);
#else
    // ------------------ fallback (non-accelerated pass; correct, slow) -----
    const int tid = threadIdx.x;
    const int n0 = blockIdx.y * 128;
    const int phase = blockIdx.z;
    const int py = phase >> 1, px = phase & 1;
    const int m0 = blockIdx.x * 128;
    const int Hp = H - 1, Wp = W - 1;
    const int HWp = Hp * Wp;
    const int M = BDIM_B * HWp;
    const int H2 = 2 * H - 2, W2 = 2 * W - 2;

    for (int idx = tid; idx < 128 * 128; idx += 256) {
        const int ml = idx >> 7, n = n0 + (idx & 127);
        const int m = m0 + ml;
        if (m >= M) continue;
        const int bb = m / HWp; const int rem = m - bb * HWp;
        const int ty = rem / Wp; const int tx = rem - ty * Wp;
        float acc = 0.f;
        for (int tap = 0; tap < 4; ++tap) {
            const int a = tap >> 1, bt = tap & 1;
            const int kh = 2 * a + 1 - py, kw = 2 * bt + 1 - px;
            const float* ah = Ah + ((size_t)(bb * H + ty + a) * W + tx + bt) * Cin;
            const float* al = Al + ((size_t)(bb * H + ty + a) * W + tx + bt) * Cin;
            const float* wh = Wh + ((size_t)((kh * 4 + kw) * COUT + n)) * Cin;
            const float* wl = Wl + ((size_t)((kh * 4 + kw) * COUT + n)) * Cin;
            for (int c = 0; c < Cin; ++c)
                acc = fmaf(ah[c] + al[c], wh[c] + wl[c], acc);
        }
        const float s = gma[n] * rsqrtf(var[n] + BN_EPS);
        float v = fmaxf(fmaf(acc - mu[n], s, bta[n]), 0.f);
        const int oy = 2 * ty + py, ox = 2 * tx + px;
        const size_t o = ((size_t)(bb * H2 + oy) * W2 + ox) * COUT + n;
        if (split_out) { const float h = tf32_hi(v); Yh[o] = h; Yl[o] = v - h; }
        else Yp[o] = v;
    }
#endif
}

// ---------------------------------------------------------------------------
// 1x1 conv 256->17; 4 pixels per thread, broadcast weight LDS.
// Output transposed to [b*17+k][HWD].
// ---------------------------------------------------------------------------
__global__ __launch_bounds__(256)
void heatmap_kernel(const float* __restrict__ y3, const float* __restrict__ wf,
                    const float* __restrict__ bfin, float* __restrict__ hm)
{
    __shared__ float wfs[COUT * KPT];
    for (int i = threadIdx.x; i < COUT * KPT; i += blockDim.x) wfs[i] = wf[i];
    __syncthreads();

    const int t = blockIdx.x * 256 + threadIdx.x;
    if (t >= NPIX / 4) return;
    const int p0 = t * 4;
    const float* yp = y3 + (size_t)p0 * COUT;

    float acc[4][KPT];
#pragma unroll
    for (int p = 0; p < 4; ++p)
#pragma unroll
        for (int k = 0; k < KPT; ++k) acc[p][k] = 0.f;

    for (int c4 = 0; c4 < COUT / 4; ++c4) {
        float4 yv[4];
#pragma unroll
        for (int p = 0; p < 4; ++p) yv[p] = *(const float4*)(yp + p * COUT + c4 * 4);
        const float* wr = wfs + (c4 * 4) * KPT;
#pragma unroll
        for (int cc = 0; cc < 4; ++cc) {
            const float y0 = (cc == 0) ? yv[0].x : (cc == 1) ? yv[0].y : (cc == 2) ? yv[0].z : yv[0].w;
            const float y1 = (cc == 0) ? yv[1].x : (cc == 1) ? yv[1].y : (cc == 2) ? yv[1].z : yv[1].w;
            const float y2 = (cc == 0) ? yv[2].x : (cc == 1) ? yv[2].y : (cc == 2) ? yv[2].z : yv[2].w;
            const float y3v = (cc == 0) ? yv[3].x : (cc == 1) ? yv[3].y : (cc == 2) ? yv[3].z : yv[3].w;
#pragma unroll
            for (int k = 0; k < KPT; ++k) {
                const float wk = wr[cc * KPT + k];
                acc[0][k] = fmaf(y0, wk, acc[0][k]);
                acc[1][k] = fmaf(y1, wk, acc[1][k]);
                acc[2][k] = fmaf(y2, wk, acc[2][k]);
                acc[3][k] = fmaf(y3v, wk, acc[3][k]);
            }
        }
    }
#pragma unroll
    for (int p = 0; p < 4; ++p) {
        const int pix = p0 + p;
        const int bb = pix / HWD; const int pp = pix - bb * HWD;
#pragma unroll
        for (int k = 0; k < KPT; ++k)
            hm[(size_t)(bb * KPT + k) * HWD + pp] = acc[p][k] + bfin[k];
    }
}

// ---------------------------------------------------------------------------
// Per-(b,k) argmax + subpixel refinement.
// ---------------------------------------------------------------------------
__global__ void detect_kernel(const float* __restrict__ hm, float* __restrict__ out)
{
    const float* row = hm + (size_t)blockIdx.x * HWD;
    const int tid = threadIdx.x;                 // 128 threads

    float best = -3.402823466e+38f; int bidx = 0x7fffffff;
    for (int i = tid; i < HWD; i += 128) {
        const float v = row[i];
        if (v > best) { best = v; bidx = i; }
    }
    __shared__ float sv[128];
    __shared__ int   si[128];
    sv[tid] = best; si[tid] = bidx;
    __syncthreads();
    for (int s = 64; s > 0; s >>= 1) {
        if (tid < s) {
            const float v2 = sv[tid + s]; const int i2 = si[tid + s];
            if (v2 > sv[tid] || (v2 == sv[tid] && i2 < si[tid])) { sv[tid] = v2; si[tid] = i2; }
        }
        __syncthreads();
    }
    if (tid == 0) {
        const float score = sv[0];
        const int idx = si[0];
        const bool pos = score > 0.f;
        const int pxi = pos ? (idx % WD) : 0;
        const int pyi = pos ? (idx / WD) : 0;
        const bool inner = (pxi > 0) && (pxi < WD - 1) && (pyi > 0) && (pyi < HD - 1);
        float dx = 0.f, dy = 0.f;
        if (inner) {
            const int base = pyi * WD + pxi;
            const float d1 = row[base + 1]  - row[base - 1];
            const float d2 = row[base + WD] - row[base - WD];
            dx = (d1 > 0.f) ? 0.25f : ((d1 < 0.f) ? -0.25f : 0.f);
            dy = (d2 > 0.f) ? 0.25f : ((d2 < 0.f) ? -0.25f : 0.f);
        }
        float* o = out + (size_t)blockIdx.x * 3;
        o[0] = (float)pxi + dx;
        o[1] = (float)pyi + dy;
        o[2] = score;
    }
}

// ---------------------------------------------------------------------------
extern "C" void kernel_launch(void* const* d_in, const int* in_sizes, int n_in,
                              void* d_out, int out_size)
{
    const float* x  = (const float*)d_in[0];
    const float* w1 = (const float*)d_in[1];
    const float* g1 = (const float*)d_in[2];
    const float* b1 = (const float*)d_in[3];
    const float* m1 = (const float*)d_in[4];
    const float* v1 = (const float*)d_in[5];
    const float* w2 = (const float*)d_in[6];
    const float* g2 = (const float*)d_in[7];
    const float* b2 = (const float*)d_in[8];
    const float* m2 = (const float*)d_in[9];
    const float* v2 = (const float*)d_in[10];
    const float* w3 = (const float*)d_in[11];
    const float* g3 = (const float*)d_in[12];
    const float* b3 = (const float*)d_in[13];
    const float* m3 = (const float*)d_in[14];
    const float* v3 = (const float*)d_in[15];
    const float* wf = (const float*)d_in[16];
    const float* bf = (const float*)d_in[17];
    float* out = (float*)d_out;

    float *xh, *xl, *w1h, *w1l, *w2h, *w2l, *w3h, *w3l;
    float *y1h, *y1l, *y2h, *y2l, *y3, *hm;
    cudaGetSymbolAddress((void**)&xh,  g_xh);
    cudaGetSymbolAddress((void**)&xl,  g_xl);
    cudaGetSymbolAddress((void**)&w1h, g_w1h);
    cudaGetSymbolAddress((void**)&w1l, g_w1l);
    cudaGetSymbolAddress((void**)&w2h, g_w2h);
    cudaGetSymbolAddress((void**)&w2l, g_w2l);
    cudaGetSymbolAddress((void**)&w3h, g_w3h);
    cudaGetSymbolAddress((void**)&w3l, g_w3l);
    cudaGetSymbolAddress((void**)&y1h, g_y1h);
    cudaGetSymbolAddress((void**)&y1l, g_y1l);
    cudaGetSymbolAddress((void**)&y2h, g_y2h);
    cudaGetSymbolAddress((void**)&y2l, g_y2l);
    cudaGetSymbolAddress((void**)&y3,  g_y3);
    cudaGetSymbolAddress((void**)&hm,  g_hm);

    static bool attr_done = false;
    if (!attr_done) {
        cudaFuncSetAttribute(deconv_tc, cudaFuncAttributeMaxDynamicSharedMemorySize, SMEM_TOTAL);
        attr_done = true;
    }

    // preprocess: split x; transpose+split weights
    split_kernel<<<4096, 256>>>(x, xh, xl, BDIM_B * 8 * 6 * 2048);
    wtrans_kernel<<<dim3(2048 / 32, COUT / 32, 16), dim3(32, 8)>>>(w1, w1h, w1l, 2048);
    wtrans_kernel<<<dim3(256 / 32,  COUT / 32, 16), dim3(32, 8)>>>(w2, w2h, w2l, 256);
    wtrans_kernel<<<dim3(256 / 32,  COUT / 32, 16), dim3(32, 8)>>>(w3, w3h, w3l, 256);

    // grids: (mblocks, nblocks=2, phases=4)
    // L1: [64,8,6,2048] -> [64,14,10,256] split.  M_phase = 2240 -> 18
    deconv_tc<<<dim3(18, 2, 4), 256, SMEM_TOTAL>>>(xh, xl, w1h, w1l, g1, b1, m1, v1,
                                                   y1h, y1l, nullptr, 8, 6, 2048, 1);
    // L2: -> [64,26,18,256] split.  M_phase = 7488 -> 59
    deconv_tc<<<dim3(59, 2, 4), 256, SMEM_TOTAL>>>(y1h, y1l, w2h, w2l, g2, b2, m2, v2,
                                                   y2h, y2l, nullptr, 14, 10, 256, 1);
    // L3: -> [64,50,34,256] plain.  M_phase = 27200 -> 213
    deconv_tc<<<dim3(213, 2, 4), 256, SMEM_TOTAL>>>(y2h, y2l, w3h, w3l, g3, b3, m3, v3,
                                                    nullptr, nullptr, y3, 26, 18, 256, 0);
    // heatmap + detect
    heatmap_kernel<<<(NPIX / 4 + 255) / 256, 256>>>(y3, wf, bf, hm);
    detect_kernel<<<BDIM_B * KPT, 128>>>(hm, out);
}

// round 6
// speedup vs baseline: 2.2485x; 1.1942x over previous
#include <cuda_runtime.h>
#include <cstdint>

// ---------------------------------------------------------------------------
// SimplePose via tcgen05 tf32 3-pass (fp32-equivalent) GEMMs.
//   3x (conv_transpose k4 s2 pads(1,1) + BN + ReLU) -> 1x1 conv -> argmax det
// Phase decomposition (py,px): kh = 2a+1-py, iy = ty+a  -> dense GEMM
//   M = B*(H-1)*(W-1), K = 4*Cin, N = 256 per phase.
// fp32 emulation: v = hi + lo, hi = cvt.rna.tf32(v);
//   C = Ah*Bh + Ah*Bl + Al*Bh  (3 tcgen05 passes into one fp32 TMEM tile)
//
// Round 6: warp-specialized producer/consumer. 288 threads: warps 0-7 load
// (free-running, 3-stage ring, lag-3 reuse waits on MMA-done), warp 9th is a
// dedicated MMA issuer paced by full[] mbarriers. No __syncthreads in the
// mainloop -> LDG latency and tcgen05 dispatch-queue stalls fully overlap.
// ---------------------------------------------------------------------------

#if defined(__CUDA_ARCH_FEAT_SM103_ALL) || defined(__CUDA_ARCH_FEAT_SM100_ALL)
#define TCPATH 1
#else
#define TCPATH 0
#endif

#define BDIM_B   64
#define COUT     256
#define KPT      17
#define BN_EPS   1e-5f
#define HD 50
#define WD 34
#define HWD (HD * WD)          // 1700
#define NPIX (BDIM_B * HWD)    // 108800
#define NTHR 288               // 8 loader warps + 1 MMA warp

// ---------------- scratch (static; cudaMalloc forbidden) -------------------
__device__ float g_xh[BDIM_B * 8 * 6 * 2048];
__device__ float g_xl[BDIM_B * 8 * 6 * 2048];
__device__ float g_w1h[16 * COUT * 2048];
__device__ float g_w1l[16 * COUT * 2048];
__device__ float g_w2h[16 * COUT * 256];
__device__ float g_w2l[16 * COUT * 256];
__device__ float g_w3h[16 * COUT * 256];
__device__ float g_w3l[16 * COUT * 256];
__device__ float g_y1h[BDIM_B * 14 * 10 * COUT];
__device__ float g_y1l[BDIM_B * 14 * 10 * COUT];
__device__ float g_y2h[BDIM_B * 26 * 18 * COUT];
__device__ float g_y2l[BDIM_B * 26 * 18 * COUT];
__device__ float g_y3 [BDIM_B * HD * WD * COUT];
__device__ float g_hm [BDIM_B * KPT * HWD];

// ---------------------------- helpers (arch-neutral) -----------------------
__device__ __forceinline__ float tf32_hi(float v) {
    float r;
    asm("cvt.rna.tf32.f32 %0, %1;" : "=f"(r) : "f"(v));
    return r;
}

#if TCPATH
__device__ __forceinline__ uint32_t smem_u32(const void* p) {
    uint32_t a;
    asm("{ .reg .u64 t; cvta.to.shared.u64 t, %1; cvt.u32.u64 %0, t; }" : "=r"(a) : "l"(p));
    return a;
}
__device__ __forceinline__ uint32_t elect_one() {
    uint32_t pr;
    asm volatile("{\n\t.reg .pred p;\n\telect.sync _|p, 0xFFFFFFFF;\n\tselp.b32 %0, 1, 0, p;\n\t}" : "=r"(pr));
    return pr;
}

#define MBARRIER_INIT(addr, cnt) \
    asm volatile("mbarrier.init.shared.b64 [%0], %1;" :: "r"(addr), "r"(cnt) : "memory")
#define MBARRIER_INVAL(addr) \
    asm volatile("mbarrier.inval.shared.b64 [%0];" :: "r"(addr) : "memory")
#define MBARRIER_ARRIVE(addr) \
    asm volatile("mbarrier.arrive.release.cta.shared::cta.b64 _, [%0];" :: "r"(addr) : "memory")
__device__ __forceinline__ void mbar_wait(uint32_t mbar, uint32_t parity) {
    asm volatile(
        "{\n\t.reg .pred P;\n\t"
        "WL%=:\n\t"
        "mbarrier.try_wait.parity.acquire.cta.shared::cta.b64 P, [%0], %1, 0x989680;\n\t"
        "@P bra.uni WD%=;\n\t"
        "bra.uni WL%=;\n\t"
        "WD%=:\n\t}"
        :: "r"(mbar), "r"(parity) : "memory");
}
#define TCGEN05_ALLOC(sm, n) \
    asm volatile("tcgen05.alloc.cta_group::1.sync.aligned.shared::cta.b32 [%0], %1;" :: "r"(sm), "r"(n) : "memory")
#define TCGEN05_DEALLOC(tm, n) \
    asm volatile("tcgen05.dealloc.cta_group::1.sync.aligned.b32 %0, %1;" :: "r"(tm), "r"(n))
#define TCGEN05_RELINQ() \
    asm volatile("tcgen05.relinquish_alloc_permit.cta_group::1.sync.aligned;")
#define TCGEN05_COMMIT(mb) \
    asm volatile("tcgen05.commit.cta_group::1.mbarrier::arrive::one.shared::cluster.b64 [%0];" :: "r"(mb) : "memory")
#define TCGEN05_FENCE_AFTER() \
    asm volatile("tcgen05.fence::after_thread_sync;" ::: "memory")
#define TCGEN05_WAIT_LD() \
    asm volatile("tcgen05.wait::ld.sync.aligned;" ::: "memory")
#define FENCE_ASYNC_SHARED() \
    asm volatile("fence.proxy.async.shared::cta;" ::: "memory")

#define TCGEN05_LD_X32(r, tm) \
    asm volatile( \
        "tcgen05.ld.sync.aligned.32x32b.x32.b32 " \
        "{%0, %1, %2, %3, %4, %5, %6, %7, " \
        " %8, %9, %10, %11, %12, %13, %14, %15, " \
        " %16, %17, %18, %19, %20, %21, %22, %23, " \
        " %24, %25, %26, %27, %28, %29, %30, %31}, [%32];" \
        : "=r"((r)[0]),  "=r"((r)[1]),  "=r"((r)[2]),  "=r"((r)[3]), \
          "=r"((r)[4]),  "=r"((r)[5]),  "=r"((r)[6]),  "=r"((r)[7]), \
          "=r"((r)[8]),  "=r"((r)[9]),  "=r"((r)[10]), "=r"((r)[11]), \
          "=r"((r)[12]), "=r"((r)[13]), "=r"((r)[14]), "=r"((r)[15]), \
          "=r"((r)[16]), "=r"((r)[17]), "=r"((r)[18]), "=r"((r)[19]), \
          "=r"((r)[20]), "=r"((r)[21]), "=r"((r)[22]), "=r"((r)[23]), \
          "=r"((r)[24]), "=r"((r)[25]), "=r"((r)[26]), "=r"((r)[27]), \
          "=r"((r)[28]), "=r"((r)[29]), "=r"((r)[30]), "=r"((r)[31]) \
        : "r"(tm))

// SMEM descriptor (K-major SW128: LBO=1, SBO=64, version=1, layout=2)
#define SMEM_DESC_BASE \
    ((uint64_t(2) << 61) | (uint64_t(1) << 46) | (uint64_t(64) << 32) | (uint64_t(1) << 16))
#define MAKE_DESC(addr) (SMEM_DESC_BASE | ((uint64_t)((addr) >> 4) & 0x3FFF))

// tf32 SS MMA, cta_group::1, M=128, N=128, K=8 per issue
#define IDESC_TF32 ((1u << 4) | (2u << 7) | (2u << 10) | (16u << 17) | (8u << 24))

__device__ __forceinline__ void mma_tf32_ss(uint32_t d, uint64_t da, uint64_t db,
                                            uint32_t en) {
    asm volatile(
        "{\n\t.reg .pred p;\n\t"
        "setp.ne.u32 p, %4, 0;\n\t"
        "tcgen05.mma.cta_group::1.kind::tf32 [%0], %1, %2, %3, {%5, %5, %5, %5}, p;\n\t"
        "}"
        :: "r"(d), "l"(da), "l"(db), "r"(IDESC_TF32), "r"(en), "r"(0u)
        : "memory");
}
#endif  // TCPATH

#define SWZ(o) ((o) ^ (((o) >> 3) & 0x70))

// ---------------------------------------------------------------------------
// Preprocess: elementwise hi/lo split
// ---------------------------------------------------------------------------
__global__ void split_kernel(const float* __restrict__ in, float* __restrict__ hi,
                             float* __restrict__ lo, int n)
{
    for (int i = blockIdx.x * blockDim.x + threadIdx.x; i < n; i += gridDim.x * blockDim.x) {
        const float v = in[i];
        const float h = tf32_hi(v);
        hi[i] = h; lo[i] = v - h;
    }
}

// Weight transpose + split: w[t, ci, co] -> wt[t, co, ci] (hi/lo)
__global__ void wtrans_kernel(const float* __restrict__ w, float* __restrict__ th,
                              float* __restrict__ tl, int Cin)
{
    __shared__ float tile[32][33];
    const int t = blockIdx.z;
    const int ci0 = blockIdx.x * 32, co0 = blockIdx.y * 32;
    const int tx = threadIdx.x, ty = threadIdx.y;   // block (32, 8)
#pragma unroll
    for (int i = 0; i < 4; ++i)
        tile[ty + 8 * i][tx] = w[((size_t)(t * Cin + ci0 + ty + 8 * i)) * COUT + co0 + tx];
    __syncthreads();
#pragma unroll
    for (int i = 0; i < 4; ++i) {
        const float v = tile[tx][ty + 8 * i];
        const float h = tf32_hi(v);
        const size_t o = ((size_t)(t * COUT + co0 + ty + 8 * i)) * Cin + ci0 + tx;
        th[o] = h; tl[o] = v - h;
    }
}

// ---------------------------------------------------------------------------
// Deconv + BN + ReLU via tcgen05 tf32 3-pass. Warp-specialized.
// Tile: M=128, N=128, chunk K=32.  3-stage SMEM ring (64KB each).
//   full[s]: 256 loader arrivals  -> MMA warp may consume stage s
//   done[s]: tcgen05.commit       -> loaders may overwrite stage s (lag-3)
// ---------------------------------------------------------------------------
#define STAGE_BYTES 65536
#define OFF_AH 0
#define OFF_AL 16384
#define OFF_BH 32768
#define OFF_BL 49152
#define SM_TMEMPTR 0
#define SM_FULL 8              // 3 mbarriers at 8,16,24
#define SM_DONE 32             // 3 mbarriers at 32,40,48
#define SM_SC 64
#define SM_BI (64 + 1024)
#define SM_STAGE0 4096
#define SMEM_TOTAL (SM_STAGE0 + 3 * STAGE_BYTES)   // 200704

__global__ __launch_bounds__(NTHR, 1)
void deconv_tc(const float* __restrict__ Ah, const float* __restrict__ Al,
               const float* __restrict__ Wh, const float* __restrict__ Wl,
               const float* __restrict__ gma, const float* __restrict__ bta,
               const float* __restrict__ mu,  const float* __restrict__ var,
               float* __restrict__ Yh, float* __restrict__ Yl,   // split outputs (or null)
               float* __restrict__ Yp,                           // plain output (or null)
               int H, int W, int Cin, int split_out)
{
#if TCPATH
    extern __shared__ char smem[];
    const uint32_t sb = smem_u32(smem);
    const int tid = threadIdx.x;
    const int wid = tid >> 5, lane = tid & 31;

    const int n0 = blockIdx.y * 128;
    const int phase = blockIdx.z;
    const int py = phase >> 1, px = phase & 1;
    const int m0 = blockIdx.x * 128;
    const int Hp = H - 1, Wp = W - 1;
    const int HWp = Hp * Wp;
    const int M = BDIM_B * HWp;
    const int NK = Cin >> 3;              // (4*Cin)/32

    if (wid == 0) { TCGEN05_ALLOC(sb + SM_TMEMPTR, 128); TCGEN05_RELINQ(); }
    if (tid < 256) {  // BN constants for all 256 channels
        const float s = gma[tid] * rsqrtf(var[tid] + BN_EPS);
        ((float*)(smem + SM_SC))[tid] = s;
        ((float*)(smem + SM_BI))[tid] = bta[tid] - mu[tid] * s;
    }
    if (tid < 3) MBARRIER_INIT(sb + SM_FULL + tid * 8, 256);
    else if (tid >= 32 && tid < 35) MBARRIER_INIT(sb + SM_DONE + (tid - 32) * 8, 1);
    __syncthreads();
    uint32_t tmem;
    asm volatile("ld.shared.b32 %0, [%1];" : "=r"(tmem) : "r"(sb + SM_TMEMPTR));

    if (wid < 8) {
        // =================== LOADER: warps 0-7 (256 threads) ===============
        const int r = tid >> 1, hh = tid & 1;
        int mrow = m0 + r; if (mrow >= M) mrow = M - 1;
        const int bbA = mrow / HWp; const int remA = mrow - bbA * HWp;
        const int tyA = remA / Wp;  const int txA = remA - tyA * Wp;
        const size_t arowbase = ((size_t)(bbA * H + tyA) * W + txA) * Cin;
        const uint32_t off = (uint32_t)(r * 128 + hh * 64);
        uint32_t swo[4];
#pragma unroll
        for (int j = 0; j < 4; ++j) swo[j] = SWZ(off + 16 * j);

        for (int i = 0; i < NK; ++i) {
            const int s3 = (i >= 3) ? (i - 3 * (i / 3)) : i;   // i % 3
            if (i >= 3) mbar_wait(sb + SM_DONE + s3 * 8, (uint32_t)(((i / 3) - 1) & 1));
            const int kt = i * 32;
            const int tap = kt / Cin;
            const int ci0 = kt - tap * Cin;
            const int a = tap >> 1, bt = tap & 1;
            const uint32_t stgo = SM_STAGE0 + s3 * STAGE_BYTES;
            {   // A: 128 rows x 32 f32 (hi/lo)
                const size_t ao = arowbase + (size_t)(a * W + bt) * Cin + ci0 + hh * 16;
                const float* pah = Ah + ao;
                const float* pal = Al + ao;
#pragma unroll
                for (int j = 0; j < 4; ++j) {
                    *(float4*)(smem + stgo + OFF_AH + swo[j]) = *(const float4*)(pah + 4 * j);
                    *(float4*)(smem + stgo + OFF_AL + swo[j]) = *(const float4*)(pal + 4 * j);
                }
            }
            {   // B: 128 rows (n0 + r) x 32 f32 (hi/lo)
                const int kh = 2 * a + 1 - py, kw = 2 * bt + 1 - px;
                const size_t bo = ((size_t)((kh * 4 + kw) * COUT + n0 + r)) * Cin + ci0 + hh * 16;
                const float* pbh = Wh + bo;
                const float* pbl = Wl + bo;
#pragma unroll
                for (int j = 0; j < 4; ++j) {
                    *(float4*)(smem + stgo + OFF_BH + swo[j]) = *(const float4*)(pbh + 4 * j);
                    *(float4*)(smem + stgo + OFF_BL + swo[j]) = *(const float4*)(pbl + 4 * j);
                }
            }
            FENCE_ASYNC_SHARED();
            MBARRIER_ARRIVE(sb + SM_FULL + s3 * 8);
        }
    } else {
        // =================== MMA ISSUER: warp 8 ============================
        if (elect_one()) {
            for (int i = 0; i < NK; ++i) {
                const int s3 = i - 3 * (i / 3);
                mbar_wait(sb + SM_FULL + s3 * 8, (uint32_t)((i / 3) & 1));
                const uint32_t stg = sb + SM_STAGE0 + s3 * STAGE_BYTES;
                const uint64_t dAh = MAKE_DESC(stg + OFF_AH);
                const uint64_t dAl = MAKE_DESC(stg + OFF_AL);
                const uint64_t dBh = MAKE_DESC(stg + OFF_BH);
                const uint64_t dBl = MAKE_DESC(stg + OFF_BL);
#pragma unroll
                for (int ks = 0; ks < 4; ++ks) {
#pragma unroll
                    for (int pass = 0; pass < 3; ++pass) {
                        const uint64_t da = (pass == 2) ? dAl : dAh;
                        const uint64_t db = (pass == 1) ? dBl : dBh;
                        const uint32_t en = (i > 0 || ks > 0 || pass > 0) ? 1u : 0u;
                        mma_tf32_ss(tmem, da + ks * 2, db + ks * 2, en);
                    }
                }
                TCGEN05_COMMIT(sb + SM_DONE + s3 * 8);
            }
        }
    }

    // ---- drain: everyone waits for the final chunk's completion ----
    {
        const int last = NK - 1;
        mbar_wait(sb + SM_DONE + (last % 3) * 8, (uint32_t)((last / 3) & 1));
    }
    TCGEN05_FENCE_AFTER();
    __syncthreads();

    // ---- epilogue (warps 0-7): BN + ReLU (+ split), scatter to NHWC ----
    if (wid < 8) {
        const float* scs = (const float*)(smem + SM_SC);
        const float* bis = (const float*)(smem + SM_BI);
        const int sub = wid & 3, half = wid >> 2;
        const int m = m0 + sub * 32 + lane;
        const bool valid = (m < M);
        int bb = 0, ty = 0, tx = 0;
        if (valid) { bb = m / HWp; const int rem = m - bb * HWp; ty = rem / Wp; tx = rem - ty * Wp; }
        const int H2 = 2 * H - 2, W2 = 2 * W - 2;
        const int oy = 2 * ty + py, ox = 2 * tx + px;
        const size_t obase = ((size_t)(bb * H2 + oy) * W2 + ox) * COUT + n0;

#pragma unroll
        for (int q = 0; q < 2; ++q) {
            const int c0 = half * 64 + q * 32;
            uint32_t regs[32];
            TCGEN05_LD_X32(regs, tmem + c0);
            TCGEN05_WAIT_LD();
            if (valid) {
#pragma unroll
                for (int k4 = 0; k4 < 8; ++k4) {
                    float v[4];
#pragma unroll
                    for (int e = 0; e < 4; ++e) {
                        const int c = n0 + c0 + k4 * 4 + e;
                        v[e] = fmaxf(fmaf(__uint_as_float(regs[k4 * 4 + e]), scs[c], bis[c]), 0.f);
                    }
                    if (split_out) {
                        float4 h4, l4;
                        h4.x = tf32_hi(v[0]); l4.x = v[0] - h4.x;
                        h4.y = tf32_hi(v[1]); l4.y = v[1] - h4.y;
                        h4.z = tf32_hi(v[2]); l4.z = v[2] - h4.z;
                        h4.w = tf32_hi(v[3]); l4.w = v[3] - h4.w;
                        *(float4*)(Yh + obase + c0 + k4 * 4) = h4;
                        *(float4*)(Yl + obase + c0 + k4 * 4) = l4;
                    } else {
                        *(float4*)(Yp + obase + c0 + k4 * 4) = make_float4(v[0], v[1], v[2], v[3]);
                    }
                }
            }
        }
    }

    __syncthreads();
    if (tid < 3) MBARRIER_INVAL(sb + SM_FULL + tid * 8);
    else if (tid >= 32 && tid < 35) MBARRIER_INVAL(sb + SM_DONE + (tid - 32) * 8);
    __syncthreads();
    if (wid == 0) TCGEN05_DEALLOC(tmem, 128);
#else
    // ------------------ fallback (non-accelerated pass; correct, slow) -----
    const int tid = threadIdx.x;
    const int n0 = blockIdx.y * 128;
    const int phase = blockIdx.z;
    const int py = phase >> 1, px = phase & 1;
    const int m0 = blockIdx.x * 128;
    const int Hp = H - 1, Wp = W - 1;
    const int HWp = Hp * Wp;
    const int M = BDIM_B * HWp;
    const int H2 = 2 * H - 2, W2 = 2 * W - 2;

    for (int idx = tid; idx < 128 * 128; idx += NTHR) {
        const int ml = idx >> 7, n = n0 + (idx & 127);
        const int m = m0 + ml;
        if (m >= M) continue;
        const int bb = m / HWp; const int rem = m - bb * HWp;
        const int ty = rem / Wp; const int tx = rem - ty * Wp;
        float acc = 0.f;
        for (int tap = 0; tap < 4; ++tap) {
            const int a = tap >> 1, bt = tap & 1;
            const int kh = 2 * a + 1 - py, kw = 2 * bt + 1 - px;
            const float* ah = Ah + ((size_t)(bb * H + ty + a) * W + tx + bt) * Cin;
            const float* al = Al + ((size_t)(bb * H + ty + a) * W + tx + bt) * Cin;
            const float* wh = Wh + ((size_t)((kh * 4 + kw) * COUT + n)) * Cin;
            const float* wl = Wl + ((size_t)((kh * 4 + kw) * COUT + n)) * Cin;
            for (int c = 0; c < Cin; ++c)
                acc = fmaf(ah[c] + al[c], wh[c] + wl[c], acc);
        }
        const float s = gma[n] * rsqrtf(var[n] + BN_EPS);
        float v = fmaxf(fmaf(acc - mu[n], s, bta[n]), 0.f);
        const int oy = 2 * ty + py, ox = 2 * tx + px;
        const size_t o = ((size_t)(bb * H2 + oy) * W2 + ox) * COUT + n;
        if (split_out) { const float h = tf32_hi(v); Yh[o] = h; Yl[o] = v - h; }
        else Yp[o] = v;
    }
#endif
}

// ---------------------------------------------------------------------------
// 1x1 conv 256->17; 4 pixels per thread, broadcast weight LDS.
// Output transposed to [b*17+k][HWD].
// ---------------------------------------------------------------------------
__global__ __launch_bounds__(256)
void heatmap_kernel(const float* __restrict__ y3, const float* __restrict__ wf,
                    const float* __restrict__ bfin, float* __restrict__ hm)
{
    __shared__ float wfs[COUT * KPT];
    for (int i = threadIdx.x; i < COUT * KPT; i += blockDim.x) wfs[i] = wf[i];
    __syncthreads();

    const int t = blockIdx.x * 256 + threadIdx.x;
    if (t >= NPIX / 4) return;
    const int p0 = t * 4;
    const float* yp = y3 + (size_t)p0 * COUT;

    float acc[4][KPT];
#pragma unroll
    for (int p = 0; p < 4; ++p)
#pragma unroll
        for (int k = 0; k < KPT; ++k) acc[p][k] = 0.f;

    for (int c4 = 0; c4 < COUT / 4; ++c4) {
        float4 yv[4];
#pragma unroll
        for (int p = 0; p < 4; ++p) yv[p] = *(const float4*)(yp + p * COUT + c4 * 4);
        const float* wr = wfs + (c4 * 4) * KPT;
#pragma unroll
        for (int cc = 0; cc < 4; ++cc) {
            const float y0 = (cc == 0) ? yv[0].x : (cc == 1) ? yv[0].y : (cc == 2) ? yv[0].z : yv[0].w;
            const float y1 = (cc == 0) ? yv[1].x : (cc == 1) ? yv[1].y : (cc == 2) ? yv[1].z : yv[1].w;
            const float y2 = (cc == 0) ? yv[2].x : (cc == 1) ? yv[2].y : (cc == 2) ? yv[2].z : yv[2].w;
            const float y3v = (cc == 0) ? yv[3].x : (cc == 1) ? yv[3].y : (cc == 2) ? yv[3].z : yv[3].w;
#pragma unroll
            for (int k = 0; k < KPT; ++k) {
                const float wk = wr[cc * KPT + k];
                acc[0][k] = fmaf(y0, wk, acc[0][k]);
                acc[1][k] = fmaf(y1, wk, acc[1][k]);
                acc[2][k] = fmaf(y2, wk, acc[2][k]);
                acc[3][k] = fmaf(y3v, wk, acc[3][k]);
            }
        }
    }
#pragma unroll
    for (int p = 0; p < 4; ++p) {
        const int pix = p0 + p;
        const int bb = pix / HWD; const int pp = pix - bb * HWD;
#pragma unroll
        for (int k = 0; k < KPT; ++k)
            hm[(size_t)(bb * KPT + k) * HWD + pp] = acc[p][k] + bfin[k];
    }
}

// ---------------------------------------------------------------------------
// Per-(b,k) argmax + subpixel refinement.
// ---------------------------------------------------------------------------
__global__ void detect_kernel(const float* __restrict__ hm, float* __restrict__ out)
{
    const float* row = hm + (size_t)blockIdx.x * HWD;
    const int tid = threadIdx.x;                 // 128 threads

    float best = -3.402823466e+38f; int bidx = 0x7fffffff;
    for (int i = tid; i < HWD; i += 128) {
        const float v = row[i];
        if (v > best) { best = v; bidx = i; }
    }
    __shared__ float sv[128];
    __shared__ int   si[128];
    sv[tid] = best; si[tid] = bidx;
    __syncthreads();
    for (int s = 64; s > 0; s >>= 1) {
        if (tid < s) {
            const float v2 = sv[tid + s]; const int i2 = si[tid + s];
            if (v2 > sv[tid] || (v2 == sv[tid] && i2 < si[tid])) { sv[tid] = v2; si[tid] = i2; }
        }
        __syncthreads();
    }
    if (tid == 0) {
        const float score = sv[0];
        const int idx = si[0];
        const bool pos = score > 0.f;
        const int pxi = pos ? (idx % WD) : 0;
        const int pyi = pos ? (idx / WD) : 0;
        const bool inner = (pxi > 0) && (pxi < WD - 1) && (pyi > 0) && (pyi < HD - 1);
        float dx = 0.f, dy = 0.f;
        if (inner) {
            const int base = pyi * WD + pxi;
            const float d1 = row[base + 1]  - row[base - 1];
            const float d2 = row[base + WD] - row[base - WD];
            dx = (d1 > 0.f) ? 0.25f : ((d1 < 0.f) ? -0.25f : 0.f);
            dy = (d2 > 0.f) ? 0.25f : ((d2 < 0.f) ? -0.25f : 0.f);
        }
        float* o = out + (size_t)blockIdx.x * 3;
        o[0] = (float)pxi + dx;
        o[1] = (float)pyi + dy;
        o[2] = score;
    }
}

// ---------------------------------------------------------------------------
extern "C" void kernel_launch(void* const* d_in, const int* in_sizes, int n_in,
                              void* d_out, int out_size)
{
    const float* x  = (const float*)d_in[0];
    const float* w1 = (const float*)d_in[1];
    const float* g1 = (const float*)d_in[2];
    const float* b1 = (const float*)d_in[3];
    const float* m1 = (const float*)d_in[4];
    const float* v1 = (const float*)d_in[5];
    const float* w2 = (const float*)d_in[6];
    const float* g2 = (const float*)d_in[7];
    const float* b2 = (const float*)d_in[8];
    const float* m2 = (const float*)d_in[9];
    const float* v2 = (const float*)d_in[10];
    const float* w3 = (const float*)d_in[11];
    const float* g3 = (const float*)d_in[12];
    const float* b3 = (const float*)d_in[13];
    const float* m3 = (const float*)d_in[14];
    const float* v3 = (const float*)d_in[15];
    const float* wf = (const float*)d_in[16];
    const float* bf = (const float*)d_in[17];
    float* out = (float*)d_out;

    float *xh, *xl, *w1h, *w1l, *w2h, *w2l, *w3h, *w3l;
    float *y1h, *y1l, *y2h, *y2l, *y3, *hm;
    cudaGetSymbolAddress((void**)&xh,  g_xh);
    cudaGetSymbolAddress((void**)&xl,  g_xl);
    cudaGetSymbolAddress((void**)&w1h, g_w1h);
    cudaGetSymbolAddress((void**)&w1l, g_w1l);
    cudaGetSymbolAddress((void**)&w2h, g_w2h);
    cudaGetSymbolAddress((void**)&w2l, g_w2l);
    cudaGetSymbolAddress((void**)&w3h, g_w3h);
    cudaGetSymbolAddress((void**)&w3l, g_w3l);
    cudaGetSymbolAddress((void**)&y1h, g_y1h);
    cudaGetSymbolAddress((void**)&y1l, g_y1l);
    cudaGetSymbolAddress((void**)&y2h, g_y2h);
    cudaGetSymbolAddress((void**)&y2l, g_y2l);
    cudaGetSymbolAddress((void**)&y3,  g_y3);
    cudaGetSymbolAddress((void**)&hm,  g_hm);

    static bool attr_done = false;
    if (!attr_done) {
        cudaFuncSetAttribute(deconv_tc, cudaFuncAttributeMaxDynamicSharedMemorySize, SMEM_TOTAL);
        attr_done = true;
    }

    // preprocess: split x; transpose+split weights
    split_kernel<<<4096, 256>>>(x, xh, xl, BDIM_B * 8 * 6 * 2048);
    wtrans_kernel<<<dim3(2048 / 32, COUT / 32, 16), dim3(32, 8)>>>(w1, w1h, w1l, 2048);
    wtrans_kernel<<<dim3(256 / 32,  COUT / 32, 16), dim3(32, 8)>>>(w2, w2h, w2l, 256);
    wtrans_kernel<<<dim3(256 / 32,  COUT / 32, 16), dim3(32, 8)>>>(w3, w3h, w3l, 256);

    // grids: (mblocks, nblocks=2, phases=4)
    // L1: [64,8,6,2048] -> [64,14,10,256] split.  M_phase = 2240 -> 18
    deconv_tc<<<dim3(18, 2, 4), NTHR, SMEM_TOTAL>>>(xh, xl, w1h, w1l, g1, b1, m1, v1,
                                                    y1h, y1l, nullptr, 8, 6, 2048, 1);
    // L2: -> [64,26,18,256] split.  M_phase = 7488 -> 59
    deconv_tc<<<dim3(59, 2, 4), NTHR, SMEM_TOTAL>>>(y1h, y1l, w2h, w2l, g2, b2, m2, v2,
                                                    y2h, y2l, nullptr, 14, 10, 256, 1);
    // L3: -> [64,50,34,256] plain.  M_phase = 27200 -> 213
    deconv_tc<<<dim3(213, 2, 4), NTHR, SMEM_TOTAL>>>(y2h, y2l, w3h, w3l, g3, b3, m3, v3,
                                                     nullptr, nullptr, y3, 26, 18, 256, 0);
    // heatmap + detect
    heatmap_kernel<<<(NPIX / 4 + 255) / 256, 256>>>(y3, wf, bf, hm);
    detect_kernel<<<BDIM_B * KPT, 128>>>(hm, out);
}

// round 7
// speedup vs baseline: 3.0577x; 1.3599x over previous
#include <cuda_runtime.h>
#include <cstdint>

// ---------------------------------------------------------------------------
// SimplePose via tcgen05 tf32 3-pass (fp32-equivalent) GEMMs.
//   3x (conv_transpose k4 s2 pads(1,1) + BN + ReLU) -> 1x1 conv -> argmax det
// Phase decomposition (py,px): kh = 2a+1-py, iy = ty+a  -> dense GEMM
//   M = B*(H-1)*(W-1), K = 4*Cin, N = 256 per phase.
// fp32 emulation: v = hi + lo, hi = cvt.rna.tf32(v);
//   C = Ah*Bh + Ah*Bl + Al*Bh  (3 tcgen05 passes into one fp32 TMEM tile)
//
// Round 7: L2/L3 use m-paired 256x256 tiles (2 M-tiles share one full-N B
// tile; D = 512 TMEM cols) to halve L2/LTS traffic. Ring slot = one
// (chunk, hi/lo half) of 64KB; MMA consumes 2 slots per chunk; 3-slot ring.
// L1 (K=8192) keeps the round-6 128x128 warp-specialized kernel.
// ---------------------------------------------------------------------------

#if defined(__CUDA_ARCH_FEAT_SM103_ALL) || defined(__CUDA_ARCH_FEAT_SM100_ALL)
#define TCPATH 1
#else
#define TCPATH 0
#endif

#define BDIM_B   64
#define COUT     256
#define KPT      17
#define BN_EPS   1e-5f
#define HD 50
#define WD 34
#define HWD (HD * WD)          // 1700
#define NPIX (BDIM_B * HWD)    // 108800
#define NTHR 288               // 8 loader warps + 1 MMA warp

// ---------------- scratch (static; cudaMalloc forbidden) -------------------
__device__ float g_xh[BDIM_B * 8 * 6 * 2048];
__device__ float g_xl[BDIM_B * 8 * 6 * 2048];
__device__ float g_w1h[16 * COUT * 2048];
__device__ float g_w1l[16 * COUT * 2048];
__device__ float g_w2h[16 * COUT * 256];
__device__ float g_w2l[16 * COUT * 256];
__device__ float g_w3h[16 * COUT * 256];
__device__ float g_w3l[16 * COUT * 256];
__device__ float g_y1h[BDIM_B * 14 * 10 * COUT];
__device__ float g_y1l[BDIM_B * 14 * 10 * COUT];
__device__ float g_y2h[BDIM_B * 26 * 18 * COUT];
__device__ float g_y2l[BDIM_B * 26 * 18 * COUT];
__device__ float g_y3 [BDIM_B * HD * WD * COUT];
__device__ float g_hm [BDIM_B * KPT * HWD];

// ---------------------------- helpers (arch-neutral) -----------------------
__device__ __forceinline__ float tf32_hi(float v) {
    float r;
    asm("cvt.rna.tf32.f32 %0, %1;" : "=f"(r) : "f"(v));
    return r;
}

#if TCPATH
__device__ __forceinline__ uint32_t smem_u32(const void* p) {
    uint32_t a;
    asm("{ .reg .u64 t; cvta.to.shared.u64 t, %1; cvt.u32.u64 %0, t; }" : "=r"(a) : "l"(p));
    return a;
}
__device__ __forceinline__ uint32_t elect_one() {
    uint32_t pr;
    asm volatile("{\n\t.reg .pred p;\n\telect.sync _|p, 0xFFFFFFFF;\n\tselp.b32 %0, 1, 0, p;\n\t}" : "=r"(pr));
    return pr;
}

#define MBARRIER_INIT(addr, cnt) \
    asm volatile("mbarrier.init.shared.b64 [%0], %1;" :: "r"(addr), "r"(cnt) : "memory")
#define MBARRIER_INVAL(addr) \
    asm volatile("mbarrier.inval.shared.b64 [%0];" :: "r"(addr) : "memory")
#define MBARRIER_ARRIVE(addr) \
    asm volatile("mbarrier.arrive.release.cta.shared::cta.b64 _, [%0];" :: "r"(addr) : "memory")
__device__ __forceinline__ void mbar_wait(uint32_t mbar, uint32_t parity) {
    asm volatile(
        "{\n\t.reg .pred P;\n\t"
        "WL%=:\n\t"
        "mbarrier.try_wait.parity.acquire.cta.shared::cta.b64 P, [%0], %1, 0x989680;\n\t"
        "@P bra.uni WD%=;\n\t"
        "bra.uni WL%=;\n\t"
        "WD%=:\n\t}"
        :: "r"(mbar), "r"(parity) : "memory");
}
#define TCGEN05_ALLOC(sm, n) \
    asm volatile("tcgen05.alloc.cta_group::1.sync.aligned.shared::cta.b32 [%0], %1;" :: "r"(sm), "r"(n) : "memory")
#define TCGEN05_DEALLOC(tm, n) \
    asm volatile("tcgen05.dealloc.cta_group::1.sync.aligned.b32 %0, %1;" :: "r"(tm), "r"(n))
#define TCGEN05_RELINQ() \
    asm volatile("tcgen05.relinquish_alloc_permit.cta_group::1.sync.aligned;")
#define TCGEN05_COMMIT(mb) \
    asm volatile("tcgen05.commit.cta_group::1.mbarrier::arrive::one.shared::cluster.b64 [%0];" :: "r"(mb) : "memory")
#define TCGEN05_FENCE_AFTER() \
    asm volatile("tcgen05.fence::after_thread_sync;" ::: "memory")
#define TCGEN05_WAIT_LD() \
    asm volatile("tcgen05.wait::ld.sync.aligned;" ::: "memory")
#define FENCE_ASYNC_SHARED() \
    asm volatile("fence.proxy.async.shared::cta;" ::: "memory")

#define TCGEN05_LD_X32(r, tm) \
    asm volatile( \
        "tcgen05.ld.sync.aligned.32x32b.x32.b32 " \
        "{%0, %1, %2, %3, %4, %5, %6, %7, " \
        " %8, %9, %10, %11, %12, %13, %14, %15, " \
        " %16, %17, %18, %19, %20, %21, %22, %23, " \
        " %24, %25, %26, %27, %28, %29, %30, %31}, [%32];" \
        : "=r"((r)[0]),  "=r"((r)[1]),  "=r"((r)[2]),  "=r"((r)[3]), \
          "=r"((r)[4]),  "=r"((r)[5]),  "=r"((r)[6]),  "=r"((r)[7]), \
          "=r"((r)[8]),  "=r"((r)[9]),  "=r"((r)[10]), "=r"((r)[11]), \
          "=r"((r)[12]), "=r"((r)[13]), "=r"((r)[14]), "=r"((r)[15]), \
          "=r"((r)[16]), "=r"((r)[17]), "=r"((r)[18]), "=r"((r)[19]), \
          "=r"((r)[20]), "=r"((r)[21]), "=r"((r)[22]), "=r"((r)[23]), \
          "=r"((r)[24]), "=r"((r)[25]), "=r"((r)[26]), "=r"((r)[27]), \
          "=r"((r)[28]), "=r"((r)[29]), "=r"((r)[30]), "=r"((r)[31]) \
        : "r"(tm))

// SMEM descriptor (K-major SW128: LBO=1, SBO=64, version=1, layout=2)
#define SMEM_DESC_BASE \
    ((uint64_t(2) << 61) | (uint64_t(1) << 46) | (uint64_t(64) << 32) | (uint64_t(1) << 16))
#define MAKE_DESC(addr) (SMEM_DESC_BASE | ((uint64_t)((addr) >> 4) & 0x3FFF))

// tf32 SS MMA, cta_group::1, M=128, N=128, K=8 per issue
#define IDESC_TF32 ((1u << 4) | (2u << 7) | (2u << 10) | (16u << 17) | (8u << 24))

__device__ __forceinline__ void mma_tf32_ss(uint32_t d, uint64_t da, uint64_t db,
                                            uint32_t en) {
    asm volatile(
        "{\n\t.reg .pred p;\n\t"
        "setp.ne.u32 p, %4, 0;\n\t"
        "tcgen05.mma.cta_group::1.kind::tf32 [%0], %1, %2, %3, {%5, %5, %5, %5}, p;\n\t"
        "}"
        :: "r"(d), "l"(da), "l"(db), "r"(IDESC_TF32), "r"(en), "r"(0u)
        : "memory");
}
#endif  // TCPATH

#define SWZ(o) ((o) ^ (((o) >> 3) & 0x70))

// ---------------------------------------------------------------------------
// Preprocess: elementwise hi/lo split
// ---------------------------------------------------------------------------
__global__ void split_kernel(const float* __restrict__ in, float* __restrict__ hi,
                             float* __restrict__ lo, int n)
{
    for (int i = blockIdx.x * blockDim.x + threadIdx.x; i < n; i += gridDim.x * blockDim.x) {
        const float v = in[i];
        const float h = tf32_hi(v);
        hi[i] = h; lo[i] = v - h;
    }
}

// Weight transpose + split: w[t, ci, co] -> wt[t, co, ci] (hi/lo)
__global__ void wtrans_kernel(const float* __restrict__ w, float* __restrict__ th,
                              float* __restrict__ tl, int Cin)
{
    __shared__ float tile[32][33];
    const int t = blockIdx.z;
    const int ci0 = blockIdx.x * 32, co0 = blockIdx.y * 32;
    const int tx = threadIdx.x, ty = threadIdx.y;   // block (32, 8)
#pragma unroll
    for (int i = 0; i < 4; ++i)
        tile[ty + 8 * i][tx] = w[((size_t)(t * Cin + ci0 + ty + 8 * i)) * COUT + co0 + tx];
    __syncthreads();
#pragma unroll
    for (int i = 0; i < 4; ++i) {
        const float v = tile[tx][ty + 8 * i];
        const float h = tf32_hi(v);
        const size_t o = ((size_t)(t * COUT + co0 + ty + 8 * i)) * Cin + ci0 + tx;
        th[o] = h; tl[o] = v - h;
    }
}

// ===========================================================================
// Kernel A (round-6): 128x128 tiles, used for L1 (K=8192).
// ===========================================================================
#define STAGE_BYTES 65536
#define OFF_AH 0
#define OFF_AL 16384
#define OFF_BH 32768
#define OFF_BL 49152
#define SM_TMEMPTR 0
#define SM_FULL 8
#define SM_DONE 32
#define SM_SC 64
#define SM_BI (64 + 1024)
#define SM_STAGE0 4096
#define SMEM_TOTAL (SM_STAGE0 + 3 * STAGE_BYTES)   // 200704

__global__ __launch_bounds__(NTHR, 1)
void deconv_tc(const float* __restrict__ Ah, const float* __restrict__ Al,
               const float* __restrict__ Wh, const float* __restrict__ Wl,
               const float* __restrict__ gma, const float* __restrict__ bta,
               const float* __restrict__ mu,  const float* __restrict__ var,
               float* __restrict__ Yh, float* __restrict__ Yl,
               float* __restrict__ Yp,
               int H, int W, int Cin, int split_out)
{
#if TCPATH
    extern __shared__ char smem[];
    const uint32_t sb = smem_u32(smem);
    const int tid = threadIdx.x;
    const int wid = tid >> 5, lane = tid & 31;

    const int n0 = blockIdx.y * 128;
    const int phase = blockIdx.z;
    const int py = phase >> 1, px = phase & 1;
    const int m0 = blockIdx.x * 128;
    const int Hp = H - 1, Wp = W - 1;
    const int HWp = Hp * Wp;
    const int M = BDIM_B * HWp;
    const int NK = Cin >> 3;

    if (wid == 0) { TCGEN05_ALLOC(sb + SM_TMEMPTR, 128); TCGEN05_RELINQ(); }
    if (tid < 256) {
        const float s = gma[tid] * rsqrtf(var[tid] + BN_EPS);
        ((float*)(smem + SM_SC))[tid] = s;
        ((float*)(smem + SM_BI))[tid] = bta[tid] - mu[tid] * s;
    }
    if (tid < 3) MBARRIER_INIT(sb + SM_FULL + tid * 8, 256);
    else if (tid >= 32 && tid < 35) MBARRIER_INIT(sb + SM_DONE + (tid - 32) * 8, 1);
    __syncthreads();
    uint32_t tmem;
    asm volatile("ld.shared.b32 %0, [%1];" : "=r"(tmem) : "r"(sb + SM_TMEMPTR));

    if (wid < 8) {
        const int r = tid >> 1, hh = tid & 1;
        int mrow = m0 + r; if (mrow >= M) mrow = M - 1;
        const int bbA = mrow / HWp; const int remA = mrow - bbA * HWp;
        const int tyA = remA / Wp;  const int txA = remA - tyA * Wp;
        const size_t arowbase = ((size_t)(bbA * H + tyA) * W + txA) * Cin;
        const uint32_t off = (uint32_t)(r * 128 + hh * 64);
        uint32_t swo[4];
#pragma unroll
        for (int j = 0; j < 4; ++j) swo[j] = SWZ(off + 16 * j);

        for (int i = 0; i < NK; ++i) {
            const int s3 = i - 3 * (i / 3);
            if (i >= 3) mbar_wait(sb + SM_DONE + s3 * 8, (uint32_t)(((i / 3) - 1) & 1));
            const int kt = i * 32;
            const int tap = kt / Cin;
            const int ci0 = kt - tap * Cin;
            const int a = tap >> 1, bt = tap & 1;
            const uint32_t stgo = SM_STAGE0 + s3 * STAGE_BYTES;
            {
                const size_t ao = arowbase + (size_t)(a * W + bt) * Cin + ci0 + hh * 16;
                const float* pah = Ah + ao;
                const float* pal = Al + ao;
#pragma unroll
                for (int j = 0; j < 4; ++j) {
                    *(float4*)(smem + stgo + OFF_AH + swo[j]) = *(const float4*)(pah + 4 * j);
                    *(float4*)(smem + stgo + OFF_AL + swo[j]) = *(const float4*)(pal + 4 * j);
                }
            }
            {
                const int kh = 2 * a + 1 - py, kw = 2 * bt + 1 - px;
                const size_t bo = ((size_t)((kh * 4 + kw) * COUT + n0 + r)) * Cin + ci0 + hh * 16;
                const float* pbh = Wh + bo;
                const float* pbl = Wl + bo;
#pragma unroll
                for (int j = 0; j < 4; ++j) {
                    *(float4*)(smem + stgo + OFF_BH + swo[j]) = *(const float4*)(pbh + 4 * j);
                    *(float4*)(smem + stgo + OFF_BL + swo[j]) = *(const float4*)(pbl + 4 * j);
                }
            }
            FENCE_ASYNC_SHARED();
            MBARRIER_ARRIVE(sb + SM_FULL + s3 * 8);
        }
    } else {
        if (elect_one()) {
            for (int i = 0; i < NK; ++i) {
                const int s3 = i - 3 * (i / 3);
                mbar_wait(sb + SM_FULL + s3 * 8, (uint32_t)((i / 3) & 1));
                const uint32_t stg = sb + SM_STAGE0 + s3 * STAGE_BYTES;
                const uint64_t dAh = MAKE_DESC(stg + OFF_AH);
                const uint64_t dAl = MAKE_DESC(stg + OFF_AL);
                const uint64_t dBh = MAKE_DESC(stg + OFF_BH);
                const uint64_t dBl = MAKE_DESC(stg + OFF_BL);
#pragma unroll
                for (int ks = 0; ks < 4; ++ks) {
#pragma unroll
                    for (int pass = 0; pass < 3; ++pass) {
                        const uint64_t da = (pass == 2) ? dAl : dAh;
                        const uint64_t db = (pass == 1) ? dBl : dBh;
                        const uint32_t en = (i > 0 || ks > 0 || pass > 0) ? 1u : 0u;
                        mma_tf32_ss(tmem, da + ks * 2, db + ks * 2, en);
                    }
                }
                TCGEN05_COMMIT(sb + SM_DONE + s3 * 8);
            }
        }
    }

    {
        const int last = NK - 1;
        mbar_wait(sb + SM_DONE + (last % 3) * 8, (uint32_t)((last / 3) & 1));
    }
    TCGEN05_FENCE_AFTER();
    __syncthreads();

    if (wid < 8) {
        const float* scs = (const float*)(smem + SM_SC);
        const float* bis = (const float*)(smem + SM_BI);
        const int sub = wid & 3, half = wid >> 2;
        const int m = m0 + sub * 32 + lane;
        const bool valid = (m < M);
        int bb = 0, ty = 0, tx = 0;
        if (valid) { bb = m / HWp; const int rem = m - bb * HWp; ty = rem / Wp; tx = rem - ty * Wp; }
        const int H2 = 2 * H - 2, W2 = 2 * W - 2;
        const int oy = 2 * ty + py, ox = 2 * tx + px;
        const size_t obase = ((size_t)(bb * H2 + oy) * W2 + ox) * COUT + n0;

#pragma unroll
        for (int q = 0; q < 2; ++q) {
            const int c0 = half * 64 + q * 32;
            uint32_t regs[32];
            TCGEN05_LD_X32(regs, tmem + c0);
            TCGEN05_WAIT_LD();
            if (valid) {
#pragma unroll
                for (int k4 = 0; k4 < 8; ++k4) {
                    float v[4];
#pragma unroll
                    for (int e = 0; e < 4; ++e) {
                        const int c = n0 + c0 + k4 * 4 + e;
                        v[e] = fmaxf(fmaf(__uint_as_float(regs[k4 * 4 + e]), scs[c], bis[c]), 0.f);
                    }
                    if (split_out) {
                        float4 h4, l4;
                        h4.x = tf32_hi(v[0]); l4.x = v[0] - h4.x;
                        h4.y = tf32_hi(v[1]); l4.y = v[1] - h4.y;
                        h4.z = tf32_hi(v[2]); l4.z = v[2] - h4.z;
                        h4.w = tf32_hi(v[3]); l4.w = v[3] - h4.w;
                        *(float4*)(Yh + obase + c0 + k4 * 4) = h4;
                        *(float4*)(Yl + obase + c0 + k4 * 4) = l4;
                    } else {
                        *(float4*)(Yp + obase + c0 + k4 * 4) = make_float4(v[0], v[1], v[2], v[3]);
                    }
                }
            }
        }
    }

    __syncthreads();
    if (tid < 3) MBARRIER_INVAL(sb + SM_FULL + tid * 8);
    else if (tid >= 32 && tid < 35) MBARRIER_INVAL(sb + SM_DONE + (tid - 32) * 8);
    __syncthreads();
    if (wid == 0) TCGEN05_DEALLOC(tmem, 128);
#else
    const int tid = threadIdx.x;
    const int n0 = blockIdx.y * 128;
    const int phase = blockIdx.z;
    const int py = phase >> 1, px = phase & 1;
    const int m0 = blockIdx.x * 128;
    const int Hp = H - 1, Wp = W - 1;
    const int HWp = Hp * Wp;
    const int M = BDIM_B * HWp;
    const int H2 = 2 * H - 2, W2 = 2 * W - 2;

    for (int idx = tid; idx < 128 * 128; idx += NTHR) {
        const int ml = idx >> 7, n = n0 + (idx & 127);
        const int m = m0 + ml;
        if (m >= M) continue;
        const int bb = m / HWp; const int rem = m - bb * HWp;
        const int ty = rem / Wp; const int tx = rem - ty * Wp;
        float acc = 0.f;
        for (int tap = 0; tap < 4; ++tap) {
            const int a = tap >> 1, bt = tap & 1;
            const int kh = 2 * a + 1 - py, kw = 2 * bt + 1 - px;
            const float* ah = Ah + ((size_t)(bb * H + ty + a) * W + tx + bt) * Cin;
            const float* al = Al + ((size_t)(bb * H + ty + a) * W + tx + bt) * Cin;
            const float* wh = Wh + ((size_t)((kh * 4 + kw) * COUT + n)) * Cin;
            const float* wl = Wl + ((size_t)((kh * 4 + kw) * COUT + n)) * Cin;
            for (int c = 0; c < Cin; ++c)
                acc = fmaf(ah[c] + al[c], wh[c] + wl[c], acc);
        }
        const float s = gma[n] * rsqrtf(var[n] + BN_EPS);
        float v = fmaxf(fmaf(acc - mu[n], s, bta[n]), 0.f);
        const int oy = 2 * ty + py, ox = 2 * tx + px;
        const size_t o = ((size_t)(bb * H2 + oy) * W2 + ox) * COUT + n;
        if (split_out) { const float h = tf32_hi(v); Yh[o] = h; Yl[o] = v - h; }
        else Yp[o] = v;
    }
#endif
}

// ===========================================================================
// Kernel B (round-7): m-paired 256x256 tiles for L2/L3 (Cin=256).
// Ring slot = one (chunk, half) of 64KB: A = 2 tiles x 128 rows x 128B,
// B = 256 rows x 128B. MMA consumes slots 2i (hi) and 2i+1 (lo) per chunk.
// D: TMEM cols [tile*256 + nh*128 .. +127], 512 cols total.
// ===========================================================================
#define SLOT_BYTES 65536
#define OFF2_B 32768
#define SL_STAGE0 4096
#define SMEM2_TOTAL (SL_STAGE0 + 3 * SLOT_BYTES)   // 200704

__global__ __launch_bounds__(NTHR, 1)
void deconv_tc2(const float* __restrict__ Ah, const float* __restrict__ Al,
                const float* __restrict__ Wh, const float* __restrict__ Wl,
                const float* __restrict__ gma, const float* __restrict__ bta,
                const float* __restrict__ mu,  const float* __restrict__ var,
                float* __restrict__ Yh, float* __restrict__ Yl,
                float* __restrict__ Yp,
                int H, int W, int Cin, int split_out)
{
#if TCPATH
    extern __shared__ char smem[];
    const uint32_t sb = smem_u32(smem);
    const int tid = threadIdx.x;
    const int wid = tid >> 5, lane = tid & 31;

    const int phase = blockIdx.y;
    const int py = phase >> 1, px = phase & 1;
    const int m0 = blockIdx.x * 256;
    const int Hp = H - 1, Wp = W - 1;
    const int HWp = Hp * Wp;
    const int M = BDIM_B * HWp;
    const int NK = Cin >> 3;               // chunks of K=32
    const int NSLOT = 2 * NK;

    if (wid == 0) { TCGEN05_ALLOC(sb + SM_TMEMPTR, 512); TCGEN05_RELINQ(); }
    if (tid < 256) {
        const float s = gma[tid] * rsqrtf(var[tid] + BN_EPS);
        ((float*)(smem + SM_SC))[tid] = s;
        ((float*)(smem + SM_BI))[tid] = bta[tid] - mu[tid] * s;
    }
    if (tid < 3) MBARRIER_INIT(sb + SM_FULL + tid * 8, 256);
    else if (tid >= 32 && tid < 35) MBARRIER_INIT(sb + SM_DONE + (tid - 32) * 8, 1);
    __syncthreads();
    uint32_t tmem;
    asm volatile("ld.shared.b32 %0, [%1];" : "=r"(tmem) : "r"(sb + SM_TMEMPTR));

    if (wid < 8) {
        // ============ LOADER: 256 threads; 2 threads per row =============
        const int rr = tid >> 1, hh = tid & 1;
        size_t arow[2];
#pragma unroll
        for (int u = 0; u < 2; ++u) {
            int mrow = m0 + u * 128 + rr; if (mrow >= M) mrow = M - 1;
            const int bbA = mrow / HWp; const int remA = mrow - bbA * HWp;
            const int tyA = remA / Wp;  const int txA = remA - tyA * Wp;
            arow[u] = ((size_t)(bbA * H + tyA) * W + txA) * Cin;
        }
        const uint32_t off = (uint32_t)(rr * 128 + hh * 64);
        uint32_t swo[4];
#pragma unroll
        for (int j = 0; j < 4; ++j) swo[j] = SWZ(off + 16 * j);

        for (int sl = 0; sl < NSLOT; ++sl) {
            const int s3 = sl % 3;
            if (sl >= 3) mbar_wait(sb + SM_DONE + s3 * 8, (uint32_t)(((sl / 3) - 1) & 1));
            const int chunk = sl >> 1, half = sl & 1;
            const int kt = chunk * 32;
            const int tap = kt / Cin;
            const int ci0 = kt - tap * Cin;
            const int a = tap >> 1, bt = tap & 1;
            const int kh = 2 * a + 1 - py, kw = 2 * bt + 1 - px;
            const float* Aarr = half ? Al : Ah;
            const float* Warr = half ? Wl : Wh;
            const uint32_t stgo = SL_STAGE0 + s3 * SLOT_BYTES;
            // A: tiles u=0,1 at stgo + u*16384
#pragma unroll
            for (int u = 0; u < 2; ++u) {
                const float* pa = Aarr + arow[u] + (size_t)(a * W + bt) * Cin + ci0 + hh * 16;
#pragma unroll
                for (int j = 0; j < 4; ++j)
                    *(float4*)(smem + stgo + u * 16384 + swo[j]) = *(const float4*)(pa + 4 * j);
            }
            // B: rows rr + u*128 at OFF2_B + u*16384 (swizzle offset additive)
#pragma unroll
            for (int u = 0; u < 2; ++u) {
                const float* pb = Warr + ((size_t)((kh * 4 + kw) * COUT + rr + u * 128)) * Cin + ci0 + hh * 16;
#pragma unroll
                for (int j = 0; j < 4; ++j)
                    *(float4*)(smem + stgo + OFF2_B + u * 16384 + swo[j]) = *(const float4*)(pb + 4 * j);
            }
            FENCE_ASYNC_SHARED();
            MBARRIER_ARRIVE(sb + SM_FULL + s3 * 8);
        }
    } else {
        // ============ MMA ISSUER: warp 8 =================================
        if (elect_one()) {
            for (int i = 0; i < NK; ++i) {
                const int jh = 2 * i, jl = 2 * i + 1;
                const int sh = jh % 3, slx = jl % 3;
                mbar_wait(sb + SM_FULL + sh * 8, (uint32_t)((jh / 3) & 1));
                mbar_wait(sb + SM_FULL + slx * 8, (uint32_t)((jl / 3) & 1));
                const uint32_t stg_h = sb + SL_STAGE0 + sh * SLOT_BYTES;
                const uint32_t stg_l = sb + SL_STAGE0 + slx * SLOT_BYTES;
                const uint64_t dAh0 = MAKE_DESC(stg_h);
                const uint64_t dAh1 = MAKE_DESC(stg_h + 16384);
                const uint64_t dAl0 = MAKE_DESC(stg_l);
                const uint64_t dAl1 = MAKE_DESC(stg_l + 16384);
                const uint64_t dBh  = MAKE_DESC(stg_h + OFF2_B);
                const uint64_t dBl  = MAKE_DESC(stg_l + OFF2_B);
#pragma unroll
                for (int ks = 0; ks < 4; ++ks) {
#pragma unroll
                    for (int pass = 0; pass < 3; ++pass) {
                        const uint64_t da0 = (pass == 2) ? dAl0 : dAh0;
                        const uint64_t da1 = (pass == 2) ? dAl1 : dAh1;
                        const uint64_t db  = (pass == 1) ? dBl  : dBh;
                        const uint32_t en = (i > 0 || ks > 0 || pass > 0) ? 1u : 0u;
#pragma unroll
                        for (int nh = 0; nh < 2; ++nh) {
                            mma_tf32_ss(tmem + 0   + nh * 128, da0 + ks * 2, db + nh * 1024 + ks * 2, en);
                            mma_tf32_ss(tmem + 256 + nh * 128, da1 + ks * 2, db + nh * 1024 + ks * 2, en);
                        }
                    }
                }
                TCGEN05_COMMIT(sb + SM_DONE + sh * 8);
                TCGEN05_COMMIT(sb + SM_DONE + slx * 8);
            }
        }
    }

    // ---- drain: wait for the last slot's commit ----
    {
        const int jlast = NSLOT - 1;
        mbar_wait(sb + SM_DONE + (jlast % 3) * 8, (uint32_t)((jlast / 3) & 1));
    }
    TCGEN05_FENCE_AFTER();
    __syncthreads();

    // ---- epilogue: warps 0-3 -> tile0, warps 4-7 -> tile1; full N=256 ----
    if (wid < 8) {
        const float* scs = (const float*)(smem + SM_SC);
        const float* bis = (const float*)(smem + SM_BI);
        const int tile = wid >> 2, sub = wid & 3;
        const int m = m0 + tile * 128 + sub * 32 + lane;
        const bool valid = (m < M);
        int bb = 0, ty = 0, tx = 0;
        if (valid) { bb = m / HWp; const int rem = m - bb * HWp; ty = rem / Wp; tx = rem - ty * Wp; }
        const int H2 = 2 * H - 2, W2 = 2 * W - 2;
        const int oy = 2 * ty + py, ox = 2 * tx + px;
        const size_t obase = ((size_t)(bb * H2 + oy) * W2 + ox) * COUT;

#pragma unroll
        for (int q = 0; q < 8; ++q) {
            const int c0 = q * 32;
            uint32_t regs[32];
            TCGEN05_LD_X32(regs, tmem + tile * 256 + c0);
            TCGEN05_WAIT_LD();
            if (valid) {
#pragma unroll
                for (int k4 = 0; k4 < 8; ++k4) {
                    float v[4];
#pragma unroll
                    for (int e = 0; e < 4; ++e) {
                        const int c = c0 + k4 * 4 + e;
                        v[e] = fmaxf(fmaf(__uint_as_float(regs[k4 * 4 + e]), scs[c], bis[c]), 0.f);
                    }
                    if (split_out) {
                        float4 h4, l4;
                        h4.x = tf32_hi(v[0]); l4.x = v[0] - h4.x;
                        h4.y = tf32_hi(v[1]); l4.y = v[1] - h4.y;
                        h4.z = tf32_hi(v[2]); l4.z = v[2] - h4.z;
                        h4.w = tf32_hi(v[3]); l4.w = v[3] - h4.w;
                        *(float4*)(Yh + obase + c0 + k4 * 4) = h4;
                        *(float4*)(Yl + obase + c0 + k4 * 4) = l4;
                    } else {
                        *(float4*)(Yp + obase + c0 + k4 * 4) = make_float4(v[0], v[1], v[2], v[3]);
                    }
                }
            }
        }
    }

    __syncthreads();
    if (tid < 3) MBARRIER_INVAL(sb + SM_FULL + tid * 8);
    else if (tid >= 32 && tid < 35) MBARRIER_INVAL(sb + SM_DONE + (tid - 32) * 8);
    __syncthreads();
    if (wid == 0) TCGEN05_DEALLOC(tmem, 512);
#else
    // ------------------ fallback (non-accelerated pass) --------------------
    const int tid = threadIdx.x;
    const int phase = blockIdx.y;
    const int py = phase >> 1, px = phase & 1;
    const int m0 = blockIdx.x * 256;
    const int Hp = H - 1, Wp = W - 1;
    const int HWp = Hp * Wp;
    const int M = BDIM_B * HWp;
    const int H2 = 2 * H - 2, W2 = 2 * W - 2;

    for (int idx = tid; idx < 256 * 256; idx += NTHR) {
        const int ml = idx >> 8, n = idx & 255;
        const int m = m0 + ml;
        if (m >= M) continue;
        const int bb = m / HWp; const int rem = m - bb * HWp;
        const int ty = rem / Wp; const int tx = rem - ty * Wp;
        float acc = 0.f;
        for (int tap = 0; tap < 4; ++tap) {
            const int a = tap >> 1, bt = tap & 1;
            const int kh = 2 * a + 1 - py, kw = 2 * bt + 1 - px;
            const float* ah = Ah + ((size_t)(bb * H + ty + a) * W + tx + bt) * Cin;
            const float* al = Al + ((size_t)(bb * H + ty + a) * W + tx + bt) * Cin;
            const float* wh = Wh + ((size_t)((kh * 4 + kw) * COUT + n)) * Cin;
            const float* wl = Wl + ((size_t)((kh * 4 + kw) * COUT + n)) * Cin;
            for (int c = 0; c < Cin; ++c)
                acc = fmaf(ah[c] + al[c], wh[c] + wl[c], acc);
        }
        const float s = gma[n] * rsqrtf(var[n] + BN_EPS);
        float v = fmaxf(fmaf(acc - mu[n], s, bta[n]), 0.f);
        const int oy = 2 * ty + py, ox = 2 * tx + px;
        const size_t o = ((size_t)(bb * H2 + oy) * W2 + ox) * COUT + n;
        if (split_out) { const float h = tf32_hi(v); Yh[o] = h; Yl[o] = v - h; }
        else Yp[o] = v;
    }
#endif
}

// ---------------------------------------------------------------------------
// 1x1 conv 256->17; 4 pixels per thread, broadcast weight LDS.
// ---------------------------------------------------------------------------
__global__ __launch_bounds__(256)
void heatmap_kernel(const float* __restrict__ y3, const float* __restrict__ wf,
                    const float* __restrict__ bfin, float* __restrict__ hm)
{
    __shared__ float wfs[COUT * KPT];
    for (int i = threadIdx.x; i < COUT * KPT; i += blockDim.x) wfs[i] = wf[i];
    __syncthreads();

    const int t = blockIdx.x * 256 + threadIdx.x;
    if (t >= NPIX / 4) return;
    const int p0 = t * 4;
    const float* yp = y3 + (size_t)p0 * COUT;

    float acc[4][KPT];
#pragma unroll
    for (int p = 0; p < 4; ++p)
#pragma unroll
        for (int k = 0; k < KPT; ++k) acc[p][k] = 0.f;

    for (int c4 = 0; c4 < COUT / 4; ++c4) {
        float4 yv[4];
#pragma unroll
        for (int p = 0; p < 4; ++p) yv[p] = *(const float4*)(yp + p * COUT + c4 * 4);
        const float* wr = wfs + (c4 * 4) * KPT;
#pragma unroll
        for (int cc = 0; cc < 4; ++cc) {
            const float y0 = (cc == 0) ? yv[0].x : (cc == 1) ? yv[0].y : (cc == 2) ? yv[0].z : yv[0].w;
            const float y1 = (cc == 0) ? yv[1].x : (cc == 1) ? yv[1].y : (cc == 2) ? yv[1].z : yv[1].w;
            const float y2 = (cc == 0) ? yv[2].x : (cc == 1) ? yv[2].y : (cc == 2) ? yv[2].z : yv[2].w;
            const float y3v = (cc == 0) ? yv[3].x : (cc == 1) ? yv[3].y : (cc == 2) ? yv[3].z : yv[3].w;
#pragma unroll
            for (int k = 0; k < KPT; ++k) {
                const float wk = wr[cc * KPT + k];
                acc[0][k] = fmaf(y0, wk, acc[0][k]);
                acc[1][k] = fmaf(y1, wk, acc[1][k]);
                acc[2][k] = fmaf(y2, wk, acc[2][k]);
                acc[3][k] = fmaf(y3v, wk, acc[3][k]);
            }
        }
    }
#pragma unroll
    for (int p = 0; p < 4; ++p) {
        const int pix = p0 + p;
        const int bb = pix / HWD; const int pp = pix - bb * HWD;
#pragma unroll
        for (int k = 0; k < KPT; ++k)
            hm[(size_t)(bb * KPT + k) * HWD + pp] = acc[p][k] + bfin[k];
    }
}

// ---------------------------------------------------------------------------
// Per-(b,k) argmax + subpixel refinement.
// ---------------------------------------------------------------------------
__global__ void detect_kernel(const float* __restrict__ hm, float* __restrict__ out)
{
    const float* row = hm + (size_t)blockIdx.x * HWD;
    const int tid = threadIdx.x;

    float best = -3.402823466e+38f; int bidx = 0x7fffffff;
    for (int i = tid; i < HWD; i += 128) {
        const float v = row[i];
        if (v > best) { best = v; bidx = i; }
    }
    __shared__ float sv[128];
    __shared__ int   si[128];
    sv[tid] = best; si[tid] = bidx;
    __syncthreads();
    for (int s = 64; s > 0; s >>= 1) {
        if (tid < s) {
            const float v2 = sv[tid + s]; const int i2 = si[tid + s];
            if (v2 > sv[tid] || (v2 == sv[tid] && i2 < si[tid])) { sv[tid] = v2; si[tid] = i2; }
        }
        __syncthreads();
    }
    if (tid == 0) {
        const float score = sv[0];
        const int idx = si[0];
        const bool pos = score > 0.f;
        const int pxi = pos ? (idx % WD) : 0;
        const int pyi = pos ? (idx / WD) : 0;
        const bool inner = (pxi > 0) && (pxi < WD - 1) && (pyi > 0) && (pyi < HD - 1);
        float dx = 0.f, dy = 0.f;
        if (inner) {
            const int base = pyi * WD + pxi;
            const float d1 = row[base + 1]  - row[base - 1];
            const float d2 = row[base + WD] - row[base - WD];
            dx = (d1 > 0.f) ? 0.25f : ((d1 < 0.f) ? -0.25f : 0.f);
            dy = (d2 > 0.f) ? 0.25f : ((d2 < 0.f) ? -0.25f : 0.f);
        }
        float* o = out + (size_t)blockIdx.x * 3;
        o[0] = (float)pxi + dx;
        o[1] = (float)pyi + dy;
        o[2] = score;
    }
}

// ---------------------------------------------------------------------------
extern "C" void kernel_launch(void* const* d_in, const int* in_sizes, int n_in,
                              void* d_out, int out_size)
{
    const float* x  = (const float*)d_in[0];
    const float* w1 = (const float*)d_in[1];
    const float* g1 = (const float*)d_in[2];
    const float* b1 = (const float*)d_in[3];
    const float* m1 = (const float*)d_in[4];
    const float* v1 = (const float*)d_in[5];
    const float* w2 = (const float*)d_in[6];
    const float* g2 = (const float*)d_in[7];
    const float* b2 = (const float*)d_in[8];
    const float* m2 = (const float*)d_in[9];
    const float* v2 = (const float*)d_in[10];
    const float* w3 = (const float*)d_in[11];
    const float* g3 = (const float*)d_in[12];
    const float* b3 = (const float*)d_in[13];
    const float* m3 = (const float*)d_in[14];
    const float* v3 = (const float*)d_in[15];
    const float* wf = (const float*)d_in[16];
    const float* bf = (const float*)d_in[17];
    float* out = (float*)d_out;

    float *xh, *xl, *w1h, *w1l, *w2h, *w2l, *w3h, *w3l;
    float *y1h, *y1l, *y2h, *y2l, *y3, *hm;
    cudaGetSymbolAddress((void**)&xh,  g_xh);
    cudaGetSymbolAddress((void**)&xl,  g_xl);
    cudaGetSymbolAddress((void**)&w1h, g_w1h);
    cudaGetSymbolAddress((void**)&w1l, g_w1l);
    cudaGetSymbolAddress((void**)&w2h, g_w2h);
    cudaGetSymbolAddress((void**)&w2l, g_w2l);
    cudaGetSymbolAddress((void**)&w3h, g_w3h);
    cudaGetSymbolAddress((void**)&w3l, g_w3l);
    cudaGetSymbolAddress((void**)&y1h, g_y1h);
    cudaGetSymbolAddress((void**)&y1l, g_y1l);
    cudaGetSymbolAddress((void**)&y2h, g_y2h);
    cudaGetSymbolAddress((void**)&y2l, g_y2l);
    cudaGetSymbolAddress((void**)&y3,  g_y3);
    cudaGetSymbolAddress((void**)&hm,  g_hm);

    static bool attr_done = false;
    if (!attr_done) {
        cudaFuncSetAttribute(deconv_tc,  cudaFuncAttributeMaxDynamicSharedMemorySize, SMEM_TOTAL);
        cudaFuncSetAttribute(deconv_tc2, cudaFuncAttributeMaxDynamicSharedMemorySize, SMEM2_TOTAL);
        attr_done = true;
    }

    // preprocess: split x; transpose+split weights
    split_kernel<<<4096, 256>>>(x, xh, xl, BDIM_B * 8 * 6 * 2048);
    wtrans_kernel<<<dim3(2048 / 32, COUT / 32, 16), dim3(32, 8)>>>(w1, w1h, w1l, 2048);
    wtrans_kernel<<<dim3(256 / 32,  COUT / 32, 16), dim3(32, 8)>>>(w2, w2h, w2l, 256);
    wtrans_kernel<<<dim3(256 / 32,  COUT / 32, 16), dim3(32, 8)>>>(w3, w3h, w3l, 256);

    // L1: [64,8,6,2048] -> [64,14,10,256] split.  M_phase = 2240 (18 tiles, 2 nblk)
    deconv_tc<<<dim3(18, 2, 4), NTHR, SMEM_TOTAL>>>(xh, xl, w1h, w1l, g1, b1, m1, v1,
                                                    y1h, y1l, nullptr, 8, 6, 2048, 1);
    // L2: -> [64,26,18,256] split.  M_phase = 7488 -> 30 m-pair tiles
    deconv_tc2<<<dim3(30, 4), NTHR, SMEM2_TOTAL>>>(y1h, y1l, w2h, w2l, g2, b2, m2, v2,
                                                   y2h, y2l, nullptr, 14, 10, 256, 1);
    // L3: -> [64,50,34,256] plain.  M_phase = 27200 -> 107 m-pair tiles
    deconv_tc2<<<dim3(107, 4), NTHR, SMEM2_TOTAL>>>(y2h, y2l, w3h, w3l, g3, b3, m3, v3,
                                                    nullptr, nullptr, y3, 26, 18, 256, 0);
    // heatmap + detect
    heatmap_kernel<<<(NPIX / 4 + 255) / 256, 256>>>(y3, wf, bf, hm);
    detect_kernel<<<BDIM_B * KPT, 128>>>(hm, out);
}

// round 8
// speedup vs baseline: 3.6141x; 1.1820x over previous
#include <cuda_runtime.h>
#include <cstdint>

// ---------------------------------------------------------------------------
// SimplePose via tcgen05 tf32 3-pass (fp32-equivalent) GEMMs.
//   3x (conv_transpose k4 s2 pads(1,1) + BN + ReLU) -> 1x1 conv -> argmax det
// Phase decomposition (py,px): kh = 2a+1-py, iy = ty+a  -> dense GEMM
//   M = B*(H-1)*(W-1), K = 4*Cin, N = 256 per phase.
// fp32 emulation: v = hi + lo, hi = cvt.rna.tf32(v);
//   C = Ah*Bh + Ah*Bl + Al*Bh  (3 tcgen05 passes into one fp32 TMEM tile)
//
// Round 8: L1 (K=8192) becomes split-K-by-tap: grid (9 m-pair tiles, 4
// phases, 4 taps) = 144 CTAs, each a dense 256x256xK2048 GEMM writing raw
// fp32 partials; a reduce kernel sums taps + BN + ReLU + hi/lo split.
// L2/L3 keep the round-7 m-paired 256x256 kernel.
// ---------------------------------------------------------------------------

#if defined(__CUDA_ARCH_FEAT_SM103_ALL) || defined(__CUDA_ARCH_FEAT_SM100_ALL)
#define TCPATH 1
#else
#define TCPATH 0
#endif

#define BDIM_B   64
#define COUT     256
#define KPT      17
#define BN_EPS   1e-5f
#define HD 50
#define WD 34
#define HWD (HD * WD)          // 1700
#define NPIX (BDIM_B * HWD)    // 108800
#define NTHR 288               // 8 loader warps + 1 MMA warp

// L1 split-K partial layout: [tap(4)][phase(4)][m(2304)][n(256)]
#define L1_MPAD 2304
#define L1_M 2240              // 64 * 7 * 5

// ---------------- scratch (static; cudaMalloc forbidden) -------------------
__device__ float g_xh[BDIM_B * 8 * 6 * 2048];
__device__ float g_xl[BDIM_B * 8 * 6 * 2048];
__device__ float g_w1h[16 * COUT * 2048];
__device__ float g_w1l[16 * COUT * 2048];
__device__ float g_w2h[16 * COUT * 256];
__device__ float g_w2l[16 * COUT * 256];
__device__ float g_w3h[16 * COUT * 256];
__device__ float g_w3l[16 * COUT * 256];
__device__ float g_p1 [4 * 4 * L1_MPAD * COUT];        // 37.7 MB partials
__device__ float g_y1h[BDIM_B * 14 * 10 * COUT];
__device__ float g_y1l[BDIM_B * 14 * 10 * COUT];
__device__ float g_y2h[BDIM_B * 26 * 18 * COUT];
__device__ float g_y2l[BDIM_B * 26 * 18 * COUT];
__device__ float g_y3 [BDIM_B * HD * WD * COUT];
__device__ float g_hm [BDIM_B * KPT * HWD];

// ---------------------------- helpers (arch-neutral) -----------------------
__device__ __forceinline__ float tf32_hi(float v) {
    float r;
    asm("cvt.rna.tf32.f32 %0, %1;" : "=f"(r) : "f"(v));
    return r;
}

#if TCPATH
__device__ __forceinline__ uint32_t smem_u32(const void* p) {
    uint32_t a;
    asm("{ .reg .u64 t; cvta.to.shared.u64 t, %1; cvt.u32.u64 %0, t; }" : "=r"(a) : "l"(p));
    return a;
}
__device__ __forceinline__ uint32_t elect_one() {
    uint32_t pr;
    asm volatile("{\n\t.reg .pred p;\n\telect.sync _|p, 0xFFFFFFFF;\n\tselp.b32 %0, 1, 0, p;\n\t}" : "=r"(pr));
    return pr;
}

#define MBARRIER_INIT(addr, cnt) \
    asm volatile("mbarrier.init.shared.b64 [%0], %1;" :: "r"(addr), "r"(cnt) : "memory")
#define MBARRIER_INVAL(addr) \
    asm volatile("mbarrier.inval.shared.b64 [%0];" :: "r"(addr) : "memory")
#define MBARRIER_ARRIVE(addr) \
    asm volatile("mbarrier.arrive.release.cta.shared::cta.b64 _, [%0];" :: "r"(addr) : "memory")
__device__ __forceinline__ void mbar_wait(uint32_t mbar, uint32_t parity) {
    asm volatile(
        "{\n\t.reg .pred P;\n\t"
        "WL%=:\n\t"
        "mbarrier.try_wait.parity.acquire.cta.shared::cta.b64 P, [%0], %1, 0x989680;\n\t"
        "@P bra.uni WD%=;\n\t"
        "bra.uni WL%=;\n\t"
        "WD%=:\n\t}"
        :: "r"(mbar), "r"(parity) : "memory");
}
#define TCGEN05_ALLOC(sm, n) \
    asm volatile("tcgen05.alloc.cta_group::1.sync.aligned.shared::cta.b32 [%0], %1;" :: "r"(sm), "r"(n) : "memory")
#define TCGEN05_DEALLOC(tm, n) \
    asm volatile("tcgen05.dealloc.cta_group::1.sync.aligned.b32 %0, %1;" :: "r"(tm), "r"(n))
#define TCGEN05_RELINQ() \
    asm volatile("tcgen05.relinquish_alloc_permit.cta_group::1.sync.aligned;")
#define TCGEN05_COMMIT(mb) \
    asm volatile("tcgen05.commit.cta_group::1.mbarrier::arrive::one.shared::cluster.b64 [%0];" :: "r"(mb) : "memory")
#define TCGEN05_FENCE_AFTER() \
    asm volatile("tcgen05.fence::after_thread_sync;" ::: "memory")
#define TCGEN05_WAIT_LD() \
    asm volatile("tcgen05.wait::ld.sync.aligned;" ::: "memory")
#define FENCE_ASYNC_SHARED() \
    asm volatile("fence.proxy.async.shared::cta;" ::: "memory")

#define TCGEN05_LD_X32(r, tm) \
    asm volatile( \
        "tcgen05.ld.sync.aligned.32x32b.x32.b32 " \
        "{%0, %1, %2, %3, %4, %5, %6, %7, " \
        " %8, %9, %10, %11, %12, %13, %14, %15, " \
        " %16, %17, %18, %19, %20, %21, %22, %23, " \
        " %24, %25, %26, %27, %28, %29, %30, %31}, [%32];" \
        : "=r"((r)[0]),  "=r"((r)[1]),  "=r"((r)[2]),  "=r"((r)[3]), \
          "=r"((r)[4]),  "=r"((r)[5]),  "=r"((r)[6]),  "=r"((r)[7]), \
          "=r"((r)[8]),  "=r"((r)[9]),  "=r"((r)[10]), "=r"((r)[11]), \
          "=r"((r)[12]), "=r"((r)[13]), "=r"((r)[14]), "=r"((r)[15]), \
          "=r"((r)[16]), "=r"((r)[17]), "=r"((r)[18]), "=r"((r)[19]), \
          "=r"((r)[20]), "=r"((r)[21]), "=r"((r)[22]), "=r"((r)[23]), \
          "=r"((r)[24]), "=r"((r)[25]), "=r"((r)[26]), "=r"((r)[27]), \
          "=r"((r)[28]), "=r"((r)[29]), "=r"((r)[30]), "=r"((r)[31]) \
        : "r"(tm))

// SMEM descriptor (K-major SW128: LBO=1, SBO=64, version=1, layout=2)
#define SMEM_DESC_BASE \
    ((uint64_t(2) << 61) | (uint64_t(1) << 46) | (uint64_t(64) << 32) | (uint64_t(1) << 16))
#define MAKE_DESC(addr) (SMEM_DESC_BASE | ((uint64_t)((addr) >> 4) & 0x3FFF))

// tf32 SS MMA, cta_group::1, M=128, N=128, K=8 per issue
#define IDESC_TF32 ((1u << 4) | (2u << 7) | (2u << 10) | (16u << 17) | (8u << 24))

__device__ __forceinline__ void mma_tf32_ss(uint32_t d, uint64_t da, uint64_t db,
                                            uint32_t en) {
    asm volatile(
        "{\n\t.reg .pred p;\n\t"
        "setp.ne.u32 p, %4, 0;\n\t"
        "tcgen05.mma.cta_group::1.kind::tf32 [%0], %1, %2, %3, {%5, %5, %5, %5}, p;\n\t"
        "}"
        :: "r"(d), "l"(da), "l"(db), "r"(IDESC_TF32), "r"(en), "r"(0u)
        : "memory");
}
#endif  // TCPATH

#define SWZ(o) ((o) ^ (((o) >> 3) & 0x70))

// SMEM layout shared by GEMM kernels
#define SLOT_BYTES 65536
#define OFF2_B 32768
#define SM_TMEMPTR 0
#define SM_FULL 8
#define SM_DONE 32
#define SM_SC 64
#define SM_BI (64 + 1024)
#define SL_STAGE0 4096
#define SMEM2_TOTAL (SL_STAGE0 + 3 * SLOT_BYTES)   // 200704

// ---------------------------------------------------------------------------
// Preprocess: elementwise hi/lo split
// ---------------------------------------------------------------------------
__global__ void split_kernel(const float* __restrict__ in, float* __restrict__ hi,
                             float* __restrict__ lo, int n)
{
    for (int i = blockIdx.x * blockDim.x + threadIdx.x; i < n; i += gridDim.x * blockDim.x) {
        const float v = in[i];
        const float h = tf32_hi(v);
        hi[i] = h; lo[i] = v - h;
    }
}

// Weight transpose + split: w[t, ci, co] -> wt[t, co, ci] (hi/lo)
__global__ void wtrans_kernel(const float* __restrict__ w, float* __restrict__ th,
                              float* __restrict__ tl, int Cin)
{
    __shared__ float tile[32][33];
    const int t = blockIdx.z;
    const int ci0 = blockIdx.x * 32, co0 = blockIdx.y * 32;
    const int tx = threadIdx.x, ty = threadIdx.y;   // block (32, 8)
#pragma unroll
    for (int i = 0; i < 4; ++i)
        tile[ty + 8 * i][tx] = w[((size_t)(t * Cin + ci0 + ty + 8 * i)) * COUT + co0 + tx];
    __syncthreads();
#pragma unroll
    for (int i = 0; i < 4; ++i) {
        const float v = tile[tx][ty + 8 * i];
        const float h = tf32_hi(v);
        const size_t o = ((size_t)(t * COUT + co0 + ty + 8 * i)) * Cin + ci0 + tx;
        th[o] = h; tl[o] = v - h;
    }
}

// ===========================================================================
// Kernel L1S: split-K-by-tap m-paired 256x256 GEMM for L1 (Cin=2048).
// grid (9, 4 phases, 4 taps); each CTA: K = 2048 (one tap), 128 slots.
// Epilogue: raw fp32 partial store to g_p1[tap][phase][m][n].
// ===========================================================================
__global__ __launch_bounds__(NTHR, 1)
void deconv_tc1s(const float* __restrict__ Ah, const float* __restrict__ Al,
                 const float* __restrict__ Wh, const float* __restrict__ Wl,
                 float* __restrict__ part)
{
    const int H = 8, W = 6, Cin = 2048;
    const int Hp = 7, Wp = 5, HWp = 35;
    const int M = L1_M;
#if TCPATH
    extern __shared__ char smem[];
    const uint32_t sb = smem_u32(smem);
    const int tid = threadIdx.x;
    const int wid = tid >> 5, lane = tid & 31;

    const int phase = blockIdx.y;
    const int py = phase >> 1, px = phase & 1;
    const int tap = blockIdx.z;
    const int a = tap >> 1, bt = tap & 1;
    const int kh = 2 * a + 1 - py, kw = 2 * bt + 1 - px;
    const int m0 = blockIdx.x * 256;
    const int NK = Cin >> 5;               // 64 chunks of K=32
    const int NSLOT = 2 * NK;              // 128 slots

    if (wid == 0) { TCGEN05_ALLOC(sb + SM_TMEMPTR, 512); TCGEN05_RELINQ(); }
    if (tid < 3) MBARRIER_INIT(sb + SM_FULL + tid * 8, 256);
    else if (tid >= 32 && tid < 35) MBARRIER_INIT(sb + SM_DONE + (tid - 32) * 8, 1);
    __syncthreads();
    uint32_t tmem;
    asm volatile("ld.shared.b32 %0, [%1];" : "=r"(tmem) : "r"(sb + SM_TMEMPTR));

    if (wid < 8) {
        // ============ LOADER: 256 threads; 2 threads per row =============
        const int rr = tid >> 1, hh = tid & 1;
        size_t arow[2];
#pragma unroll
        for (int u = 0; u < 2; ++u) {
            int mrow = m0 + u * 128 + rr; if (mrow >= M) mrow = M - 1;
            const int bbA = mrow / HWp; const int remA = mrow - bbA * HWp;
            const int tyA = remA / Wp;  const int txA = remA - tyA * Wp;
            arow[u] = ((size_t)(bbA * H + tyA + a) * W + txA + bt) * Cin;
        }
        const size_t brow0 = ((size_t)((kh * 4 + kw) * COUT + rr)) * Cin;
        const size_t brow1 = ((size_t)((kh * 4 + kw) * COUT + rr + 128)) * Cin;
        const uint32_t off = (uint32_t)(rr * 128 + hh * 64);
        uint32_t swo[4];
#pragma unroll
        for (int j = 0; j < 4; ++j) swo[j] = SWZ(off + 16 * j);

        for (int sl = 0; sl < NSLOT; ++sl) {
            const int s3 = sl % 3;
            if (sl >= 3) mbar_wait(sb + SM_DONE + s3 * 8, (uint32_t)(((sl / 3) - 1) & 1));
            const int chunk = sl >> 1, half = sl & 1;
            const int ci0 = chunk * 32 + hh * 16;
            const float* Aarr = half ? Al : Ah;
            const float* Warr = half ? Wl : Wh;
            const uint32_t stgo = SL_STAGE0 + s3 * SLOT_BYTES;
#pragma unroll
            for (int u = 0; u < 2; ++u) {
                const float* pa = Aarr + arow[u] + ci0;
#pragma unroll
                for (int j = 0; j < 4; ++j)
                    *(float4*)(smem + stgo + u * 16384 + swo[j]) = *(const float4*)(pa + 4 * j);
            }
            {
                const float* pb0 = Warr + brow0 + ci0;
                const float* pb1 = Warr + brow1 + ci0;
#pragma unroll
                for (int j = 0; j < 4; ++j) {
                    *(float4*)(smem + stgo + OFF2_B + swo[j])         = *(const float4*)(pb0 + 4 * j);
                    *(float4*)(smem + stgo + OFF2_B + 16384 + swo[j]) = *(const float4*)(pb1 + 4 * j);
                }
            }
            FENCE_ASYNC_SHARED();
            MBARRIER_ARRIVE(sb + SM_FULL + s3 * 8);
        }
    } else {
        // ============ MMA ISSUER: warp 8 =================================
        if (elect_one()) {
            for (int i = 0; i < NK; ++i) {
                const int jh = 2 * i, jl = 2 * i + 1;
                const int sh = jh % 3, slx = jl % 3;
                mbar_wait(sb + SM_FULL + sh * 8, (uint32_t)((jh / 3) & 1));
                mbar_wait(sb + SM_FULL + slx * 8, (uint32_t)((jl / 3) & 1));
                const uint32_t stg_h = sb + SL_STAGE0 + sh * SLOT_BYTES;
                const uint32_t stg_l = sb + SL_STAGE0 + slx * SLOT_BYTES;
                const uint64_t dAh0 = MAKE_DESC(stg_h);
                const uint64_t dAh1 = MAKE_DESC(stg_h + 16384);
                const uint64_t dAl0 = MAKE_DESC(stg_l);
                const uint64_t dAl1 = MAKE_DESC(stg_l + 16384);
                const uint64_t dBh  = MAKE_DESC(stg_h + OFF2_B);
                const uint64_t dBl  = MAKE_DESC(stg_l + OFF2_B);
#pragma unroll
                for (int ks = 0; ks < 4; ++ks) {
#pragma unroll
                    for (int pass = 0; pass < 3; ++pass) {
                        const uint64_t da0 = (pass == 2) ? dAl0 : dAh0;
                        const uint64_t da1 = (pass == 2) ? dAl1 : dAh1;
                        const uint64_t db  = (pass == 1) ? dBl  : dBh;
                        const uint32_t en = (i > 0 || ks > 0 || pass > 0) ? 1u : 0u;
#pragma unroll
                        for (int nh = 0; nh < 2; ++nh) {
                            mma_tf32_ss(tmem + 0   + nh * 128, da0 + ks * 2, db + nh * 1024 + ks * 2, en);
                            mma_tf32_ss(tmem + 256 + nh * 128, da1 + ks * 2, db + nh * 1024 + ks * 2, en);
                        }
                    }
                }
                TCGEN05_COMMIT(sb + SM_DONE + sh * 8);
                TCGEN05_COMMIT(sb + SM_DONE + slx * 8);
            }
        }
    }

    {
        const int jlast = NSLOT - 1;
        mbar_wait(sb + SM_DONE + (jlast % 3) * 8, (uint32_t)((jlast / 3) & 1));
    }
    TCGEN05_FENCE_AFTER();
    __syncthreads();

    // ---- epilogue: raw fp32 partial store (no BN) ----
    if (wid < 8) {
        const int tile = wid >> 2, sub = wid & 3;
        const int m = m0 + tile * 128 + sub * 32 + lane;       // < 2304 always
        float* pb = part + (((size_t)(tap * 4 + phase) * L1_MPAD + m) * COUT);
#pragma unroll
        for (int q = 0; q < 8; ++q) {
            const int c0 = q * 32;
            uint32_t regs[32];
            TCGEN05_LD_X32(regs, tmem + tile * 256 + c0);
            TCGEN05_WAIT_LD();
#pragma unroll
            for (int k4 = 0; k4 < 8; ++k4) {
                float4 v;
                v.x = __uint_as_float(regs[k4 * 4 + 0]);
                v.y = __uint_as_float(regs[k4 * 4 + 1]);
                v.z = __uint_as_float(regs[k4 * 4 + 2]);
                v.w = __uint_as_float(regs[k4 * 4 + 3]);
                *(float4*)(pb + c0 + k4 * 4) = v;
            }
        }
    }

    __syncthreads();
    if (tid < 3) MBARRIER_INVAL(sb + SM_FULL + tid * 8);
    else if (tid >= 32 && tid < 35) MBARRIER_INVAL(sb + SM_DONE + (tid - 32) * 8);
    __syncthreads();
    if (wid == 0) TCGEN05_DEALLOC(tmem, 512);
#else
    // fallback: per-tap partial GEMM
    const int tid = threadIdx.x;
    const int phase = blockIdx.y;
    const int py = phase >> 1, px = phase & 1;
    const int tap = blockIdx.z;
    const int a = tap >> 1, bt = tap & 1;
    const int kh = 2 * a + 1 - py, kw = 2 * bt + 1 - px;
    const int m0 = blockIdx.x * 256;
    for (int idx = tid; idx < 256 * 256; idx += NTHR) {
        const int ml = idx >> 8, n = idx & 255;
        const int m = m0 + ml;
        if (m >= M) continue;
        const int bb = m / HWp; const int rem = m - bb * HWp;
        const int ty = rem / Wp; const int tx = rem - ty * Wp;
        const float* ah = Ah + ((size_t)(bb * H + ty + a) * W + tx + bt) * Cin;
        const float* al = Al + ((size_t)(bb * H + ty + a) * W + tx + bt) * Cin;
        const float* wh = Wh + ((size_t)((kh * 4 + kw) * COUT + n)) * Cin;
        const float* wl = Wl + ((size_t)((kh * 4 + kw) * COUT + n)) * Cin;
        float acc = 0.f;
        for (int c = 0; c < Cin; ++c)
            acc = fmaf(ah[c] + al[c], wh[c] + wl[c], acc);
        part[(((size_t)(tap * 4 + phase) * L1_MPAD + m) * COUT) + n] = acc;
    }
#endif
}

// Reduce L1 partials: sum 4 taps, BN + ReLU, hi/lo split, scatter NHWC.
__global__ __launch_bounds__(256)
void reduce_l1(const float* __restrict__ part,
               const float* __restrict__ gma, const float* __restrict__ bta,
               const float* __restrict__ mu,  const float* __restrict__ var,
               float* __restrict__ Yh, float* __restrict__ Yl)
{
    const int t = blockIdx.x * 256 + threadIdx.x;      // over 4*2240*64 float4
    if (t >= 4 * L1_M * 64) return;
    const int n4 = t & 63;
    const int rest = t >> 6;
    const int m = rest % L1_M;
    const int phase = rest / L1_M;
    const int py = phase >> 1, px = phase & 1;

    float4 acc = make_float4(0.f, 0.f, 0.f, 0.f);
#pragma unroll
    for (int tap = 0; tap < 4; ++tap) {
        const float4 v = *(const float4*)(part + ((size_t)(tap * 4 + phase) * L1_MPAD + m) * COUT + n4 * 4);
        acc.x += v.x; acc.y += v.y; acc.z += v.z; acc.w += v.w;
    }
    const int c = n4 * 4;
    float vv[4] = {acc.x, acc.y, acc.z, acc.w};
    float4 h4, l4;
    float* hp = &h4.x; float* lp = &l4.x;
#pragma unroll
    for (int e = 0; e < 4; ++e) {
        const float s = gma[c + e] * rsqrtf(var[c + e] + BN_EPS);
        const float bi = bta[c + e] - mu[c + e] * s;
        const float v = fmaxf(fmaf(vv[e], s, bi), 0.f);
        const float h = tf32_hi(v);
        hp[e] = h; lp[e] = v - h;
    }
    // NHWC scatter: HWp=35 (7x5), H2=14, W2=10
    const int bb = m / 35; const int rem = m - bb * 35;
    const int ty = rem / 5; const int tx = rem - ty * 5;
    const int oy = 2 * ty + py, ox = 2 * tx + px;
    const size_t o = ((size_t)(bb * 14 + oy) * 10 + ox) * COUT + c;
    *(float4*)(Yh + o) = h4;
    *(float4*)(Yl + o) = l4;
}

// ===========================================================================
// Kernel B (round-7): m-paired 256x256 tiles for L2/L3 (Cin=256).
// ===========================================================================
__global__ __launch_bounds__(NTHR, 1)
void deconv_tc2(const float* __restrict__ Ah, const float* __restrict__ Al,
                const float* __restrict__ Wh, const float* __restrict__ Wl,
                const float* __restrict__ gma, const float* __restrict__ bta,
                const float* __restrict__ mu,  const float* __restrict__ var,
                float* __restrict__ Yh, float* __restrict__ Yl,
                float* __restrict__ Yp,
                int H, int W, int Cin, int split_out)
{
#if TCPATH
    extern __shared__ char smem[];
    const uint32_t sb = smem_u32(smem);
    const int tid = threadIdx.x;
    const int wid = tid >> 5, lane = tid & 31;

    const int phase = blockIdx.y;
    const int py = phase >> 1, px = phase & 1;
    const int m0 = blockIdx.x * 256;
    const int Hp = H - 1, Wp = W - 1;
    const int HWp = Hp * Wp;
    const int M = BDIM_B * HWp;
    const int NK = Cin >> 3;
    const int NSLOT = 2 * NK;

    if (wid == 0) { TCGEN05_ALLOC(sb + SM_TMEMPTR, 512); TCGEN05_RELINQ(); }
    if (tid < 256) {
        const float s = gma[tid] * rsqrtf(var[tid] + BN_EPS);
        ((float*)(smem + SM_SC))[tid] = s;
        ((float*)(smem + SM_BI))[tid] = bta[tid] - mu[tid] * s;
    }
    if (tid < 3) MBARRIER_INIT(sb + SM_FULL + tid * 8, 256);
    else if (tid >= 32 && tid < 35) MBARRIER_INIT(sb + SM_DONE + (tid - 32) * 8, 1);
    __syncthreads();
    uint32_t tmem;
    asm volatile("ld.shared.b32 %0, [%1];" : "=r"(tmem) : "r"(sb + SM_TMEMPTR));

    if (wid < 8) {
        const int rr = tid >> 1, hh = tid & 1;
        size_t arow[2];
#pragma unroll
        for (int u = 0; u < 2; ++u) {
            int mrow = m0 + u * 128 + rr; if (mrow >= M) mrow = M - 1;
            const int bbA = mrow / HWp; const int remA = mrow - bbA * HWp;
            const int tyA = remA / Wp;  const int txA = remA - tyA * Wp;
            arow[u] = ((size_t)(bbA * H + tyA) * W + txA) * Cin;
        }
        const uint32_t off = (uint32_t)(rr * 128 + hh * 64);
        uint32_t swo[4];
#pragma unroll
        for (int j = 0; j < 4; ++j) swo[j] = SWZ(off + 16 * j);

        for (int sl = 0; sl < NSLOT; ++sl) {
            const int s3 = sl % 3;
            if (sl >= 3) mbar_wait(sb + SM_DONE + s3 * 8, (uint32_t)(((sl / 3) - 1) & 1));
            const int chunk = sl >> 1, half = sl & 1;
            const int kt = chunk * 32;
            const int tap = kt / Cin;
            const int ci0 = kt - tap * Cin;
            const int a = tap >> 1, bt = tap & 1;
            const int kh = 2 * a + 1 - py, kw = 2 * bt + 1 - px;
            const float* Aarr = half ? Al : Ah;
            const float* Warr = half ? Wl : Wh;
            const uint32_t stgo = SL_STAGE0 + s3 * SLOT_BYTES;
#pragma unroll
            for (int u = 0; u < 2; ++u) {
                const float* pa = Aarr + arow[u] + (size_t)(a * W + bt) * Cin + ci0 + hh * 16;
#pragma unroll
                for (int j = 0; j < 4; ++j)
                    *(float4*)(smem + stgo + u * 16384 + swo[j]) = *(const float4*)(pa + 4 * j);
            }
#pragma unroll
            for (int u = 0; u < 2; ++u) {
                const float* pb = Warr + ((size_t)((kh * 4 + kw) * COUT + rr + u * 128)) * Cin + ci0 + hh * 16;
#pragma unroll
                for (int j = 0; j < 4; ++j)
                    *(float4*)(smem + stgo + OFF2_B + u * 16384 + swo[j]) = *(const float4*)(pb + 4 * j);
            }
            FENCE_ASYNC_SHARED();
            MBARRIER_ARRIVE(sb + SM_FULL + s3 * 8);
        }
    } else {
        if (elect_one()) {
            for (int i = 0; i < NK; ++i) {
                const int jh = 2 * i, jl = 2 * i + 1;
                const int sh = jh % 3, slx = jl % 3;
                mbar_wait(sb + SM_FULL + sh * 8, (uint32_t)((jh / 3) & 1));
                mbar_wait(sb + SM_FULL + slx * 8, (uint32_t)((jl / 3) & 1));
                const uint32_t stg_h = sb + SL_STAGE0 + sh * SLOT_BYTES;
                const uint32_t stg_l = sb + SL_STAGE0 + slx * SLOT_BYTES;
                const uint64_t dAh0 = MAKE_DESC(stg_h);
                const uint64_t dAh1 = MAKE_DESC(stg_h + 16384);
                const uint64_t dAl0 = MAKE_DESC(stg_l);
                const uint64_t dAl1 = MAKE_DESC(stg_l + 16384);
                const uint64_t dBh  = MAKE_DESC(stg_h + OFF2_B);
                const uint64_t dBl  = MAKE_DESC(stg_l + OFF2_B);
#pragma unroll
                for (int ks = 0; ks < 4; ++ks) {
#pragma unroll
                    for (int pass = 0; pass < 3; ++pass) {
                        const uint64_t da0 = (pass == 2) ? dAl0 : dAh0;
                        const uint64_t da1 = (pass == 2) ? dAl1 : dAh1;
                        const uint64_t db  = (pass == 1) ? dBl  : dBh;
                        const uint32_t en = (i > 0 || ks > 0 || pass > 0) ? 1u : 0u;
#pragma unroll
                        for (int nh = 0; nh < 2; ++nh) {
                            mma_tf32_ss(tmem + 0   + nh * 128, da0 + ks * 2, db + nh * 1024 + ks * 2, en);
                            mma_tf32_ss(tmem + 256 + nh * 128, da1 + ks * 2, db + nh * 1024 + ks * 2, en);
                        }
                    }
                }
                TCGEN05_COMMIT(sb + SM_DONE + sh * 8);
                TCGEN05_COMMIT(sb + SM_DONE + slx * 8);
            }
        }
    }

    {
        const int jlast = NSLOT - 1;
        mbar_wait(sb + SM_DONE + (jlast % 3) * 8, (uint32_t)((jlast / 3) & 1));
    }
    TCGEN05_FENCE_AFTER();
    __syncthreads();

    if (wid < 8) {
        const float* scs = (const float*)(smem + SM_SC);
        const float* bis = (const float*)(smem + SM_BI);
        const int tile = wid >> 2, sub = wid & 3;
        const int m = m0 + tile * 128 + sub * 32 + lane;
        const bool valid = (m < M);
        int bb = 0, ty = 0, tx = 0;
        if (valid) { bb = m / HWp; const int rem = m - bb * HWp; ty = rem / Wp; tx = rem - ty * Wp; }
        const int H2 = 2 * H - 2, W2 = 2 * W - 2;
        const int oy = 2 * ty + py, ox = 2 * tx + px;
        const size_t obase = ((size_t)(bb * H2 + oy) * W2 + ox) * COUT;

#pragma unroll
        for (int q = 0; q < 8; ++q) {
            const int c0 = q * 32;
            uint32_t regs[32];
            TCGEN05_LD_X32(regs, tmem + tile * 256 + c0);
            TCGEN05_WAIT_LD();
            if (valid) {
#pragma unroll
                for (int k4 = 0; k4 < 8; ++k4) {
                    float v[4];
#pragma unroll
                    for (int e = 0; e < 4; ++e) {
                        const int c = c0 + k4 * 4 + e;
                        v[e] = fmaxf(fmaf(__uint_as_float(regs[k4 * 4 + e]), scs[c], bis[c]), 0.f);
                    }
                    if (split_out) {
                        float4 h4, l4;
                        h4.x = tf32_hi(v[0]); l4.x = v[0] - h4.x;
                        h4.y = tf32_hi(v[1]); l4.y = v[1] - h4.y;
                        h4.z = tf32_hi(v[2]); l4.z = v[2] - h4.z;
                        h4.w = tf32_hi(v[3]); l4.w = v[3] - h4.w;
                        *(float4*)(Yh + obase + c0 + k4 * 4) = h4;
                        *(float4*)(Yl + obase + c0 + k4 * 4) = l4;
                    } else {
                        *(float4*)(Yp + obase + c0 + k4 * 4) = make_float4(v[0], v[1], v[2], v[3]);
                    }
                }
            }
        }
    }

    __syncthreads();
    if (tid < 3) MBARRIER_INVAL(sb + SM_FULL + tid * 8);
    else if (tid >= 32 && tid < 35) MBARRIER_INVAL(sb + SM_DONE + (tid - 32) * 8);
    __syncthreads();
    if (wid == 0) TCGEN05_DEALLOC(tmem, 512);
#else
    const int tid = threadIdx.x;
    const int phase = blockIdx.y;
    const int py = phase >> 1, px = phase & 1;
    const int m0 = blockIdx.x * 256;
    const int Hp = H - 1, Wp = W - 1;
    const int HWp = Hp * Wp;
    const int M = BDIM_B * HWp;
    const int H2 = 2 * H - 2, W2 = 2 * W - 2;

    for (int idx = tid; idx < 256 * 256; idx += NTHR) {
        const int ml = idx >> 8, n = idx & 255;
        const int m = m0 + ml;
        if (m >= M) continue;
        const int bb = m / HWp; const int rem = m - bb * HWp;
        const int ty = rem / Wp; const int tx = rem - ty * Wp;
        float acc = 0.f;
        for (int tap = 0; tap < 4; ++tap) {
            const int a = tap >> 1, bt = tap & 1;
            const int kh = 2 * a + 1 - py, kw = 2 * bt + 1 - px;
            const float* ah = Ah + ((size_t)(bb * H + ty + a) * W + tx + bt) * Cin;
            const float* al = Al + ((size_t)(bb * H + ty + a) * W + tx + bt) * Cin;
            const float* wh = Wh + ((size_t)((kh * 4 + kw) * COUT + n)) * Cin;
            const float* wl = Wl + ((size_t)((kh * 4 + kw) * COUT + n)) * Cin;
            for (int c = 0; c < Cin; ++c)
                acc = fmaf(ah[c] + al[c], wh[c] + wl[c], acc);
        }
        const float s = gma[n] * rsqrtf(var[n] + BN_EPS);
        float v = fmaxf(fmaf(acc - mu[n], s, bta[n]), 0.f);
        const int oy = 2 * ty + py, ox = 2 * tx + px;
        const size_t o = ((size_t)(bb * H2 + oy) * W2 + ox) * COUT + n;
        if (split_out) { const float h = tf32_hi(v); Yh[o] = h; Yl[o] = v - h; }
        else Yp[o] = v;
    }
#endif
}

// ---------------------------------------------------------------------------
// 1x1 conv 256->17; 4 pixels per thread, broadcast weight LDS.
// ---------------------------------------------------------------------------
__global__ __launch_bounds__(256)
void heatmap_kernel(const float* __restrict__ y3, const float* __restrict__ wf,
                    const float* __restrict__ bfin, float* __restrict__ hm)
{
    __shared__ float wfs[COUT * KPT];
    for (int i = threadIdx.x; i < COUT * KPT; i += blockDim.x) wfs[i] = wf[i];
    __syncthreads();

    const int t = blockIdx.x * 256 + threadIdx.x;
    if (t >= NPIX / 4) return;
    const int p0 = t * 4;
    const float* yp = y3 + (size_t)p0 * COUT;

    float acc[4][KPT];
#pragma unroll
    for (int p = 0; p < 4; ++p)
#pragma unroll
        for (int k = 0; k < KPT; ++k) acc[p][k] = 0.f;

    for (int c4 = 0; c4 < COUT / 4; ++c4) {
        float4 yv[4];
#pragma unroll
        for (int p = 0; p < 4; ++p) yv[p] = *(const float4*)(yp + p * COUT + c4 * 4);
        const float* wr = wfs + (c4 * 4) * KPT;
#pragma unroll
        for (int cc = 0; cc < 4; ++cc) {
            const float y0 = (cc == 0) ? yv[0].x : (cc == 1) ? yv[0].y : (cc == 2) ? yv[0].z : yv[0].w;
            const float y1 = (cc == 0) ? yv[1].x : (cc == 1) ? yv[1].y : (cc == 2) ? yv[1].z : yv[1].w;
            const float y2 = (cc == 0) ? yv[2].x : (cc == 1) ? yv[2].y : (cc == 2) ? yv[2].z : yv[2].w;
            const float y3v = (cc == 0) ? yv[3].x : (cc == 1) ? yv[3].y : (cc == 2) ? yv[3].z : yv[3].w;
#pragma unroll
            for (int k = 0; k < KPT; ++k) {
                const float wk = wr[cc * KPT + k];
                acc[0][k] = fmaf(y0, wk, acc[0][k]);
                acc[1][k] = fmaf(y1, wk, acc[1][k]);
                acc[2][k] = fmaf(y2, wk, acc[2][k]);
                acc[3][k] = fmaf(y3v, wk, acc[3][k]);
            }
        }
    }
#pragma unroll
    for (int p = 0; p < 4; ++p) {
        const int pix = p0 + p;
        const int bb = pix / HWD; const int pp = pix - bb * HWD;
#pragma unroll
        for (int k = 0; k < KPT; ++k)
            hm[(size_t)(bb * KPT + k) * HWD + pp] = acc[p][k] + bfin[k];
    }
}

// ---------------------------------------------------------------------------
// Per-(b,k) argmax + subpixel refinement.
// ---------------------------------------------------------------------------
__global__ void detect_kernel(const float* __restrict__ hm, float* __restrict__ out)
{
    const float* row = hm + (size_t)blockIdx.x * HWD;
    const int tid = threadIdx.x;

    float best = -3.402823466e+38f; int bidx = 0x7fffffff;
    for (int i = tid; i < HWD; i += 128) {
        const float v = row[i];
        if (v > best) { best = v; bidx = i; }
    }
    __shared__ float sv[128];
    __shared__ int   si[128];
    sv[tid] = best; si[tid] = bidx;
    __syncthreads();
    for (int s = 64; s > 0; s >>= 1) {
        if (tid < s) {
            const float v2 = sv[tid + s]; const int i2 = si[tid + s];
            if (v2 > sv[tid] || (v2 == sv[tid] && i2 < si[tid])) { sv[tid] = v2; si[tid] = i2; }
        }
        __syncthreads();
    }
    if (tid == 0) {
        const float score = sv[0];
        const int idx = si[0];
        const bool pos = score > 0.f;
        const int pxi = pos ? (idx % WD) : 0;
        const int pyi = pos ? (idx / WD) : 0;
        const bool inner = (pxi > 0) && (pxi < WD - 1) && (pyi > 0) && (pyi < HD - 1);
        float dx = 0.f, dy = 0.f;
        if (inner) {
            const int base = pyi * WD + pxi;
            const float d1 = row[base + 1]  - row[base - 1];
            const float d2 = row[base + WD] - row[base - WD];
            dx = (d1 > 0.f) ? 0.25f : ((d1 < 0.f) ? -0.25f : 0.f);
            dy = (d2 > 0.f) ? 0.25f : ((d2 < 0.f) ? -0.25f : 0.f);
        }
        float* o = out + (size_t)blockIdx.x * 3;
        o[0] = (float)pxi + dx;
        o[1] = (float)pyi + dy;
        o[2] = score;
    }
}

// ---------------------------------------------------------------------------
extern "C" void kernel_launch(void* const* d_in, const int* in_sizes, int n_in,
                              void* d_out, int out_size)
{
    const float* x  = (const float*)d_in[0];
    const float* w1 = (const float*)d_in[1];
    const float* g1 = (const float*)d_in[2];
    const float* b1 = (const float*)d_in[3];
    const float* m1 = (const float*)d_in[4];
    const float* v1 = (const float*)d_in[5];
    const float* w2 = (const float*)d_in[6];
    const float* g2 = (const float*)d_in[7];
    const float* b2 = (const float*)d_in[8];
    const float* m2 = (const float*)d_in[9];
    const float* v2 = (const float*)d_in[10];
    const float* w3 = (const float*)d_in[11];
    const float* g3 = (const float*)d_in[12];
    const float* b3 = (const float*)d_in[13];
    const float* m3 = (const float*)d_in[14];
    const float* v3 = (const float*)d_in[15];
    const float* wf = (const float*)d_in[16];
    const float* bf = (const float*)d_in[17];
    float* out = (float*)d_out;

    float *xh, *xl, *w1h, *w1l, *w2h, *w2l, *w3h, *w3l;
    float *p1, *y1h, *y1l, *y2h, *y2l, *y3, *hm;
    cudaGetSymbolAddress((void**)&xh,  g_xh);
    cudaGetSymbolAddress((void**)&xl,  g_xl);
    cudaGetSymbolAddress((void**)&w1h, g_w1h);
    cudaGetSymbolAddress((void**)&w1l, g_w1l);
    cudaGetSymbolAddress((void**)&w2h, g_w2h);
    cudaGetSymbolAddress((void**)&w2l, g_w2l);
    cudaGetSymbolAddress((void**)&w3h, g_w3h);
    cudaGetSymbolAddress((void**)&w3l, g_w3l);
    cudaGetSymbolAddress((void**)&p1,  g_p1);
    cudaGetSymbolAddress((void**)&y1h, g_y1h);
    cudaGetSymbolAddress((void**)&y1l, g_y1l);
    cudaGetSymbolAddress((void**)&y2h, g_y2h);
    cudaGetSymbolAddress((void**)&y2l, g_y2l);
    cudaGetSymbolAddress((void**)&y3,  g_y3);
    cudaGetSymbolAddress((void**)&hm,  g_hm);

    static bool attr_done = false;
    if (!attr_done) {
        cudaFuncSetAttribute(deconv_tc1s, cudaFuncAttributeMaxDynamicSharedMemorySize, SMEM2_TOTAL);
        cudaFuncSetAttribute(deconv_tc2,  cudaFuncAttributeMaxDynamicSharedMemorySize, SMEM2_TOTAL);
        attr_done = true;
    }

    // preprocess: split x; transpose+split weights
    split_kernel<<<4096, 256>>>(x, xh, xl, BDIM_B * 8 * 6 * 2048);
    wtrans_kernel<<<dim3(2048 / 32, COUT / 32, 16), dim3(32, 8)>>>(w1, w1h, w1l, 2048);
    wtrans_kernel<<<dim3(256 / 32,  COUT / 32, 16), dim3(32, 8)>>>(w2, w2h, w2l, 256);
    wtrans_kernel<<<dim3(256 / 32,  COUT / 32, 16), dim3(32, 8)>>>(w3, w3h, w3l, 256);

    // L1 split-K-by-tap: grid (9 m-pair tiles, 4 phases, 4 taps) = 144 CTAs
    deconv_tc1s<<<dim3(9, 4, 4), NTHR, SMEM2_TOTAL>>>(xh, xl, w1h, w1l, p1);
    // reduce taps + BN + ReLU + split -> y1 (4*2240*64 float4)
    reduce_l1<<<(4 * L1_M * 64 + 255) / 256, 256>>>(p1, g1, b1, m1, v1, y1h, y1l);

    // L2: -> [64,26,18,256] split.  M_phase = 7488 -> 30 m-pair tiles
    deconv_tc2<<<dim3(30, 4), NTHR, SMEM2_TOTAL>>>(y1h, y1l, w2h, w2l, g2, b2, m2, v2,
                                                   y2h, y2l, nullptr, 14, 10, 256, 1);
    // L3: -> [64,50,34,256] plain.  M_phase = 27200 -> 107 m-pair tiles
    deconv_tc2<<<dim3(107, 4), NTHR, SMEM2_TOTAL>>>(y2h, y2l, w3h, w3l, g3, b3, m3, v3,
                                                    nullptr, nullptr, y3, 26, 18, 256, 0);
    // heatmap + detect
    heatmap_kernel<<<(NPIX / 4 + 255) / 256, 256>>>(y3, wf, bf, hm);
    detect_kernel<<<BDIM_B * KPT, 128>>>(hm, out);
}

// round 9
// speedup vs baseline: 3.7291x; 1.0318x over previous
#include <cuda_runtime.h>
#include <cstdint>

// ---------------------------------------------------------------------------
// SimplePose via tcgen05 tf32 3-pass (fp32-equivalent) GEMMs.
//   3x (conv_transpose k4 s2 pads(1,1) + BN + ReLU) -> 1x1 conv -> argmax det
// Phase decomposition (py,px): kh = 2a+1-py, iy = ty+a  -> dense GEMM
//   M = B*(H-1)*(W-1), K = 4*Cin, N = 256 per phase.
// fp32 emulation: v = hi + lo, hi = cvt.rna.tf32(v);
//   C = Ah*Bh + Ah*Bl + Al*Bh  (3 tcgen05 passes into one fp32 TMEM tile)
//
// Round 9: fuse the 1x1 conv (256->17) + bias into the L3 epilogue. The
// epilogue thread already holds its pixel's full 256 channels across the
// q-loop, so project to 17 heatmap channels in registers and write the
// transposed heatmap directly. y3 (111 MB) is never materialized.
// ---------------------------------------------------------------------------

#if defined(__CUDA_ARCH_FEAT_SM103_ALL) || defined(__CUDA_ARCH_FEAT_SM100_ALL)
#define TCPATH 1
#else
#define TCPATH 0
#endif

#define BDIM_B   64
#define COUT     256
#define KPT      17
#define BN_EPS   1e-5f
#define HD 50
#define WD 34
#define HWD (HD * WD)          // 1700
#define NTHR 288               // 8 loader warps + 1 MMA warp

// L1 split-K partial layout: [tap(4)][phase(4)][m(2304)][n(256)]
#define L1_MPAD 2304
#define L1_M 2240              // 64 * 7 * 5

// ---------------- scratch (static; cudaMalloc forbidden) -------------------
__device__ float g_xh[BDIM_B * 8 * 6 * 2048];
__device__ float g_xl[BDIM_B * 8 * 6 * 2048];
__device__ float g_w1h[16 * COUT * 2048];
__device__ float g_w1l[16 * COUT * 2048];
__device__ float g_w2h[16 * COUT * 256];
__device__ float g_w2l[16 * COUT * 256];
__device__ float g_w3h[16 * COUT * 256];
__device__ float g_w3l[16 * COUT * 256];
__device__ float g_p1 [4 * 4 * L1_MPAD * COUT];        // 37.7 MB partials
__device__ float g_y1h[BDIM_B * 14 * 10 * COUT];
__device__ float g_y1l[BDIM_B * 14 * 10 * COUT];
__device__ float g_y2h[BDIM_B * 26 * 18 * COUT];
__device__ float g_y2l[BDIM_B * 26 * 18 * COUT];
__device__ float g_hm [BDIM_B * KPT * HWD];

// ---------------------------- helpers (arch-neutral) -----------------------
__device__ __forceinline__ float tf32_hi(float v) {
    float r;
    asm("cvt.rna.tf32.f32 %0, %1;" : "=f"(r) : "f"(v));
    return r;
}

#if TCPATH
__device__ __forceinline__ uint32_t smem_u32(const void* p) {
    uint32_t a;
    asm("{ .reg .u64 t; cvta.to.shared.u64 t, %1; cvt.u32.u64 %0, t; }" : "=r"(a) : "l"(p));
    return a;
}
__device__ __forceinline__ uint32_t elect_one() {
    uint32_t pr;
    asm volatile("{\n\t.reg .pred p;\n\telect.sync _|p, 0xFFFFFFFF;\n\tselp.b32 %0, 1, 0, p;\n\t}" : "=r"(pr));
    return pr;
}

#define MBARRIER_INIT(addr, cnt) \
    asm volatile("mbarrier.init.shared.b64 [%0], %1;" :: "r"(addr), "r"(cnt) : "memory")
#define MBARRIER_INVAL(addr) \
    asm volatile("mbarrier.inval.shared.b64 [%0];" :: "r"(addr) : "memory")
#define MBARRIER_ARRIVE(addr) \
    asm volatile("mbarrier.arrive.release.cta.shared::cta.b64 _, [%0];" :: "r"(addr) : "memory")
__device__ __forceinline__ void mbar_wait(uint32_t mbar, uint32_t parity) {
    asm volatile(
        "{\n\t.reg .pred P;\n\t"
        "WL%=:\n\t"
        "mbarrier.try_wait.parity.acquire.cta.shared::cta.b64 P, [%0], %1, 0x989680;\n\t"
        "@P bra.uni WD%=;\n\t"
        "bra.uni WL%=;\n\t"
        "WD%=:\n\t}"
        :: "r"(mbar), "r"(parity) : "memory");
}
#define TCGEN05_ALLOC(sm, n) \
    asm volatile("tcgen05.alloc.cta_group::1.sync.aligned.shared::cta.b32 [%0], %1;" :: "r"(sm), "r"(n) : "memory")
#define TCGEN05_DEALLOC(tm, n) \
    asm volatile("tcgen05.dealloc.cta_group::1.sync.aligned.b32 %0, %1;" :: "r"(tm), "r"(n))
#define TCGEN05_RELINQ() \
    asm volatile("tcgen05.relinquish_alloc_permit.cta_group::1.sync.aligned;")
#define TCGEN05_COMMIT(mb) \
    asm volatile("tcgen05.commit.cta_group::1.mbarrier::arrive::one.shared::cluster.b64 [%0];" :: "r"(mb) : "memory")
#define TCGEN05_FENCE_AFTER() \
    asm volatile("tcgen05.fence::after_thread_sync;" ::: "memory")
#define TCGEN05_WAIT_LD() \
    asm volatile("tcgen05.wait::ld.sync.aligned;" ::: "memory")
#define FENCE_ASYNC_SHARED() \
    asm volatile("fence.proxy.async.shared::cta;" ::: "memory")

#define TCGEN05_LD_X32(r, tm) \
    asm volatile( \
        "tcgen05.ld.sync.aligned.32x32b.x32.b32 " \
        "{%0, %1, %2, %3, %4, %5, %6, %7, " \
        " %8, %9, %10, %11, %12, %13, %14, %15, " \
        " %16, %17, %18, %19, %20, %21, %22, %23, " \
        " %24, %25, %26, %27, %28, %29, %30, %31}, [%32];" \
        : "=r"((r)[0]),  "=r"((r)[1]),  "=r"((r)[2]),  "=r"((r)[3]), \
          "=r"((r)[4]),  "=r"((r)[5]),  "=r"((r)[6]),  "=r"((r)[7]), \
          "=r"((r)[8]),  "=r"((r)[9]),  "=r"((r)[10]), "=r"((r)[11]), \
          "=r"((r)[12]), "=r"((r)[13]), "=r"((r)[14]), "=r"((r)[15]), \
          "=r"((r)[16]), "=r"((r)[17]), "=r"((r)[18]), "=r"((r)[19]), \
          "=r"((r)[20]), "=r"((r)[21]), "=r"((r)[22]), "=r"((r)[23]), \
          "=r"((r)[24]), "=r"((r)[25]), "=r"((r)[26]), "=r"((r)[27]), \
          "=r"((r)[28]), "=r"((r)[29]), "=r"((r)[30]), "=r"((r)[31]) \
        : "r"(tm))

// SMEM descriptor (K-major SW128: LBO=1, SBO=64, version=1, layout=2)
#define SMEM_DESC_BASE \
    ((uint64_t(2) << 61) | (uint64_t(1) << 46) | (uint64_t(64) << 32) | (uint64_t(1) << 16))
#define MAKE_DESC(addr) (SMEM_DESC_BASE | ((uint64_t)((addr) >> 4) & 0x3FFF))

// tf32 SS MMA, cta_group::1, M=128, N=128, K=8 per issue
#define IDESC_TF32 ((1u << 4) | (2u << 7) | (2u << 10) | (16u << 17) | (8u << 24))

__device__ __forceinline__ void mma_tf32_ss(uint32_t d, uint64_t da, uint64_t db,
                                            uint32_t en) {
    asm volatile(
        "{\n\t.reg .pred p;\n\t"
        "setp.ne.u32 p, %4, 0;\n\t"
        "tcgen05.mma.cta_group::1.kind::tf32 [%0], %1, %2, %3, {%5, %5, %5, %5}, p;\n\t"
        "}"
        :: "r"(d), "l"(da), "l"(db), "r"(IDESC_TF32), "r"(en), "r"(0u)
        : "memory");
}
#endif  // TCPATH

#define SWZ(o) ((o) ^ (((o) >> 3) & 0x70))

// SMEM layout shared by GEMM kernels
#define SLOT_BYTES 65536
#define OFF2_B 32768
#define SM_TMEMPTR 0
#define SM_FULL 8
#define SM_DONE 32
#define SM_SC 64
#define SM_BI (64 + 1024)
#define SL_STAGE0 4096
#define SM_WF (SL_STAGE0 + 3 * SLOT_BYTES)          // 200704: wf[256*17]
#define SMEM2_TOTAL (SM_WF + COUT * KPT * 4)         // 218112

// ---------------------------------------------------------------------------
// Preprocess: elementwise hi/lo split
// ---------------------------------------------------------------------------
__global__ void split_kernel(const float* __restrict__ in, float* __restrict__ hi,
                             float* __restrict__ lo, int n)
{
    for (int i = blockIdx.x * blockDim.x + threadIdx.x; i < n; i += gridDim.x * blockDim.x) {
        const float v = in[i];
        const float h = tf32_hi(v);
        hi[i] = h; lo[i] = v - h;
    }
}

// Weight transpose + split: w[t, ci, co] -> wt[t, co, ci] (hi/lo)
__global__ void wtrans_kernel(const float* __restrict__ w, float* __restrict__ th,
                              float* __restrict__ tl, int Cin)
{
    __shared__ float tile[32][33];
    const int t = blockIdx.z;
    const int ci0 = blockIdx.x * 32, co0 = blockIdx.y * 32;
    const int tx = threadIdx.x, ty = threadIdx.y;   // block (32, 8)
#pragma unroll
    for (int i = 0; i < 4; ++i)
        tile[ty + 8 * i][tx] = w[((size_t)(t * Cin + ci0 + ty + 8 * i)) * COUT + co0 + tx];
    __syncthreads();
#pragma unroll
    for (int i = 0; i < 4; ++i) {
        const float v = tile[tx][ty + 8 * i];
        const float h = tf32_hi(v);
        const size_t o = ((size_t)(t * COUT + co0 + ty + 8 * i)) * Cin + ci0 + tx;
        th[o] = h; tl[o] = v - h;
    }
}

// ===========================================================================
// Kernel L1S: split-K-by-tap m-paired 256x256 GEMM for L1 (Cin=2048).
// ===========================================================================
__global__ __launch_bounds__(NTHR, 1)
void deconv_tc1s(const float* __restrict__ Ah, const float* __restrict__ Al,
                 const float* __restrict__ Wh, const float* __restrict__ Wl,
                 float* __restrict__ part)
{
    const int H = 8, W = 6, Cin = 2048;
    const int Hp = 7, Wp = 5, HWp = 35;
    const int M = L1_M;
#if TCPATH
    extern __shared__ char smem[];
    const uint32_t sb = smem_u32(smem);
    const int tid = threadIdx.x;
    const int wid = tid >> 5, lane = tid & 31;

    const int phase = blockIdx.y;
    const int py = phase >> 1, px = phase & 1;
    const int tap = blockIdx.z;
    const int a = tap >> 1, bt = tap & 1;
    const int kh = 2 * a + 1 - py, kw = 2 * bt + 1 - px;
    const int m0 = blockIdx.x * 256;
    const int NK = Cin >> 5;               // 64 chunks of K=32
    const int NSLOT = 2 * NK;              // 128 slots

    if (wid == 0) { TCGEN05_ALLOC(sb + SM_TMEMPTR, 512); TCGEN05_RELINQ(); }
    if (tid < 3) MBARRIER_INIT(sb + SM_FULL + tid * 8, 256);
    else if (tid >= 32 && tid < 35) MBARRIER_INIT(sb + SM_DONE + (tid - 32) * 8, 1);
    __syncthreads();
    uint32_t tmem;
    asm volatile("ld.shared.b32 %0, [%1];" : "=r"(tmem) : "r"(sb + SM_TMEMPTR));

    if (wid < 8) {
        const int rr = tid >> 1, hh = tid & 1;
        size_t arow[2];
#pragma unroll
        for (int u = 0; u < 2; ++u) {
            int mrow = m0 + u * 128 + rr; if (mrow >= M) mrow = M - 1;
            const int bbA = mrow / HWp; const int remA = mrow - bbA * HWp;
            const int tyA = remA / Wp;  const int txA = remA - tyA * Wp;
            arow[u] = ((size_t)(bbA * H + tyA + a) * W + txA + bt) * Cin;
        }
        const size_t brow0 = ((size_t)((kh * 4 + kw) * COUT + rr)) * Cin;
        const size_t brow1 = ((size_t)((kh * 4 + kw) * COUT + rr + 128)) * Cin;
        const uint32_t off = (uint32_t)(rr * 128 + hh * 64);
        uint32_t swo[4];
#pragma unroll
        for (int j = 0; j < 4; ++j) swo[j] = SWZ(off + 16 * j);

        for (int sl = 0; sl < NSLOT; ++sl) {
            const int s3 = sl % 3;
            if (sl >= 3) mbar_wait(sb + SM_DONE + s3 * 8, (uint32_t)(((sl / 3) - 1) & 1));
            const int chunk = sl >> 1, half = sl & 1;
            const int ci0 = chunk * 32 + hh * 16;
            const float* Aarr = half ? Al : Ah;
            const float* Warr = half ? Wl : Wh;
            const uint32_t stgo = SL_STAGE0 + s3 * SLOT_BYTES;
#pragma unroll
            for (int u = 0; u < 2; ++u) {
                const float* pa = Aarr + arow[u] + ci0;
#pragma unroll
                for (int j = 0; j < 4; ++j)
                    *(float4*)(smem + stgo + u * 16384 + swo[j]) = *(const float4*)(pa + 4 * j);
            }
            {
                const float* pb0 = Warr + brow0 + ci0;
                const float* pb1 = Warr + brow1 + ci0;
#pragma unroll
                for (int j = 0; j < 4; ++j) {
                    *(float4*)(smem + stgo + OFF2_B + swo[j])         = *(const float4*)(pb0 + 4 * j);
                    *(float4*)(smem + stgo + OFF2_B + 16384 + swo[j]) = *(const float4*)(pb1 + 4 * j);
                }
            }
            FENCE_ASYNC_SHARED();
            MBARRIER_ARRIVE(sb + SM_FULL + s3 * 8);
        }
    } else {
        if (elect_one()) {
            for (int i = 0; i < NK; ++i) {
                const int jh = 2 * i, jl = 2 * i + 1;
                const int sh = jh % 3, slx = jl % 3;
                mbar_wait(sb + SM_FULL + sh * 8, (uint32_t)((jh / 3) & 1));
                mbar_wait(sb + SM_FULL + slx * 8, (uint32_t)((jl / 3) & 1));
                const uint32_t stg_h = sb + SL_STAGE0 + sh * SLOT_BYTES;
                const uint32_t stg_l = sb + SL_STAGE0 + slx * SLOT_BYTES;
                const uint64_t dAh0 = MAKE_DESC(stg_h);
                const uint64_t dAh1 = MAKE_DESC(stg_h + 16384);
                const uint64_t dAl0 = MAKE_DESC(stg_l);
                const uint64_t dAl1 = MAKE_DESC(stg_l + 16384);
                const uint64_t dBh  = MAKE_DESC(stg_h + OFF2_B);
                const uint64_t dBl  = MAKE_DESC(stg_l + OFF2_B);
#pragma unroll
                for (int ks = 0; ks < 4; ++ks) {
#pragma unroll
                    for (int pass = 0; pass < 3; ++pass) {
                        const uint64_t da0 = (pass == 2) ? dAl0 : dAh0;
                        const uint64_t da1 = (pass == 2) ? dAl1 : dAh1;
                        const uint64_t db  = (pass == 1) ? dBl  : dBh;
                        const uint32_t en = (i > 0 || ks > 0 || pass > 0) ? 1u : 0u;
#pragma unroll
                        for (int nh = 0; nh < 2; ++nh) {
                            mma_tf32_ss(tmem + 0   + nh * 128, da0 + ks * 2, db + nh * 1024 + ks * 2, en);
                            mma_tf32_ss(tmem + 256 + nh * 128, da1 + ks * 2, db + nh * 1024 + ks * 2, en);
                        }
                    }
                }
                TCGEN05_COMMIT(sb + SM_DONE + sh * 8);
                TCGEN05_COMMIT(sb + SM_DONE + slx * 8);
            }
        }
    }

    {
        const int jlast = NSLOT - 1;
        mbar_wait(sb + SM_DONE + (jlast % 3) * 8, (uint32_t)((jlast / 3) & 1));
    }
    TCGEN05_FENCE_AFTER();
    __syncthreads();

    if (wid < 8) {
        const int tile = wid >> 2, sub = wid & 3;
        const int m = m0 + tile * 128 + sub * 32 + lane;
        float* pb = part + (((size_t)(tap * 4 + phase) * L1_MPAD + m) * COUT);
#pragma unroll
        for (int q = 0; q < 8; ++q) {
            const int c0 = q * 32;
            uint32_t regs[32];
            TCGEN05_LD_X32(regs, tmem + tile * 256 + c0);
            TCGEN05_WAIT_LD();
#pragma unroll
            for (int k4 = 0; k4 < 8; ++k4) {
                float4 v;
                v.x = __uint_as_float(regs[k4 * 4 + 0]);
                v.y = __uint_as_float(regs[k4 * 4 + 1]);
                v.z = __uint_as_float(regs[k4 * 4 + 2]);
                v.w = __uint_as_float(regs[k4 * 4 + 3]);
                *(float4*)(pb + c0 + k4 * 4) = v;
            }
        }
    }

    __syncthreads();
    if (tid < 3) MBARRIER_INVAL(sb + SM_FULL + tid * 8);
    else if (tid >= 32 && tid < 35) MBARRIER_INVAL(sb + SM_DONE + (tid - 32) * 8);
    __syncthreads();
    if (wid == 0) TCGEN05_DEALLOC(tmem, 512);
#else
    const int tid = threadIdx.x;
    const int phase = blockIdx.y;
    const int py = phase >> 1, px = phase & 1;
    const int tap = blockIdx.z;
    const int a = tap >> 1, bt = tap & 1;
    const int kh = 2 * a + 1 - py, kw = 2 * bt + 1 - px;
    const int m0 = blockIdx.x * 256;
    for (int idx = tid; idx < 256 * 256; idx += NTHR) {
        const int ml = idx >> 8, n = idx & 255;
        const int m = m0 + ml;
        if (m >= M) continue;
        const int bb = m / HWp; const int rem = m - bb * HWp;
        const int ty = rem / Wp; const int tx = rem - ty * Wp;
        const float* ah = Ah + ((size_t)(bb * H + ty + a) * W + tx + bt) * Cin;
        const float* al = Al + ((size_t)(bb * H + ty + a) * W + tx + bt) * Cin;
        const float* wh = Wh + ((size_t)((kh * 4 + kw) * COUT + n)) * Cin;
        const float* wl = Wl + ((size_t)((kh * 4 + kw) * COUT + n)) * Cin;
        float acc = 0.f;
        for (int c = 0; c < Cin; ++c)
            acc = fmaf(ah[c] + al[c], wh[c] + wl[c], acc);
        part[(((size_t)(tap * 4 + phase) * L1_MPAD + m) * COUT) + n] = acc;
    }
#endif
}

// Reduce L1 partials: sum 4 taps, BN + ReLU, hi/lo split, scatter NHWC.
__global__ __launch_bounds__(256)
void reduce_l1(const float* __restrict__ part,
               const float* __restrict__ gma, const float* __restrict__ bta,
               const float* __restrict__ mu,  const float* __restrict__ var,
               float* __restrict__ Yh, float* __restrict__ Yl)
{
    const int t = blockIdx.x * 256 + threadIdx.x;
    if (t >= 4 * L1_M * 64) return;
    const int n4 = t & 63;
    const int rest = t >> 6;
    const int m = rest % L1_M;
    const int phase = rest / L1_M;
    const int py = phase >> 1, px = phase & 1;

    float4 acc = make_float4(0.f, 0.f, 0.f, 0.f);
#pragma unroll
    for (int tap = 0; tap < 4; ++tap) {
        const float4 v = *(const float4*)(part + ((size_t)(tap * 4 + phase) * L1_MPAD + m) * COUT + n4 * 4);
        acc.x += v.x; acc.y += v.y; acc.z += v.z; acc.w += v.w;
    }
    const int c = n4 * 4;
    float vv[4] = {acc.x, acc.y, acc.z, acc.w};
    float4 h4, l4;
    float* hp = &h4.x; float* lp = &l4.x;
#pragma unroll
    for (int e = 0; e < 4; ++e) {
        const float s = gma[c + e] * rsqrtf(var[c + e] + BN_EPS);
        const float bi = bta[c + e] - mu[c + e] * s;
        const float v = fmaxf(fmaf(vv[e], s, bi), 0.f);
        const float h = tf32_hi(v);
        hp[e] = h; lp[e] = v - h;
    }
    const int bb = m / 35; const int rem = m - bb * 35;
    const int ty = rem / 5; const int tx = rem - ty * 5;
    const int oy = 2 * ty + py, ox = 2 * tx + px;
    const size_t o = ((size_t)(bb * 14 + oy) * 10 + ox) * COUT + c;
    *(float4*)(Yh + o) = h4;
    *(float4*)(Yl + o) = l4;
}

// ===========================================================================
// Kernel B: m-paired 256x256 tiles for L2/L3 (Cin=256).
// mode 1: BN+ReLU+hi/lo split store (L2).
// mode 0: BN+ReLU then fused 1x1 conv (256->17)+bias -> transposed heatmap.
// ===========================================================================
__global__ __launch_bounds__(NTHR, 1)
void deconv_tc2(const float* __restrict__ Ah, const float* __restrict__ Al,
                const float* __restrict__ Wh, const float* __restrict__ Wl,
                const float* __restrict__ gma, const float* __restrict__ bta,
                const float* __restrict__ mu,  const float* __restrict__ var,
                float* __restrict__ Yh, float* __restrict__ Yl,
                const float* __restrict__ wfp, const float* __restrict__ bfp,
                float* __restrict__ hmp,
                int H, int W, int Cin, int mode)
{
#if TCPATH
    extern __shared__ char smem[];
    const uint32_t sb = smem_u32(smem);
    const int tid = threadIdx.x;
    const int wid = tid >> 5, lane = tid & 31;

    const int phase = blockIdx.y;
    const int py = phase >> 1, px = phase & 1;
    const int m0 = blockIdx.x * 256;
    const int Hp = H - 1, Wp = W - 1;
    const int HWp = Hp * Wp;
    const int M = BDIM_B * HWp;
    const int NK = Cin >> 3;
    const int NSLOT = 2 * NK;

    if (wid == 0) { TCGEN05_ALLOC(sb + SM_TMEMPTR, 512); TCGEN05_RELINQ(); }
    if (tid < 256) {
        const float s = gma[tid] * rsqrtf(var[tid] + BN_EPS);
        ((float*)(smem + SM_SC))[tid] = s;
        ((float*)(smem + SM_BI))[tid] = bta[tid] - mu[tid] * s;
    }
    if (mode == 0) {   // stage wf for the fused heatmap epilogue
        for (int i = tid; i < COUT * KPT; i += NTHR)
            ((float*)(smem + SM_WF))[i] = wfp[i];
    }
    if (tid < 3) MBARRIER_INIT(sb + SM_FULL + tid * 8, 256);
    else if (tid >= 32 && tid < 35) MBARRIER_INIT(sb + SM_DONE + (tid - 32) * 8, 1);
    __syncthreads();
    uint32_t tmem;
    asm volatile("ld.shared.b32 %0, [%1];" : "=r"(tmem) : "r"(sb + SM_TMEMPTR));

    if (wid < 8) {
        const int rr = tid >> 1, hh = tid & 1;
        size_t arow[2];
#pragma unroll
        for (int u = 0; u < 2; ++u) {
            int mrow = m0 + u * 128 + rr; if (mrow >= M) mrow = M - 1;
            const int bbA = mrow / HWp; const int remA = mrow - bbA * HWp;
            const int tyA = remA / Wp;  const int txA = remA - tyA * Wp;
            arow[u] = ((size_t)(bbA * H + tyA) * W + txA) * Cin;
        }
        const uint32_t off = (uint32_t)(rr * 128 + hh * 64);
        uint32_t swo[4];
#pragma unroll
        for (int j = 0; j < 4; ++j) swo[j] = SWZ(off + 16 * j);

        for (int sl = 0; sl < NSLOT; ++sl) {
            const int s3 = sl % 3;
            if (sl >= 3) mbar_wait(sb + SM_DONE + s3 * 8, (uint32_t)(((sl / 3) - 1) & 1));
            const int chunk = sl >> 1, half = sl & 1;
            const int kt = chunk * 32;
            const int tap = kt / Cin;
            const int ci0 = kt - tap * Cin;
            const int a = tap >> 1, bt = tap & 1;
            const int kh = 2 * a + 1 - py, kw = 2 * bt + 1 - px;
            const float* Aarr = half ? Al : Ah;
            const float* Warr = half ? Wl : Wh;
            const uint32_t stgo = SL_STAGE0 + s3 * SLOT_BYTES;
#pragma unroll
            for (int u = 0; u < 2; ++u) {
                const float* pa = Aarr + arow[u] + (size_t)(a * W + bt) * Cin + ci0 + hh * 16;
#pragma unroll
                for (int j = 0; j < 4; ++j)
                    *(float4*)(smem + stgo + u * 16384 + swo[j]) = *(const float4*)(pa + 4 * j);
            }
#pragma unroll
            for (int u = 0; u < 2; ++u) {
                const float* pb = Warr + ((size_t)((kh * 4 + kw) * COUT + rr + u * 128)) * Cin + ci0 + hh * 16;
#pragma unroll
                for (int j = 0; j < 4; ++j)
                    *(float4*)(smem + stgo + OFF2_B + u * 16384 + swo[j]) = *(const float4*)(pb + 4 * j);
            }
            FENCE_ASYNC_SHARED();
            MBARRIER_ARRIVE(sb + SM_FULL + s3 * 8);
        }
    } else {
        if (elect_one()) {
            for (int i = 0; i < NK; ++i) {
                const int jh = 2 * i, jl = 2 * i + 1;
                const int sh = jh % 3, slx = jl % 3;
                mbar_wait(sb + SM_FULL + sh * 8, (uint32_t)((jh / 3) & 1));
                mbar_wait(sb + SM_FULL + slx * 8, (uint32_t)((jl / 3) & 1));
                const uint32_t stg_h = sb + SL_STAGE0 + sh * SLOT_BYTES;
                const uint32_t stg_l = sb + SL_STAGE0 + slx * SLOT_BYTES;
                const uint64_t dAh0 = MAKE_DESC(stg_h);
                const uint64_t dAh1 = MAKE_DESC(stg_h + 16384);
                const uint64_t dAl0 = MAKE_DESC(stg_l);
                const uint64_t dAl1 = MAKE_DESC(stg_l + 16384);
                const uint64_t dBh  = MAKE_DESC(stg_h + OFF2_B);
                const uint64_t dBl  = MAKE_DESC(stg_l + OFF2_B);
#pragma unroll
                for (int ks = 0; ks < 4; ++ks) {
#pragma unroll
                    for (int pass = 0; pass < 3; ++pass) {
                        const uint64_t da0 = (pass == 2) ? dAl0 : dAh0;
                        const uint64_t da1 = (pass == 2) ? dAl1 : dAh1;
                        const uint64_t db  = (pass == 1) ? dBl  : dBh;
                        const uint32_t en = (i > 0 || ks > 0 || pass > 0) ? 1u : 0u;
#pragma unroll
                        for (int nh = 0; nh < 2; ++nh) {
                            mma_tf32_ss(tmem + 0   + nh * 128, da0 + ks * 2, db + nh * 1024 + ks * 2, en);
                            mma_tf32_ss(tmem + 256 + nh * 128, da1 + ks * 2, db + nh * 1024 + ks * 2, en);
                        }
                    }
                }
                TCGEN05_COMMIT(sb + SM_DONE + sh * 8);
                TCGEN05_COMMIT(sb + SM_DONE + slx * 8);
            }
        }
    }

    {
        const int jlast = NSLOT - 1;
        mbar_wait(sb + SM_DONE + (jlast % 3) * 8, (uint32_t)((jlast / 3) & 1));
    }
    TCGEN05_FENCE_AFTER();
    __syncthreads();

    if (wid < 8) {
        const float* scs = (const float*)(smem + SM_SC);
        const float* bis = (const float*)(smem + SM_BI);
        const float* wfs = (const float*)(smem + SM_WF);
        const int tile = wid >> 2, sub = wid & 3;
        const int m = m0 + tile * 128 + sub * 32 + lane;
        const bool valid = (m < M);
        int bb = 0, ty = 0, tx = 0;
        if (valid) { bb = m / HWp; const int rem = m - bb * HWp; ty = rem / Wp; tx = rem - ty * Wp; }
        const int H2 = 2 * H - 2, W2 = 2 * W - 2;
        const int oy = 2 * ty + py, ox = 2 * tx + px;

        float hacc[KPT];
        if (mode == 0) {
#pragma unroll
            for (int k = 0; k < KPT; ++k) hacc[k] = bfp[k];
        }
        const size_t obase = ((size_t)(bb * H2 + oy) * W2 + ox) * COUT;

#pragma unroll
        for (int q = 0; q < 8; ++q) {
            const int c0 = q * 32;
            uint32_t regs[32];
            TCGEN05_LD_X32(regs, tmem + tile * 256 + c0);
            TCGEN05_WAIT_LD();
            if (valid) {
                if (mode == 0) {
#pragma unroll
                    for (int e = 0; e < 32; ++e) {
                        const int c = c0 + e;
                        const float v = fmaxf(fmaf(__uint_as_float(regs[e]), scs[c], bis[c]), 0.f);
                        const float* wr = wfs + c * KPT;
#pragma unroll
                        for (int k = 0; k < KPT; ++k)
                            hacc[k] = fmaf(v, wr[k], hacc[k]);
                    }
                } else {
#pragma unroll
                    for (int k4 = 0; k4 < 8; ++k4) {
                        float v[4];
#pragma unroll
                        for (int e = 0; e < 4; ++e) {
                            const int c = c0 + k4 * 4 + e;
                            v[e] = fmaxf(fmaf(__uint_as_float(regs[k4 * 4 + e]), scs[c], bis[c]), 0.f);
                        }
                        float4 h4, l4;
                        h4.x = tf32_hi(v[0]); l4.x = v[0] - h4.x;
                        h4.y = tf32_hi(v[1]); l4.y = v[1] - h4.y;
                        h4.z = tf32_hi(v[2]); l4.z = v[2] - h4.z;
                        h4.w = tf32_hi(v[3]); l4.w = v[3] - h4.w;
                        *(float4*)(Yh + obase + c0 + k4 * 4) = h4;
                        *(float4*)(Yl + obase + c0 + k4 * 4) = l4;
                    }
                }
            }
        }
        if (mode == 0 && valid) {
            const int pp = oy * WD + ox;
            float* hb = hmp + (size_t)bb * KPT * HWD + pp;
#pragma unroll
            for (int k = 0; k < KPT; ++k)
                hb[(size_t)k * HWD] = hacc[k];
        }
    }

    __syncthreads();
    if (tid < 3) MBARRIER_INVAL(sb + SM_FULL + tid * 8);
    else if (tid >= 32 && tid < 35) MBARRIER_INVAL(sb + SM_DONE + (tid - 32) * 8);
    __syncthreads();
    if (wid == 0) TCGEN05_DEALLOC(tmem, 512);
#else
    // ------------------ fallback (non-accelerated pass) --------------------
    const int tid = threadIdx.x;
    const int phase = blockIdx.y;
    const int py = phase >> 1, px = phase & 1;
    const int m0 = blockIdx.x * 256;
    const int Hp = H - 1, Wp = W - 1;
    const int HWp = Hp * Wp;
    const int M = BDIM_B * HWp;
    const int H2 = 2 * H - 2, W2 = 2 * W - 2;

    if (mode == 1) {
        for (int idx = tid; idx < 256 * 256; idx += NTHR) {
            const int ml = idx >> 8, n = idx & 255;
            const int m = m0 + ml;
            if (m >= M) continue;
            const int bb = m / HWp; const int rem = m - bb * HWp;
            const int ty = rem / Wp; const int tx = rem - ty * Wp;
            float acc = 0.f;
            for (int tap = 0; tap < 4; ++tap) {
                const int a = tap >> 1, bt = tap & 1;
                const int kh = 2 * a + 1 - py, kw = 2 * bt + 1 - px;
                const float* ah = Ah + ((size_t)(bb * H + ty + a) * W + tx + bt) * Cin;
                const float* al = Al + ((size_t)(bb * H + ty + a) * W + tx + bt) * Cin;
                const float* wh = Wh + ((size_t)((kh * 4 + kw) * COUT + n)) * Cin;
                const float* wl = Wl + ((size_t)((kh * 4 + kw) * COUT + n)) * Cin;
                for (int c = 0; c < Cin; ++c)
                    acc = fmaf(ah[c] + al[c], wh[c] + wl[c], acc);
            }
            const float s = gma[n] * rsqrtf(var[n] + BN_EPS);
            float v = fmaxf(fmaf(acc - mu[n], s, bta[n]), 0.f);
            const int oy = 2 * ty + py, ox = 2 * tx + px;
            const size_t o = ((size_t)(bb * H2 + oy) * W2 + ox) * COUT + n;
            const float h = tf32_hi(v); Yh[o] = h; Yl[o] = v - h;
        }
    } else {
        for (int ml = tid; ml < 256; ml += NTHR) {
            const int m = m0 + ml;
            if (m >= M) continue;
            const int bb = m / HWp; const int rem = m - bb * HWp;
            const int ty = rem / Wp; const int tx = rem - ty * Wp;
            float hacc[KPT];
            for (int k = 0; k < KPT; ++k) hacc[k] = bfp[k];
            for (int n = 0; n < COUT; ++n) {
                float acc = 0.f;
                for (int tap = 0; tap < 4; ++tap) {
                    const int a = tap >> 1, bt = tap & 1;
                    const int kh = 2 * a + 1 - py, kw = 2 * bt + 1 - px;
                    const float* ah = Ah + ((size_t)(bb * H + ty + a) * W + tx + bt) * Cin;
                    const float* al = Al + ((size_t)(bb * H + ty + a) * W + tx + bt) * Cin;
                    const float* wh = Wh + ((size_t)((kh * 4 + kw) * COUT + n)) * Cin;
                    const float* wl = Wl + ((size_t)((kh * 4 + kw) * COUT + n)) * Cin;
                    for (int c = 0; c < Cin; ++c)
                        acc = fmaf(ah[c] + al[c], wh[c] + wl[c], acc);
                }
                const float s = gma[n] * rsqrtf(var[n] + BN_EPS);
                const float v = fmaxf(fmaf(acc - mu[n], s, bta[n]), 0.f);
                for (int k = 0; k < KPT; ++k)
                    hacc[k] = fmaf(v, wfp[n * KPT + k], hacc[k]);
            }
            const int oy = 2 * ty + py, ox = 2 * tx + px;
            const int pp = oy * WD + ox;
            for (int k = 0; k < KPT; ++k)
                hmp[(size_t)(bb * KPT + k) * HWD + pp] = hacc[k];
        }
    }
#endif
}

// ---------------------------------------------------------------------------
// Per-(b,k) argmax + subpixel refinement.
// ---------------------------------------------------------------------------
__global__ void detect_kernel(const float* __restrict__ hm, float* __restrict__ out)
{
    const float* row = hm + (size_t)blockIdx.x * HWD;
    const int tid = threadIdx.x;

    float best = -3.402823466e+38f; int bidx = 0x7fffffff;
    for (int i = tid; i < HWD; i += 128) {
        const float v = row[i];
        if (v > best) { best = v; bidx = i; }
    }
    __shared__ float sv[128];
    __shared__ int   si[128];
    sv[tid] = best; si[tid] = bidx;
    __syncthreads();
    for (int s = 64; s > 0; s >>= 1) {
        if (tid < s) {
            const float v2 = sv[tid + s]; const int i2 = si[tid + s];
            if (v2 > sv[tid] || (v2 == sv[tid] && i2 < si[tid])) { sv[tid] = v2; si[tid] = i2; }
        }
        __syncthreads();
    }
    if (tid == 0) {
        const float score = sv[0];
        const int idx = si[0];
        const bool pos = score > 0.f;
        const int pxi = pos ? (idx % WD) : 0;
        const int pyi = pos ? (idx / WD) : 0;
        const bool inner = (pxi > 0) && (pxi < WD - 1) && (pyi > 0) && (pyi < HD - 1);
        float dx = 0.f, dy = 0.f;
        if (inner) {
            const int base = pyi * WD + pxi;
            const float d1 = row[base + 1]  - row[base - 1];
            const float d2 = row[base + WD] - row[base - WD];
            dx = (d1 > 0.f) ? 0.25f : ((d1 < 0.f) ? -0.25f : 0.f);
            dy = (d2 > 0.f) ? 0.25f : ((d2 < 0.f) ? -0.25f : 0.f);
        }
        float* o = out + (size_t)blockIdx.x * 3;
        o[0] = (float)pxi + dx;
        o[1] = (float)pyi + dy;
        o[2] = score;
    }
}

// ---------------------------------------------------------------------------
extern "C" void kernel_launch(void* const* d_in, const int* in_sizes, int n_in,
                              void* d_out, int out_size)
{
    const float* x  = (const float*)d_in[0];
    const float* w1 = (const float*)d_in[1];
    const float* g1 = (const float*)d_in[2];
    const float* b1 = (const float*)d_in[3];
    const float* m1 = (const float*)d_in[4];
    const float* v1 = (const float*)d_in[5];
    const float* w2 = (const float*)d_in[6];
    const float* g2 = (const float*)d_in[7];
    const float* b2 = (const float*)d_in[8];
    const float* m2 = (const float*)d_in[9];
    const float* v2 = (const float*)d_in[10];
    const float* w3 = (const float*)d_in[11];
    const float* g3 = (const float*)d_in[12];
    const float* b3 = (const float*)d_in[13];
    const float* m3 = (const float*)d_in[14];
    const float* v3 = (const float*)d_in[15];
    const float* wf = (const float*)d_in[16];
    const float* bf = (const float*)d_in[17];
    float* out = (float*)d_out;

    float *xh, *xl, *w1h, *w1l, *w2h, *w2l, *w3h, *w3l;
    float *p1, *y1h, *y1l, *y2h, *y2l, *hm;
    cudaGetSymbolAddress((void**)&xh,  g_xh);
    cudaGetSymbolAddress((void**)&xl,  g_xl);
    cudaGetSymbolAddress((void**)&w1h, g_w1h);
    cudaGetSymbolAddress((void**)&w1l, g_w1l);
    cudaGetSymbolAddress((void**)&w2h, g_w2h);
    cudaGetSymbolAddress((void**)&w2l, g_w2l);
    cudaGetSymbolAddress((void**)&w3h, g_w3h);
    cudaGetSymbolAddress((void**)&w3l, g_w3l);
    cudaGetSymbolAddress((void**)&p1,  g_p1);
    cudaGetSymbolAddress((void**)&y1h, g_y1h);
    cudaGetSymbolAddress((void**)&y1l, g_y1l);
    cudaGetSymbolAddress((void**)&y2h, g_y2h);
    cudaGetSymbolAddress((void**)&y2l, g_y2l);
    cudaGetSymbolAddress((void**)&hm,  g_hm);

    static bool attr_done = false;
    if (!attr_done) {
        cudaFuncSetAttribute(deconv_tc1s, cudaFuncAttributeMaxDynamicSharedMemorySize, SMEM2_TOTAL);
        cudaFuncSetAttribute(deconv_tc2,  cudaFuncAttributeMaxDynamicSharedMemorySize, SMEM2_TOTAL);
        attr_done = true;
    }

    // preprocess: split x; transpose+split weights
    split_kernel<<<4096, 256>>>(x, xh, xl, BDIM_B * 8 * 6 * 2048);
    wtrans_kernel<<<dim3(2048 / 32, COUT / 32, 16), dim3(32, 8)>>>(w1, w1h, w1l, 2048);
    wtrans_kernel<<<dim3(256 / 32,  COUT / 32, 16), dim3(32, 8)>>>(w2, w2h, w2l, 256);
    wtrans_kernel<<<dim3(256 / 32,  COUT / 32, 16), dim3(32, 8)>>>(w3, w3h, w3l, 256);

    // L1 split-K-by-tap: grid (9 m-pair tiles, 4 phases, 4 taps) = 144 CTAs
    deconv_tc1s<<<dim3(9, 4, 4), NTHR, SMEM2_TOTAL>>>(xh, xl, w1h, w1l, p1);
    reduce_l1<<<(4 * L1_M * 64 + 255) / 256, 256>>>(p1, g1, b1, m1, v1, y1h, y1l);

    // L2: -> [64,26,18,256] split.  M_phase = 7488 -> 30 m-pair tiles
    deconv_tc2<<<dim3(30, 4), NTHR, SMEM2_TOTAL>>>(y1h, y1l, w2h, w2l, g2, b2, m2, v2,
                                                   y2h, y2l, nullptr, nullptr, nullptr,
                                                   14, 10, 256, 1);
    // L3 + fused heatmap: M_phase = 27200 -> 107 m-pair tiles
    deconv_tc2<<<dim3(107, 4), NTHR, SMEM2_TOTAL>>>(y2h, y2l, w3h, w3l, g3, b3, m3, v3,
                                                    nullptr, nullptr, wf, bf, hm,
                                                    26, 18, 256, 0);
    // argmax + subpixel per (b, keypoint)
    detect_kernel<<<BDIM_B * KPT, 128>>>(hm, out);
}

// round 10
// speedup vs baseline: 3.7737x; 1.0120x over previous
#include <cuda_runtime.h>
#include <cuda_bf16.h>
#include <cstdint>

// ---------------------------------------------------------------------------
// SimplePose via tcgen05 tf32 3-pass (fp32-equivalent) GEMMs.
//   3x (conv_transpose k4 s2 pads(1,1) + BN + ReLU) -> 1x1 conv -> argmax det
// Phase decomposition (py,px): kh = 2a+1-py, iy = ty+a  -> dense GEMM
//   M = B*(H-1)*(W-1), K = 4*Cin, N = 256 per phase.
// fp32 emulation: v = hi + lo, hi = cvt.rna.tf32(v);
//   C = Ah*Bh + Ah*Bl + Al*Bh  (3 tcgen05 passes into one fp32 TMEM tile)
//
// Round 10: lo terms stored as bf16 (operand traffic 8 -> 6 B/elem; added
// quantization ~2^-20 relative, negligible). Loaders convert bf16->f32 in
// registers before STS; SMEM layout / MMA schedule unchanged.
// ---------------------------------------------------------------------------

#if defined(__CUDA_ARCH_FEAT_SM103_ALL) || defined(__CUDA_ARCH_FEAT_SM100_ALL)
#define TCPATH 1
#else
#define TCPATH 0
#endif

#define BDIM_B   64
#define COUT     256
#define KPT      17
#define BN_EPS   1e-5f
#define HD 50
#define WD 34
#define HWD (HD * WD)          // 1700
#define NTHR 288               // 8 loader warps + 1 MMA warp

// L1 split-K partial layout: [tap(4)][phase(4)][m(2304)][n(256)]
#define L1_MPAD 2304
#define L1_M 2240              // 64 * 7 * 5

typedef __nv_bfloat16 bf16;

// ---------------- scratch (static; cudaMalloc forbidden) -------------------
__device__ float g_xh[BDIM_B * 8 * 6 * 2048];
__device__ bf16  g_xl[BDIM_B * 8 * 6 * 2048];
__device__ float g_w1h[16 * COUT * 2048];
__device__ bf16  g_w1l[16 * COUT * 2048];
__device__ float g_w2h[16 * COUT * 256];
__device__ bf16  g_w2l[16 * COUT * 256];
__device__ float g_w3h[16 * COUT * 256];
__device__ bf16  g_w3l[16 * COUT * 256];
__device__ float g_p1 [4 * 4 * L1_MPAD * COUT];        // 37.7 MB partials
__device__ float g_y1h[BDIM_B * 14 * 10 * COUT];
__device__ bf16  g_y1l[BDIM_B * 14 * 10 * COUT];
__device__ float g_y2h[BDIM_B * 26 * 18 * COUT];
__device__ bf16  g_y2l[BDIM_B * 26 * 18 * COUT];
__device__ float g_hm [BDIM_B * KPT * HWD];

// ---------------------------- helpers (arch-neutral) -----------------------
__device__ __forceinline__ float tf32_hi(float v) {
    float r;
    asm("cvt.rna.tf32.f32 %0, %1;" : "=f"(r) : "f"(v));
    return r;
}

#if TCPATH
__device__ __forceinline__ uint32_t smem_u32(const void* p) {
    uint32_t a;
    asm("{ .reg .u64 t; cvta.to.shared.u64 t, %1; cvt.u32.u64 %0, t; }" : "=r"(a) : "l"(p));
    return a;
}
__device__ __forceinline__ uint32_t elect_one() {
    uint32_t pr;
    asm volatile("{\n\t.reg .pred p;\n\telect.sync _|p, 0xFFFFFFFF;\n\tselp.b32 %0, 1, 0, p;\n\t}" : "=r"(pr));
    return pr;
}

// 16 consecutive bf16 -> 16 f32 (exact)
__device__ __forceinline__ void lo16_to_f32(const bf16* __restrict__ p, float* f) {
    const uint4 q0 = *(const uint4*)p;
    const uint4 q1 = *(const uint4*)(p + 8);
    const __nv_bfloat162* h0 = (const __nv_bfloat162*)&q0;
    const __nv_bfloat162* h1 = (const __nv_bfloat162*)&q1;
#pragma unroll
    for (int i = 0; i < 4; ++i) {
        const float2 a = __bfloat1622float2(h0[i]);
        const float2 b = __bfloat1622float2(h1[i]);
        f[2 * i]     = a.x; f[2 * i + 1]     = a.y;
        f[8 + 2 * i] = b.x; f[8 + 2 * i + 1] = b.y;
    }
}

#define MBARRIER_INIT(addr, cnt) \
    asm volatile("mbarrier.init.shared.b64 [%0], %1;" :: "r"(addr), "r"(cnt) : "memory")
#define MBARRIER_INVAL(addr) \
    asm volatile("mbarrier.inval.shared.b64 [%0];" :: "r"(addr) : "memory")
#define MBARRIER_ARRIVE(addr) \
    asm volatile("mbarrier.arrive.release.cta.shared::cta.b64 _, [%0];" :: "r"(addr) : "memory")
__device__ __forceinline__ void mbar_wait(uint32_t mbar, uint32_t parity) {
    asm volatile(
        "{\n\t.reg .pred P;\n\t"
        "WL%=:\n\t"
        "mbarrier.try_wait.parity.acquire.cta.shared::cta.b64 P, [%0], %1, 0x989680;\n\t"
        "@P bra.uni WD%=;\n\t"
        "bra.uni WL%=;\n\t"
        "WD%=:\n\t}"
        :: "r"(mbar), "r"(parity) : "memory");
}
#define TCGEN05_ALLOC(sm, n) \
    asm volatile("tcgen05.alloc.cta_group::1.sync.aligned.shared::cta.b32 [%0], %1;" :: "r"(sm), "r"(n) : "memory")
#define TCGEN05_DEALLOC(tm, n) \
    asm volatile("tcgen05.dealloc.cta_group::1.sync.aligned.b32 %0, %1;" :: "r"(tm), "r"(n))
#define TCGEN05_RELINQ() \
    asm volatile("tcgen05.relinquish_alloc_permit.cta_group::1.sync.aligned;")
#define TCGEN05_COMMIT(mb) \
    asm volatile("tcgen05.commit.cta_group::1.mbarrier::arrive::one.shared::cluster.b64 [%0];" :: "r"(mb) : "memory")
#define TCGEN05_FENCE_AFTER() \
    asm volatile("tcgen05.fence::after_thread_sync;" ::: "memory")
#define TCGEN05_WAIT_LD() \
    asm volatile("tcgen05.wait::ld.sync.aligned;" ::: "memory")
#define FENCE_ASYNC_SHARED() \
    asm volatile("fence.proxy.async.shared::cta;" ::: "memory")

#define TCGEN05_LD_X32(r, tm) \
    asm volatile( \
        "tcgen05.ld.sync.aligned.32x32b.x32.b32 " \
        "{%0, %1, %2, %3, %4, %5, %6, %7, " \
        " %8, %9, %10, %11, %12, %13, %14, %15, " \
        " %16, %17, %18, %19, %20, %21, %22, %23, " \
        " %24, %25, %26, %27, %28, %29, %30, %31}, [%32];" \
        : "=r"((r)[0]),  "=r"((r)[1]),  "=r"((r)[2]),  "=r"((r)[3]), \
          "=r"((r)[4]),  "=r"((r)[5]),  "=r"((r)[6]),  "=r"((r)[7]), \
          "=r"((r)[8]),  "=r"((r)[9]),  "=r"((r)[10]), "=r"((r)[11]), \
          "=r"((r)[12]), "=r"((r)[13]), "=r"((r)[14]), "=r"((r)[15]), \
          "=r"((r)[16]), "=r"((r)[17]), "=r"((r)[18]), "=r"((r)[19]), \
          "=r"((r)[20]), "=r"((r)[21]), "=r"((r)[22]), "=r"((r)[23]), \
          "=r"((r)[24]), "=r"((r)[25]), "=r"((r)[26]), "=r"((r)[27]), \
          "=r"((r)[28]), "=r"((r)[29]), "=r"((r)[30]), "=r"((r)[31]) \
        : "r"(tm))

// SMEM descriptor (K-major SW128: LBO=1, SBO=64, version=1, layout=2)
#define SMEM_DESC_BASE \
    ((uint64_t(2) << 61) | (uint64_t(1) << 46) | (uint64_t(64) << 32) | (uint64_t(1) << 16))
#define MAKE_DESC(addr) (SMEM_DESC_BASE | ((uint64_t)((addr) >> 4) & 0x3FFF))

// tf32 SS MMA, cta_group::1, M=128, N=128, K=8 per issue
#define IDESC_TF32 ((1u << 4) | (2u << 7) | (2u << 10) | (16u << 17) | (8u << 24))

__device__ __forceinline__ void mma_tf32_ss(uint32_t d, uint64_t da, uint64_t db,
                                            uint32_t en) {
    asm volatile(
        "{\n\t.reg .pred p;\n\t"
        "setp.ne.u32 p, %4, 0;\n\t"
        "tcgen05.mma.cta_group::1.kind::tf32 [%0], %1, %2, %3, {%5, %5, %5, %5}, p;\n\t"
        "}"
        :: "r"(d), "l"(da), "l"(db), "r"(IDESC_TF32), "r"(en), "r"(0u)
        : "memory");
}
#endif  // TCPATH

#define SWZ(o) ((o) ^ (((o) >> 3) & 0x70))

// SMEM layout shared by GEMM kernels
#define SLOT_BYTES 65536
#define OFF2_B 32768
#define SM_TMEMPTR 0
#define SM_FULL 8
#define SM_DONE 32
#define SM_SC 64
#define SM_BI (64 + 1024)
#define SL_STAGE0 4096
#define SM_WF (SL_STAGE0 + 3 * SLOT_BYTES)          // 200704: wf[256*17]
#define SMEM2_TOTAL (SM_WF + COUT * KPT * 4)         // 218112

// ---------------------------------------------------------------------------
// Preprocess: elementwise hi/lo split (lo -> bf16)
// ---------------------------------------------------------------------------
__global__ void split_kernel(const float* __restrict__ in, float* __restrict__ hi,
                             bf16* __restrict__ lo, int n)
{
    for (int i = blockIdx.x * blockDim.x + threadIdx.x; i < n; i += gridDim.x * blockDim.x) {
        const float v = in[i];
        const float h = tf32_hi(v);
        hi[i] = h; lo[i] = __float2bfloat16_rn(v - h);
    }
}

// Weight transpose + split: w[t, ci, co] -> wt[t, co, ci] (hi f32 / lo bf16)
__global__ void wtrans_kernel(const float* __restrict__ w, float* __restrict__ th,
                              bf16* __restrict__ tl, int Cin)
{
    __shared__ float tile[32][33];
    const int t = blockIdx.z;
    const int ci0 = blockIdx.x * 32, co0 = blockIdx.y * 32;
    const int tx = threadIdx.x, ty = threadIdx.y;   // block (32, 8)
#pragma unroll
    for (int i = 0; i < 4; ++i)
        tile[ty + 8 * i][tx] = w[((size_t)(t * Cin + ci0 + ty + 8 * i)) * COUT + co0 + tx];
    __syncthreads();
#pragma unroll
    for (int i = 0; i < 4; ++i) {
        const float v = tile[tx][ty + 8 * i];
        const float h = tf32_hi(v);
        const size_t o = ((size_t)(t * COUT + co0 + ty + 8 * i)) * Cin + ci0 + tx;
        th[o] = h; tl[o] = __float2bfloat16_rn(v - h);
    }
}

// ===========================================================================
// Kernel L1S: split-K-by-tap m-paired 256x256 GEMM for L1 (Cin=2048).
// ===========================================================================
__global__ __launch_bounds__(NTHR, 1)
void deconv_tc1s(const float* __restrict__ Ah, const bf16* __restrict__ Al,
                 const float* __restrict__ Wh, const bf16* __restrict__ Wl,
                 float* __restrict__ part)
{
    const int H = 8, W = 6, Cin = 2048;
    const int Hp = 7, Wp = 5, HWp = 35;
    const int M = L1_M;
#if TCPATH
    extern __shared__ char smem[];
    const uint32_t sb = smem_u32(smem);
    const int tid = threadIdx.x;
    const int wid = tid >> 5, lane = tid & 31;

    const int phase = blockIdx.y;
    const int py = phase >> 1, px = phase & 1;
    const int tap = blockIdx.z;
    const int a = tap >> 1, bt = tap & 1;
    const int kh = 2 * a + 1 - py, kw = 2 * bt + 1 - px;
    const int m0 = blockIdx.x * 256;
    const int NK = Cin >> 5;               // 64 chunks of K=32
    const int NSLOT = 2 * NK;              // 128 slots

    if (wid == 0) { TCGEN05_ALLOC(sb + SM_TMEMPTR, 512); TCGEN05_RELINQ(); }
    if (tid < 3) MBARRIER_INIT(sb + SM_FULL + tid * 8, 256);
    else if (tid >= 32 && tid < 35) MBARRIER_INIT(sb + SM_DONE + (tid - 32) * 8, 1);
    __syncthreads();
    uint32_t tmem;
    asm volatile("ld.shared.b32 %0, [%1];" : "=r"(tmem) : "r"(sb + SM_TMEMPTR));

    if (wid < 8) {
        const int rr = tid >> 1, hh = tid & 1;
        size_t arow[2];
#pragma unroll
        for (int u = 0; u < 2; ++u) {
            int mrow = m0 + u * 128 + rr; if (mrow >= M) mrow = M - 1;
            const int bbA = mrow / HWp; const int remA = mrow - bbA * HWp;
            const int tyA = remA / Wp;  const int txA = remA - tyA * Wp;
            arow[u] = ((size_t)(bbA * H + tyA + a) * W + txA + bt) * Cin;
        }
        const size_t brow0 = ((size_t)((kh * 4 + kw) * COUT + rr)) * Cin;
        const size_t brow1 = ((size_t)((kh * 4 + kw) * COUT + rr + 128)) * Cin;
        const uint32_t off = (uint32_t)(rr * 128 + hh * 64);
        uint32_t swo[4];
#pragma unroll
        for (int j = 0; j < 4; ++j) swo[j] = SWZ(off + 16 * j);

        for (int sl = 0; sl < NSLOT; ++sl) {
            const int s3 = sl % 3;
            if (sl >= 3) mbar_wait(sb + SM_DONE + s3 * 8, (uint32_t)(((sl / 3) - 1) & 1));
            const int chunk = sl >> 1, half = sl & 1;
            const int ci0 = chunk * 32 + hh * 16;
            const uint32_t stgo = SL_STAGE0 + s3 * SLOT_BYTES;
            if (half == 0) {
#pragma unroll
                for (int u = 0; u < 2; ++u) {
                    const float* pa = Ah + arow[u] + ci0;
#pragma unroll
                    for (int j = 0; j < 4; ++j)
                        *(float4*)(smem + stgo + u * 16384 + swo[j]) = *(const float4*)(pa + 4 * j);
                }
                const float* pb0 = Wh + brow0 + ci0;
                const float* pb1 = Wh + brow1 + ci0;
#pragma unroll
                for (int j = 0; j < 4; ++j) {
                    *(float4*)(smem + stgo + OFF2_B + swo[j])         = *(const float4*)(pb0 + 4 * j);
                    *(float4*)(smem + stgo + OFF2_B + 16384 + swo[j]) = *(const float4*)(pb1 + 4 * j);
                }
            } else {
                float f[16];
#pragma unroll
                for (int u = 0; u < 2; ++u) {
                    lo16_to_f32(Al + arow[u] + ci0, f);
#pragma unroll
                    for (int j = 0; j < 4; ++j)
                        *(float4*)(smem + stgo + u * 16384 + swo[j]) =
                            make_float4(f[4 * j], f[4 * j + 1], f[4 * j + 2], f[4 * j + 3]);
                }
                lo16_to_f32(Wl + brow0 + ci0, f);
#pragma unroll
                for (int j = 0; j < 4; ++j)
                    *(float4*)(smem + stgo + OFF2_B + swo[j]) =
                        make_float4(f[4 * j], f[4 * j + 1], f[4 * j + 2], f[4 * j + 3]);
                lo16_to_f32(Wl + brow1 + ci0, f);
#pragma unroll
                for (int j = 0; j < 4; ++j)
                    *(float4*)(smem + stgo + OFF2_B + 16384 + swo[j]) =
                        make_float4(f[4 * j], f[4 * j + 1], f[4 * j + 2], f[4 * j + 3]);
            }
            FENCE_ASYNC_SHARED();
            MBARRIER_ARRIVE(sb + SM_FULL + s3 * 8);
        }
    } else {
        if (elect_one()) {
            for (int i = 0; i < NK; ++i) {
                const int jh = 2 * i, jl = 2 * i + 1;
                const int sh = jh % 3, slx = jl % 3;
                mbar_wait(sb + SM_FULL + sh * 8, (uint32_t)((jh / 3) & 1));
                mbar_wait(sb + SM_FULL + slx * 8, (uint32_t)((jl / 3) & 1));
                const uint32_t stg_h = sb + SL_STAGE0 + sh * SLOT_BYTES;
                const uint32_t stg_l = sb + SL_STAGE0 + slx * SLOT_BYTES;
                const uint64_t dAh0 = MAKE_DESC(stg_h);
                const uint64_t dAh1 = MAKE_DESC(stg_h + 16384);
                const uint64_t dAl0 = MAKE_DESC(stg_l);
                const uint64_t dAl1 = MAKE_DESC(stg_l + 16384);
                const uint64_t dBh  = MAKE_DESC(stg_h + OFF2_B);
                const uint64_t dBl  = MAKE_DESC(stg_l + OFF2_B);
#pragma unroll
                for (int ks = 0; ks < 4; ++ks) {
#pragma unroll
                    for (int pass = 0; pass < 3; ++pass) {
                        const uint64_t da0 = (pass == 2) ? dAl0 : dAh0;
                        const uint64_t da1 = (pass == 2) ? dAl1 : dAh1;
                        const uint64_t db  = (pass == 1) ? dBl  : dBh;
                        const uint32_t en = (i > 0 || ks > 0 || pass > 0) ? 1u : 0u;
#pragma unroll
                        for (int nh = 0; nh < 2; ++nh) {
                            mma_tf32_ss(tmem + 0   + nh * 128, da0 + ks * 2, db + nh * 1024 + ks * 2, en);
                            mma_tf32_ss(tmem + 256 + nh * 128, da1 + ks * 2, db + nh * 1024 + ks * 2, en);
                        }
                    }
                }
                TCGEN05_COMMIT(sb + SM_DONE + sh * 8);
                TCGEN05_COMMIT(sb + SM_DONE + slx * 8);
            }
        }
    }

    {
        const int jlast = NSLOT - 1;
        mbar_wait(sb + SM_DONE + (jlast % 3) * 8, (uint32_t)((jlast / 3) & 1));
    }
    TCGEN05_FENCE_AFTER();
    __syncthreads();

    if (wid < 8) {
        const int tile = wid >> 2, sub = wid & 3;
        const int m = m0 + tile * 128 + sub * 32 + lane;
        float* pb = part + (((size_t)(tap * 4 + phase) * L1_MPAD + m) * COUT);
#pragma unroll
        for (int q = 0; q < 8; ++q) {
            const int c0 = q * 32;
            uint32_t regs[32];
            TCGEN05_LD_X32(regs, tmem + tile * 256 + c0);
            TCGEN05_WAIT_LD();
#pragma unroll
            for (int k4 = 0; k4 < 8; ++k4) {
                float4 v;
                v.x = __uint_as_float(regs[k4 * 4 + 0]);
                v.y = __uint_as_float(regs[k4 * 4 + 1]);
                v.z = __uint_as_float(regs[k4 * 4 + 2]);
                v.w = __uint_as_float(regs[k4 * 4 + 3]);
                *(float4*)(pb + c0 + k4 * 4) = v;
            }
        }
    }

    __syncthreads();
    if (tid < 3) MBARRIER_INVAL(sb + SM_FULL + tid * 8);
    else if (tid >= 32 && tid < 35) MBARRIER_INVAL(sb + SM_DONE + (tid - 32) * 8);
    __syncthreads();
    if (wid == 0) TCGEN05_DEALLOC(tmem, 512);
#else
    const int tid = threadIdx.x;
    const int phase = blockIdx.y;
    const int py = phase >> 1, px = phase & 1;
    const int tap = blockIdx.z;
    const int a = tap >> 1, bt = tap & 1;
    const int kh = 2 * a + 1 - py, kw = 2 * bt + 1 - px;
    const int m0 = blockIdx.x * 256;
    for (int idx = tid; idx < 256 * 256; idx += NTHR) {
        const int ml = idx >> 8, n = idx & 255;
        const int m = m0 + ml;
        if (m >= M) continue;
        const int bb = m / HWp; const int rem = m - bb * HWp;
        const int ty = rem / Wp; const int tx = rem - ty * Wp;
        const float* ah = Ah + ((size_t)(bb * H + ty + a) * W + tx + bt) * Cin;
        const bf16*  al = Al + ((size_t)(bb * H + ty + a) * W + tx + bt) * Cin;
        const float* wh = Wh + ((size_t)((kh * 4 + kw) * COUT + n)) * Cin;
        const bf16*  wl = Wl + ((size_t)((kh * 4 + kw) * COUT + n)) * Cin;
        float acc = 0.f;
        for (int c = 0; c < Cin; ++c)
            acc = fmaf(ah[c] + __bfloat162float(al[c]), wh[c] + __bfloat162float(wl[c]), acc);
        part[(((size_t)(tap * 4 + phase) * L1_MPAD + m) * COUT) + n] = acc;
    }
#endif
}

// Reduce L1 partials: sum 4 taps, BN + ReLU, hi/lo split, scatter NHWC.
__global__ __launch_bounds__(256)
void reduce_l1(const float* __restrict__ part,
               const float* __restrict__ gma, const float* __restrict__ bta,
               const float* __restrict__ mu,  const float* __restrict__ var,
               float* __restrict__ Yh, bf16* __restrict__ Yl)
{
    const int t = blockIdx.x * 256 + threadIdx.x;
    if (t >= 4 * L1_M * 64) return;
    const int n4 = t & 63;
    const int rest = t >> 6;
    const int m = rest % L1_M;
    const int phase = rest / L1_M;
    const int py = phase >> 1, px = phase & 1;

    float4 acc = make_float4(0.f, 0.f, 0.f, 0.f);
#pragma unroll
    for (int tap = 0; tap < 4; ++tap) {
        const float4 v = *(const float4*)(part + ((size_t)(tap * 4 + phase) * L1_MPAD + m) * COUT + n4 * 4);
        acc.x += v.x; acc.y += v.y; acc.z += v.z; acc.w += v.w;
    }
    const int c = n4 * 4;
    float vv[4] = {acc.x, acc.y, acc.z, acc.w};
    float4 h4;
    float lo[4];
    float* hp = &h4.x;
#pragma unroll
    for (int e = 0; e < 4; ++e) {
        const float s = gma[c + e] * rsqrtf(var[c + e] + BN_EPS);
        const float bi = bta[c + e] - mu[c + e] * s;
        const float v = fmaxf(fmaf(vv[e], s, bi), 0.f);
        const float h = tf32_hi(v);
        hp[e] = h; lo[e] = v - h;
    }
    const int bb = m / 35; const int rem = m - bb * 35;
    const int ty = rem / 5; const int tx = rem - ty * 5;
    const int oy = 2 * ty + py, ox = 2 * tx + px;
    const size_t o = ((size_t)(bb * 14 + oy) * 10 + ox) * COUT + c;
    *(float4*)(Yh + o) = h4;
    *(__nv_bfloat162*)(Yl + o)     = __floats2bfloat162_rn(lo[0], lo[1]);
    *(__nv_bfloat162*)(Yl + o + 2) = __floats2bfloat162_rn(lo[2], lo[3]);
}

// ===========================================================================
// Kernel B: m-paired 256x256 tiles for L2/L3 (Cin=256).
// mode 1: BN+ReLU + hi(f32)/lo(bf16) split store (L2).
// mode 0: BN+ReLU then fused 1x1 conv (256->17)+bias -> transposed heatmap.
// ===========================================================================
__global__ __launch_bounds__(NTHR, 1)
void deconv_tc2(const float* __restrict__ Ah, const bf16* __restrict__ Al,
                const float* __restrict__ Wh, const bf16* __restrict__ Wl,
                const float* __restrict__ gma, const float* __restrict__ bta,
                const float* __restrict__ mu,  const float* __restrict__ var,
                float* __restrict__ Yh, bf16* __restrict__ Yl,
                const float* __restrict__ wfp, const float* __restrict__ bfp,
                float* __restrict__ hmp,
                int H, int W, int Cin, int mode)
{
#if TCPATH
    extern __shared__ char smem[];
    const uint32_t sb = smem_u32(smem);
    const int tid = threadIdx.x;
    const int wid = tid >> 5, lane = tid & 31;

    const int phase = blockIdx.y;
    const int py = phase >> 1, px = phase & 1;
    const int m0 = blockIdx.x * 256;
    const int Hp = H - 1, Wp = W - 1;
    const int HWp = Hp * Wp;
    const int M = BDIM_B * HWp;
    const int NK = Cin >> 3;
    const int NSLOT = 2 * NK;

    if (wid == 0) { TCGEN05_ALLOC(sb + SM_TMEMPTR, 512); TCGEN05_RELINQ(); }
    if (tid < 256) {
        const float s = gma[tid] * rsqrtf(var[tid] + BN_EPS);
        ((float*)(smem + SM_SC))[tid] = s;
        ((float*)(smem + SM_BI))[tid] = bta[tid] - mu[tid] * s;
    }
    if (mode == 0) {
        for (int i = tid; i < COUT * KPT; i += NTHR)
            ((float*)(smem + SM_WF))[i] = wfp[i];
    }
    if (tid < 3) MBARRIER_INIT(sb + SM_FULL + tid * 8, 256);
    else if (tid >= 32 && tid < 35) MBARRIER_INIT(sb + SM_DONE + (tid - 32) * 8, 1);
    __syncthreads();
    uint32_t tmem;
    asm volatile("ld.shared.b32 %0, [%1];" : "=r"(tmem) : "r"(sb + SM_TMEMPTR));

    if (wid < 8) {
        const int rr = tid >> 1, hh = tid & 1;
        size_t arow[2];
#pragma unroll
        for (int u = 0; u < 2; ++u) {
            int mrow = m0 + u * 128 + rr; if (mrow >= M) mrow = M - 1;
            const int bbA = mrow / HWp; const int remA = mrow - bbA * HWp;
            const int tyA = remA / Wp;  const int txA = remA - tyA * Wp;
            arow[u] = ((size_t)(bbA * H + tyA) * W + txA) * Cin;
        }
        const uint32_t off = (uint32_t)(rr * 128 + hh * 64);
        uint32_t swo[4];
#pragma unroll
        for (int j = 0; j < 4; ++j) swo[j] = SWZ(off + 16 * j);

        for (int sl = 0; sl < NSLOT; ++sl) {
            const int s3 = sl % 3;
            if (sl >= 3) mbar_wait(sb + SM_DONE + s3 * 8, (uint32_t)(((sl / 3) - 1) & 1));
            const int chunk = sl >> 1, half = sl & 1;
            const int kt = chunk * 32;
            const int tap = kt / Cin;
            const int ci0 = kt - tap * Cin + hh * 16;
            const int a = tap >> 1, bt = tap & 1;
            const int kh = 2 * a + 1 - py, kw = 2 * bt + 1 - px;
            const size_t aoff = (size_t)(a * W + bt) * Cin + ci0;
            const size_t boff0 = ((size_t)((kh * 4 + kw) * COUT + rr)) * Cin + ci0;
            const size_t boff1 = ((size_t)((kh * 4 + kw) * COUT + rr + 128)) * Cin + ci0;
            const uint32_t stgo = SL_STAGE0 + s3 * SLOT_BYTES;
            if (half == 0) {
#pragma unroll
                for (int u = 0; u < 2; ++u) {
                    const float* pa = Ah + arow[u] + aoff;
#pragma unroll
                    for (int j = 0; j < 4; ++j)
                        *(float4*)(smem + stgo + u * 16384 + swo[j]) = *(const float4*)(pa + 4 * j);
                }
                const float* pb0 = Wh + boff0;
                const float* pb1 = Wh + boff1;
#pragma unroll
                for (int j = 0; j < 4; ++j) {
                    *(float4*)(smem + stgo + OFF2_B + swo[j])         = *(const float4*)(pb0 + 4 * j);
                    *(float4*)(smem + stgo + OFF2_B + 16384 + swo[j]) = *(const float4*)(pb1 + 4 * j);
                }
            } else {
                float f[16];
#pragma unroll
                for (int u = 0; u < 2; ++u) {
                    lo16_to_f32(Al + arow[u] + aoff, f);
#pragma unroll
                    for (int j = 0; j < 4; ++j)
                        *(float4*)(smem + stgo + u * 16384 + swo[j]) =
                            make_float4(f[4 * j], f[4 * j + 1], f[4 * j + 2], f[4 * j + 3]);
                }
                lo16_to_f32(Wl + boff0, f);
#pragma unroll
                for (int j = 0; j < 4; ++j)
                    *(float4*)(smem + stgo + OFF2_B + swo[j]) =
                        make_float4(f[4 * j], f[4 * j + 1], f[4 * j + 2], f[4 * j + 3]);
                lo16_to_f32(Wl + boff1, f);
#pragma unroll
                for (int j = 0; j < 4; ++j)
                    *(float4*)(smem + stgo + OFF2_B + 16384 + swo[j]) =
                        make_float4(f[4 * j], f[4 * j + 1], f[4 * j + 2], f[4 * j + 3]);
            }
            FENCE_ASYNC_SHARED();
            MBARRIER_ARRIVE(sb + SM_FULL + s3 * 8);
        }
    } else {
        if (elect_one()) {
            for (int i = 0; i < NK; ++i) {
                const int jh = 2 * i, jl = 2 * i + 1;
                const int sh = jh % 3, slx = jl % 3;
                mbar_wait(sb + SM_FULL + sh * 8, (uint32_t)((jh / 3) & 1));
                mbar_wait(sb + SM_FULL + slx * 8, (uint32_t)((jl / 3) & 1));
                const uint32_t stg_h = sb + SL_STAGE0 + sh * SLOT_BYTES;
                const uint32_t stg_l = sb + SL_STAGE0 + slx * SLOT_BYTES;
                const uint64_t dAh0 = MAKE_DESC(stg_h);
                const uint64_t dAh1 = MAKE_DESC(stg_h + 16384);
                const uint64_t dAl0 = MAKE_DESC(stg_l);
                const uint64_t dAl1 = MAKE_DESC(stg_l + 16384);
                const uint64_t dBh  = MAKE_DESC(stg_h + OFF2_B);
                const uint64_t dBl  = MAKE_DESC(stg_l + OFF2_B);
#pragma unroll
                for (int ks = 0; ks < 4; ++ks) {
#pragma unroll
                    for (int pass = 0; pass < 3; ++pass) {
                        const uint64_t da0 = (pass == 2) ? dAl0 : dAh0;
                        const uint64_t da1 = (pass == 2) ? dAl1 : dAh1;
                        const uint64_t db  = (pass == 1) ? dBl  : dBh;
                        const uint32_t en = (i > 0 || ks > 0 || pass > 0) ? 1u : 0u;
#pragma unroll
                        for (int nh = 0; nh < 2; ++nh) {
                            mma_tf32_ss(tmem + 0   + nh * 128, da0 + ks * 2, db + nh * 1024 + ks * 2, en);
                            mma_tf32_ss(tmem + 256 + nh * 128, da1 + ks * 2, db + nh * 1024 + ks * 2, en);
                        }
                    }
                }
                TCGEN05_COMMIT(sb + SM_DONE + sh * 8);
                TCGEN05_COMMIT(sb + SM_DONE + slx * 8);
            }
        }
    }

    {
        const int jlast = NSLOT - 1;
        mbar_wait(sb + SM_DONE + (jlast % 3) * 8, (uint32_t)((jlast / 3) & 1));
    }
    TCGEN05_FENCE_AFTER();
    __syncthreads();

    if (wid < 8) {
        const float* scs = (const float*)(smem + SM_SC);
        const float* bis = (const float*)(smem + SM_BI);
        const float* wfs = (const float*)(smem + SM_WF);
        const int tile = wid >> 2, sub = wid & 3;
        const int m = m0 + tile * 128 + sub * 32 + lane;
        const bool valid = (m < M);
        int bb = 0, ty = 0, tx = 0;
        if (valid) { bb = m / HWp; const int rem = m - bb * HWp; ty = rem / Wp; tx = rem - ty * Wp; }
        const int H2 = 2 * H - 2, W2 = 2 * W - 2;
        const int oy = 2 * ty + py, ox = 2 * tx + px;

        float hacc[KPT];
        if (mode == 0) {
#pragma unroll
            for (int k = 0; k < KPT; ++k) hacc[k] = bfp[k];
        }
        const size_t obase = ((size_t)(bb * H2 + oy) * W2 + ox) * COUT;

#pragma unroll
        for (int q = 0; q < 8; ++q) {
            const int c0 = q * 32;
            uint32_t regs[32];
            TCGEN05_LD_X32(regs, tmem + tile * 256 + c0);
            TCGEN05_WAIT_LD();
            if (valid) {
                if (mode == 0) {
#pragma unroll
                    for (int e = 0; e < 32; ++e) {
                        const int c = c0 + e;
                        const float v = fmaxf(fmaf(__uint_as_float(regs[e]), scs[c], bis[c]), 0.f);
                        const float* wr = wfs + c * KPT;
#pragma unroll
                        for (int k = 0; k < KPT; ++k)
                            hacc[k] = fmaf(v, wr[k], hacc[k]);
                    }
                } else {
#pragma unroll
                    for (int k4 = 0; k4 < 8; ++k4) {
                        float v[4];
#pragma unroll
                        for (int e = 0; e < 4; ++e) {
                            const int c = c0 + k4 * 4 + e;
                            v[e] = fmaxf(fmaf(__uint_as_float(regs[k4 * 4 + e]), scs[c], bis[c]), 0.f);
                        }
                        float4 h4;
                        float lo[4];
                        h4.x = tf32_hi(v[0]); lo[0] = v[0] - h4.x;
                        h4.y = tf32_hi(v[1]); lo[1] = v[1] - h4.y;
                        h4.z = tf32_hi(v[2]); lo[2] = v[2] - h4.z;
                        h4.w = tf32_hi(v[3]); lo[3] = v[3] - h4.w;
                        *(float4*)(Yh + obase + c0 + k4 * 4) = h4;
                        *(__nv_bfloat162*)(Yl + obase + c0 + k4 * 4)     = __floats2bfloat162_rn(lo[0], lo[1]);
                        *(__nv_bfloat162*)(Yl + obase + c0 + k4 * 4 + 2) = __floats2bfloat162_rn(lo[2], lo[3]);
                    }
                }
            }
        }
        if (mode == 0 && valid) {
            const int pp = oy * WD + ox;
            float* hb = hmp + (size_t)bb * KPT * HWD + pp;
#pragma unroll
            for (int k = 0; k < KPT; ++k)
                hb[(size_t)k * HWD] = hacc[k];
        }
    }

    __syncthreads();
    if (tid < 3) MBARRIER_INVAL(sb + SM_FULL + tid * 8);
    else if (tid >= 32 && tid < 35) MBARRIER_INVAL(sb + SM_DONE + (tid - 32) * 8);
    __syncthreads();
    if (wid == 0) TCGEN05_DEALLOC(tmem, 512);
#else
    // ------------------ fallback (non-accelerated pass) --------------------
    const int tid = threadIdx.x;
    const int phase = blockIdx.y;
    const int py = phase >> 1, px = phase & 1;
    const int m0 = blockIdx.x * 256;
    const int Hp = H - 1, Wp = W - 1;
    const int HWp = Hp * Wp;
    const int M = BDIM_B * HWp;
    const int H2 = 2 * H - 2, W2 = 2 * W - 2;

    if (mode == 1) {
        for (int idx = tid; idx < 256 * 256; idx += NTHR) {
            const int ml = idx >> 8, n = idx & 255;
            const int m = m0 + ml;
            if (m >= M) continue;
            const int bb = m / HWp; const int rem = m - bb * HWp;
            const int ty = rem / Wp; const int tx = rem - ty * Wp;
            float acc = 0.f;
            for (int tap = 0; tap < 4; ++tap) {
                const int a = tap >> 1, bt = tap & 1;
                const int kh = 2 * a + 1 - py, kw = 2 * bt + 1 - px;
                const float* ah = Ah + ((size_t)(bb * H + ty + a) * W + tx + bt) * Cin;
                const bf16*  al = Al + ((size_t)(bb * H + ty + a) * W + tx + bt) * Cin;
                const float* wh = Wh + ((size_t)((kh * 4 + kw) * COUT + n)) * Cin;
                const bf16*  wl = Wl + ((size_t)((kh * 4 + kw) * COUT + n)) * Cin;
                for (int c = 0; c < Cin; ++c)
                    acc = fmaf(ah[c] + __bfloat162float(al[c]),
                               wh[c] + __bfloat162float(wl[c]), acc);
            }
            const float s = gma[n] * rsqrtf(var[n] + BN_EPS);
            float v = fmaxf(fmaf(acc - mu[n], s, bta[n]), 0.f);
            const int oy = 2 * ty + py, ox = 2 * tx + px;
            const size_t o = ((size_t)(bb * H2 + oy) * W2 + ox) * COUT + n;
            const float h = tf32_hi(v); Yh[o] = h; Yl[o] = __float2bfloat16_rn(v - h);
        }
    } else {
        for (int ml = tid; ml < 256; ml += NTHR) {
            const int m = m0 + ml;
            if (m >= M) continue;
            const int bb = m / HWp; const int rem = m - bb * HWp;
            const int ty = rem / Wp; const int tx = rem - ty * Wp;
            float hacc[KPT];
            for (int k = 0; k < KPT; ++k) hacc[k] = bfp[k];
            for (int n = 0; n < COUT; ++n) {
                float acc = 0.f;
                for (int tap = 0; tap < 4; ++tap) {
                    const int a = tap >> 1, bt = tap & 1;
                    const int kh = 2 * a + 1 - py, kw = 2 * bt + 1 - px;
                    const float* ah = Ah + ((size_t)(bb * H + ty + a) * W + tx + bt) * Cin;
                    const bf16*  al = Al + ((size_t)(bb * H + ty + a) * W + tx + bt) * Cin;
                    const float* wh = Wh + ((size_t)((kh * 4 + kw) * COUT + n)) * Cin;
                    const bf16*  wl = Wl + ((size_t)((kh * 4 + kw) * COUT + n)) * Cin;
                    for (int c = 0; c < Cin; ++c)
                        acc = fmaf(ah[c] + __bfloat162float(al[c]),
                                   wh[c] + __bfloat162float(wl[c]), acc);
                }
                const float s = gma[n] * rsqrtf(var[n] + BN_EPS);
                const float v = fmaxf(fmaf(acc - mu[n], s, bta[n]), 0.f);
                for (int k = 0; k < KPT; ++k)
                    hacc[k] = fmaf(v, wfp[n * KPT + k], hacc[k]);
            }
            const int oy = 2 * ty + py, ox = 2 * tx + px;
            const int pp = oy * WD + ox;
            for (int k = 0; k < KPT; ++k)
                hmp[(size_t)(bb * KPT + k) * HWD + pp] = hacc[k];
        }
    }
#endif
}

// ---------------------------------------------------------------------------
// Per-(b,k) argmax + subpixel refinement.
// ---------------------------------------------------------------------------
__global__ void detect_kernel(const float* __restrict__ hm, float* __restrict__ out)
{
    const float* row = hm + (size_t)blockIdx.x * HWD;
    const int tid = threadIdx.x;

    float best = -3.402823466e+38f; int bidx = 0x7fffffff;
    for (int i = tid; i < HWD; i += 128) {
        const float v = row[i];
        if (v > best) { best = v; bidx = i; }
    }
    __shared__ float sv[128];
    __shared__ int   si[128];
    sv[tid] = best; si[tid] = bidx;
    __syncthreads();
    for (int s = 64; s > 0; s >>= 1) {
        if (tid < s) {
            const float v2 = sv[tid + s]; const int i2 = si[tid + s];
            if (v2 > sv[tid] || (v2 == sv[tid] && i2 < si[tid])) { sv[tid] = v2; si[tid] = i2; }
        }
        __syncthreads();
    }
    if (tid == 0) {
        const float score = sv[0];
        const int idx = si[0];
        const bool pos = score > 0.f;
        const int pxi = pos ? (idx % WD) : 0;
        const int pyi = pos ? (idx / WD) : 0;
        const bool inner = (pxi > 0) && (pxi < WD - 1) && (pyi > 0) && (pyi < HD - 1);
        float dx = 0.f, dy = 0.f;
        if (inner) {
            const int base = pyi * WD + pxi;
            const float d1 = row[base + 1]  - row[base - 1];
            const float d2 = row[base + WD] - row[base - WD];
            dx = (d1 > 0.f) ? 0.25f : ((d1 < 0.f) ? -0.25f : 0.f);
            dy = (d2 > 0.f) ? 0.25f : ((d2 < 0.f) ? -0.25f : 0.f);
        }
        float* o = out + (size_t)blockIdx.x * 3;
        o[0] = (float)pxi + dx;
        o[1] = (float)pyi + dy;
        o[2] = score;
    }
}

// ---------------------------------------------------------------------------
extern "C" void kernel_launch(void* const* d_in, const int* in_sizes, int n_in,
                              void* d_out, int out_size)
{
    const float* x  = (const float*)d_in[0];
    const float* w1 = (const float*)d_in[1];
    const float* g1 = (const float*)d_in[2];
    const float* b1 = (const float*)d_in[3];
    const float* m1 = (const float*)d_in[4];
    const float* v1 = (const float*)d_in[5];
    const float* w2 = (const float*)d_in[6];
    const float* g2 = (const float*)d_in[7];
    const float* b2 = (const float*)d_in[8];
    const float* m2 = (const float*)d_in[9];
    const float* v2 = (const float*)d_in[10];
    const float* w3 = (const float*)d_in[11];
    const float* g3 = (const float*)d_in[12];
    const float* b3 = (const float*)d_in[13];
    const float* m3 = (const float*)d_in[14];
    const float* v3 = (const float*)d_in[15];
    const float* wf = (const float*)d_in[16];
    const float* bf = (const float*)d_in[17];
    float* out = (float*)d_out;

    float *xh, *w1h, *w2h, *w3h, *p1, *y1h, *y2h, *hm;
    bf16  *xl, *w1l, *w2l, *w3l, *y1l, *y2l;
    cudaGetSymbolAddress((void**)&xh,  g_xh);
    cudaGetSymbolAddress((void**)&xl,  g_xl);
    cudaGetSymbolAddress((void**)&w1h, g_w1h);
    cudaGetSymbolAddress((void**)&w1l, g_w1l);
    cudaGetSymbolAddress((void**)&w2h, g_w2h);
    cudaGetSymbolAddress((void**)&w2l, g_w2l);
    cudaGetSymbolAddress((void**)&w3h, g_w3h);
    cudaGetSymbolAddress((void**)&w3l, g_w3l);
    cudaGetSymbolAddress((void**)&p1,  g_p1);
    cudaGetSymbolAddress((void**)&y1h, g_y1h);
    cudaGetSymbolAddress((void**)&y1l, g_y1l);
    cudaGetSymbolAddress((void**)&y2h, g_y2h);
    cudaGetSymbolAddress((void**)&y2l, g_y2l);
    cudaGetSymbolAddress((void**)&hm,  g_hm);

    static bool attr_done = false;
    if (!attr_done) {
        cudaFuncSetAttribute(deconv_tc1s, cudaFuncAttributeMaxDynamicSharedMemorySize, SMEM2_TOTAL);
        cudaFuncSetAttribute(deconv_tc2,  cudaFuncAttributeMaxDynamicSharedMemorySize, SMEM2_TOTAL);
        attr_done = true;
    }

    // preprocess: split x; transpose+split weights
    split_kernel<<<4096, 256>>>(x, xh, xl, BDIM_B * 8 * 6 * 2048);
    wtrans_kernel<<<dim3(2048 / 32, COUT / 32, 16), dim3(32, 8)>>>(w1, w1h, w1l, 2048);
    wtrans_kernel<<<dim3(256 / 32,  COUT / 32, 16), dim3(32, 8)>>>(w2, w2h, w2l, 256);
    wtrans_kernel<<<dim3(256 / 32,  COUT / 32, 16), dim3(32, 8)>>>(w3, w3h, w3l, 256);

    // L1 split-K-by-tap: grid (9 m-pair tiles, 4 phases, 4 taps) = 144 CTAs
    deconv_tc1s<<<dim3(9, 4, 4), NTHR, SMEM2_TOTAL>>>(xh, xl, w1h, w1l, p1);
    reduce_l1<<<(4 * L1_M * 64 + 255) / 256, 256>>>(p1, g1, b1, m1, v1, y1h, y1l);

    // L2: -> [64,26,18,256] split.  M_phase = 7488 -> 30 m-pair tiles
    deconv_tc2<<<dim3(30, 4), NTHR, SMEM2_TOTAL>>>(y1h, y1l, w2h, w2l, g2, b2, m2, v2,
                                                   y2h, y2l, nullptr, nullptr, nullptr,
                                                   14, 10, 256, 1);
    // L3 + fused heatmap: M_phase = 27200 -> 107 m-pair tiles
    deconv_tc2<<<dim3(107, 4), NTHR, SMEM2_TOTAL>>>(y2h, y2l, w3h, w3l, g3, b3, m3, v3,
                                                    nullptr, nullptr, wf, bf, hm,
                                                    26, 18, 256, 0);
    // argmax + subpixel per (b, keypoint)
    detect_kernel<<<BDIM_B * KPT, 128>>>(hm, out);
}